// round 5
// baseline (speedup 1.0000x reference)
#include <cuda_runtime.h>
#include <cstdint>

#define E_DIM 1024
#define S_MAX 2048
#define LEVELS 4
#define R_TOT 3840   // 2048+1024+512+256

// ---------------- scratch ---------------------------------------------------
__device__ float g_qkv[R_TOT * 3 * E_DIM];
__device__ float g_attn[R_TOT * E_DIM];
__device__ float g_outs[R_TOT * E_DIM];
__device__ float g_t2[256 * E_DIM];
__device__ float g_t1[512 * E_DIM];
__device__ float g_t0[1024 * E_DIM];

// ---------------- helpers ---------------------------------------------------
__device__ __forceinline__ uint32_t f2tf32(float f) {
    uint32_t r;
    asm("cvt.rna.tf32.f32 %0, %1;" : "=r"(r) : "f"(f));
    return r;
}

__device__ __forceinline__ void mma_tf32(float* c, const uint32_t* a,
                                         uint32_t b0, uint32_t b1) {
    asm volatile(
        "mma.sync.aligned.m16n8k8.row.col.f32.tf32.tf32.f32 "
        "{%0,%1,%2,%3}, {%4,%5,%6,%7}, {%8,%9}, {%0,%1,%2,%3};"
        : "+f"(c[0]), "+f"(c[1]), "+f"(c[2]), "+f"(c[3])
        : "r"(a[0]), "r"(a[1]), "r"(a[2]), "r"(a[3]), "r"(b0), "r"(b1));
}

// ---------------- shared GEMM core ------------------------------------------
#define BM 128
#define BN 128
#define BK 32
#define SST 36
#define GEMM_SMEM (2 * 2 * BM * SST * 4)

template <class FA>
__device__ __forceinline__ void gemm_core(
    FA fa,
    const float* __restrict__ Wp,       // W + bn*K
    const float* __restrict__ bias,
    const float* __restrict__ addend,   // or nullptr
    float* __restrict__ Y,
    int N, int K, int bm, int bn,
    uint32_t* As, uint32_t* Bs)
{
    const int tid = threadIdx.x;
    const int lane = tid & 31;
    const int wid = tid >> 5;
    const int warp_row = (wid & 1) * 64;
    const int warp_col = (wid >> 1) * 32;

    const int lc = (tid & 7) * 4;
    const int lr = tid >> 3;

    float acc[4][4][4];
#pragma unroll
    for (int mi = 0; mi < 4; mi++)
#pragma unroll
        for (int ni = 0; ni < 4; ni++)
#pragma unroll
            for (int j = 0; j < 4; j++) acc[mi][ni][j] = 0.f;

    float4 ra[4], rb[4];

#define G_FETCH(k0)                                                            \
    {                                                                          \
        _Pragma("unroll") for (int it = 0; it < 4; it++) {                     \
            int r = lr + it * 32;                                              \
            ra[it] = fa(bm + r, (k0) + lc);                                    \
            rb[it] = *reinterpret_cast<const float4*>(Wp + (size_t)r * K + (k0) + lc); \
        }                                                                      \
    }

#define G_STORE(sg)                                                            \
    {                                                                          \
        _Pragma("unroll") for (int it = 0; it < 4; it++) {                     \
            int r = lr + it * 32;                                              \
            uint4 at = {f2tf32(ra[it].x), f2tf32(ra[it].y),                    \
                        f2tf32(ra[it].z), f2tf32(ra[it].w)};                   \
            *reinterpret_cast<uint4*>(As + (sg)*BM*SST + r*SST + lc) = at;     \
            uint4 bt = {f2tf32(rb[it].x), f2tf32(rb[it].y),                    \
                        f2tf32(rb[it].z), f2tf32(rb[it].w)};                   \
            *reinterpret_cast<uint4*>(Bs + (sg)*BN*SST + r*SST + lc) = bt;     \
        }                                                                      \
    }

    G_FETCH(0);
    G_STORE(0);
    __syncthreads();

    const int g = lane >> 2;
    const int q = lane & 3;

    for (int k0 = 0; k0 < K; k0 += BK) {
        const int s = (k0 / BK) & 1;
        const bool more = (k0 + BK) < K;
        if (more) G_FETCH(k0 + BK);

        const uint32_t* Ab = As + s * BM * SST;
        const uint32_t* Bb = Bs + s * BN * SST;
#pragma unroll
        for (int kk = 0; kk < 4; kk++) {
            uint32_t af[4][4], bf[4][2];
            const int kc = kk * 8 + q;
#pragma unroll
            for (int mi = 0; mi < 4; mi++) {
                const uint32_t* p = Ab + (warp_row + mi * 16 + g) * SST + kc;
                af[mi][0] = p[0];
                af[mi][1] = p[8 * SST];
                af[mi][2] = p[4];
                af[mi][3] = p[8 * SST + 4];
            }
#pragma unroll
            for (int ni = 0; ni < 4; ni++) {
                const uint32_t* p = Bb + (warp_col + ni * 8 + g) * SST + kc;
                bf[ni][0] = p[0];
                bf[ni][1] = p[4];
            }
#pragma unroll
            for (int mi = 0; mi < 4; mi++)
#pragma unroll
                for (int ni = 0; ni < 4; ni++)
                    mma_tf32(acc[mi][ni], af[mi], bf[ni][0], bf[ni][1]);
        }
        if (more) G_STORE(s ^ 1);
        __syncthreads();
    }

#pragma unroll
    for (int mi = 0; mi < 4; mi++) {
        const int row0 = bm + warp_row + mi * 16 + g;
#pragma unroll
        for (int ni = 0; ni < 4; ni++) {
            const int col = bn + warp_col + ni * 8 + 2 * q;
            float2 bb = *reinterpret_cast<const float2*>(bias + col);
            float v0 = acc[mi][ni][0] + bb.x;
            float v1 = acc[mi][ni][1] + bb.y;
            float v2 = acc[mi][ni][2] + bb.x;
            float v3 = acc[mi][ni][3] + bb.y;
            if (addend) {
                float2 a0 = *reinterpret_cast<const float2*>(addend + (size_t)row0 * N + col);
                float2 a1 = *reinterpret_cast<const float2*>(addend + (size_t)(row0 + 8) * N + col);
                v0 += a0.x; v1 += a0.y; v2 += a1.x; v3 += a1.y;
            }
            *reinterpret_cast<float2*>(Y + (size_t)row0 * N + col) = make_float2(v0, v1);
            *reinterpret_cast<float2*>(Y + (size_t)(row0 + 8) * N + col) = make_float2(v2, v3);
        }
    }
#undef G_FETCH
#undef G_STORE
}

// A-load functors
struct PlainFA {
    const float* X; int ldx;
    __device__ __forceinline__ float4 operator()(int r, int c) const {
        return *reinterpret_cast<const float4*>(X + (size_t)r * ldx + c);
    }
};
// A(r,c) = lerp of src rows (2x upsample, src has Lsrc rows) + fine[r]
struct UpAddFA {
    const float* src; const float* fine; int Lsrc;
    __device__ __forceinline__ float4 operator()(int r, int c) const {
        float s = 0.5f * (float)r - 0.25f;
        s = fminf(fmaxf(s, 0.f), (float)(Lsrc - 1));
        int i0 = (int)floorf(s);
        int i1 = min(i0 + 1, Lsrc - 1);
        float w = s - (float)i0;
        float4 a = *reinterpret_cast<const float4*>(src + (size_t)i0 * E_DIM + c);
        float4 b = *reinterpret_cast<const float4*>(src + (size_t)i1 * E_DIM + c);
        float4 f = *reinterpret_cast<const float4*>(fine + (size_t)r * E_DIM + c);
        float4 o;
        o.x = a.x + (b.x - a.x) * w + f.x;
        o.y = a.y + (b.y - a.y) * w + f.y;
        o.z = a.z + (b.z - a.z) * w + f.z;
        o.w = a.w + (b.w - a.w) * w + f.w;
        return o;
    }
};

// level tables
__device__ __constant__ int d_qoff[4] = {0, 2048, 3072, 3584};
__device__ __constant__ int d_rbCum[5] = {0, 16, 24, 28, 30};
__device__ __constant__ int d_qbCum[5] = {0, 32, 48, 56, 60};
__device__ __constant__ int d_Llvl[4] = {2048, 1024, 512, 256};

// ---------------- batched QKV projection ------------------------------------
__global__ void __launch_bounds__(256) gemm_qkv_all(
    const float* __restrict__ query,
    const float* __restrict__ in_w,
    const float* __restrict__ in_b)
{
    extern __shared__ uint32_t smem[];
    const int by = blockIdx.y;
    int lvl = 0;
#pragma unroll
    for (int i = 0; i < 3; i++) if (by >= d_rbCum[i + 1]) lvl = i + 1;
    const int bm = (by - d_rbCum[lvl]) * BM;
    const int bn = blockIdx.x * BN;
    const int stride = 1 << lvl;

    PlainFA fa{query, stride * E_DIM};
    gemm_core(fa,
              in_w + (size_t)lvl * 3 * E_DIM * E_DIM + (size_t)bn * E_DIM,
              in_b + (size_t)lvl * 3 * E_DIM,
              nullptr,
              g_qkv + (size_t)d_qoff[lvl] * 3 * E_DIM,
              3 * E_DIM, E_DIM, bm, bn,
              smem, smem + 2 * BM * SST);
}

// ---------------- batched out projection ------------------------------------
__global__ void __launch_bounds__(256) gemm_out_all(
    const float* __restrict__ out_w,
    const float* __restrict__ out_b)
{
    extern __shared__ uint32_t smem[];
    const int by = blockIdx.y;
    int lvl = 0;
#pragma unroll
    for (int i = 0; i < 3; i++) if (by >= d_rbCum[i + 1]) lvl = i + 1;
    const int bm = (by - d_rbCum[lvl]) * BM;
    const int bn = blockIdx.x * BN;

    PlainFA fa{g_attn + (size_t)d_qoff[lvl] * E_DIM, E_DIM};
    gemm_core(fa,
              out_w + (size_t)lvl * E_DIM * E_DIM + (size_t)bn * E_DIM,
              out_b + (size_t)lvl * E_DIM,
              nullptr,
              g_outs + (size_t)d_qoff[lvl] * E_DIM,
              E_DIM, E_DIM, bm, bn,
              smem, smem + 2 * BM * SST);
}

// ---------------- combine GEMMs (coarse-resolution projections) -------------
__global__ void __launch_bounds__(256) gemm_proj(
    const float* __restrict__ X,
    const float* __restrict__ W,
    const float* __restrict__ bias,
    float* __restrict__ Y)
{
    extern __shared__ uint32_t smem[];
    PlainFA fa{X, E_DIM};
    gemm_core(fa, W + (size_t)blockIdx.x * BN * E_DIM, bias, nullptr, Y,
              E_DIM, E_DIM, blockIdx.y * BM, blockIdx.x * BN,
              smem, smem + 2 * BM * SST);
}

__global__ void __launch_bounds__(256) gemm_upadd_proj(
    const float* __restrict__ src, int Lsrc,
    const float* __restrict__ fine,
    const float* __restrict__ W,
    const float* __restrict__ bias,
    float* __restrict__ Y)
{
    extern __shared__ uint32_t smem[];
    UpAddFA fa{src, fine, Lsrc};
    gemm_core(fa, W + (size_t)blockIdx.x * BN * E_DIM, bias, nullptr, Y,
              E_DIM, E_DIM, blockIdx.y * BM, blockIdx.x * BN,
              smem, smem + 2 * BM * SST);
}

// final: out[r] = up(t0)[r] + o0[r]
__global__ void __launch_bounds__(256) upadd_final(
    const float* __restrict__ src, int Lsrc,
    const float* __restrict__ fine,
    float* __restrict__ out)
{
    const int r = blockIdx.x;
    float s = 0.5f * (float)r - 0.25f;
    s = fminf(fmaxf(s, 0.f), (float)(Lsrc - 1));
    int i0 = (int)floorf(s);
    int i1 = min(i0 + 1, Lsrc - 1);
    float w = s - (float)i0;
    const float* a = src + (size_t)i0 * E_DIM;
    const float* b = src + (size_t)i1 * E_DIM;
    const float* f = fine + (size_t)r * E_DIM;
    float* yp = out + (size_t)r * E_DIM;
    for (int c = threadIdx.x * 4; c < E_DIM; c += blockDim.x * 4) {
        float4 va = *reinterpret_cast<const float4*>(a + c);
        float4 vb = *reinterpret_cast<const float4*>(b + c);
        float4 vf = *reinterpret_cast<const float4*>(f + c);
        float4 o;
        o.x = va.x + (vb.x - va.x) * w + vf.x;
        o.y = va.y + (vb.y - va.y) * w + vf.y;
        o.z = va.z + (vb.z - va.z) * w + vf.z;
        o.w = va.w + (vb.w - va.w) * w + vf.w;
        *reinterpret_cast<float4*>(yp + c) = o;
    }
}

// ---------------- batched tensor-core flash attention -----------------------
#define AST 68
#define ATTN_SMEM (3 * 64 * AST * 4)

__global__ void __launch_bounds__(128) attn_all()
{
    extern __shared__ uint32_t sm[];
    uint32_t* Qs = sm;
    uint32_t* Ks = sm + 64 * AST;
    uint32_t* Vs = sm + 2 * 64 * AST;
    uint32_t* Ps = Qs;

    const int bx = blockIdx.x;
    int lvl = 0;
#pragma unroll
    for (int i = 0; i < 3; i++) if (bx >= d_qbCum[i + 1]) lvl = i + 1;
    const int L = d_Llvl[lvl];
    const float* qkv = g_qkv + (size_t)d_qoff[lvl] * 3 * E_DIM;
    float* out = g_attn + (size_t)d_qoff[lvl] * E_DIM;

    const int h = blockIdx.y;
    const int q0 = (bx - d_qbCum[lvl]) * 64;
    const int tid = threadIdx.x;
    const int wid = tid >> 5;
    const int lane = tid & 31;
    const int g = lane >> 2;
    const int q = lane & 3;

    const int lc = (tid & 15) * 4;
    const int lr0 = tid >> 4;

#pragma unroll
    for (int it = 0; it < 8; it++) {
        int r = lr0 + it * 8;
        float4 v = *reinterpret_cast<const float4*>(
            qkv + (size_t)(q0 + r) * 3072 + h * 64 + lc);
        uint4 t = {f2tf32(v.x * 0.125f), f2tf32(v.y * 0.125f),
                   f2tf32(v.z * 0.125f), f2tf32(v.w * 0.125f)};
        *reinterpret_cast<uint4*>(Qs + r * AST + lc) = t;
    }
    __syncthreads();

    uint32_t qa[8][4];
    const int arow = wid * 16 + g;
#pragma unroll
    for (int kk = 0; kk < 8; kk++) {
        const uint32_t* p = Qs + arow * AST + kk * 8 + q;
        qa[kk][0] = p[0];
        qa[kk][1] = p[8 * AST];
        qa[kk][2] = p[4];
        qa[kk][3] = p[8 * AST + 4];
    }

    float m_i[2] = {-1e30f, -1e30f};
    float l_i[2] = {0.f, 0.f};
    float O[8][4];
#pragma unroll
    for (int ni = 0; ni < 8; ni++)
#pragma unroll
        for (int j = 0; j < 4; j++) O[ni][j] = 0.f;

    for (int kb = 0; kb < L; kb += 64) {
        __syncthreads();
#pragma unroll
        for (int it = 0; it < 8; it++) {
            int r = lr0 + it * 8;
            const float* base = qkv + (size_t)(kb + r) * 3072 + h * 64 + lc;
            float4 kv = *reinterpret_cast<const float4*>(base + 1024);
            uint4 kt = {f2tf32(kv.x), f2tf32(kv.y), f2tf32(kv.z), f2tf32(kv.w)};
            *reinterpret_cast<uint4*>(Ks + r * AST + lc) = kt;
            float4 vv = *reinterpret_cast<const float4*>(base + 2048);
            uint4 vt = {f2tf32(vv.x), f2tf32(vv.y), f2tf32(vv.z), f2tf32(vv.w)};
            *reinterpret_cast<uint4*>(Vs + r * AST + lc) = vt;
        }
        __syncthreads();

        float s[8][4];
#pragma unroll
        for (int ni = 0; ni < 8; ni++)
#pragma unroll
            for (int j = 0; j < 4; j++) s[ni][j] = 0.f;
#pragma unroll
        for (int kk = 0; kk < 8; kk++) {
            const int kc = kk * 8 + q;
#pragma unroll
            for (int ni = 0; ni < 8; ni++) {
                const uint32_t* p = Ks + (ni * 8 + g) * AST + kc;
                mma_tf32(s[ni], qa[kk], p[0], p[4]);
            }
        }

        float rmax0 = -1e30f, rmax1 = -1e30f;
#pragma unroll
        for (int ni = 0; ni < 8; ni++) {
            rmax0 = fmaxf(rmax0, fmaxf(s[ni][0], s[ni][1]));
            rmax1 = fmaxf(rmax1, fmaxf(s[ni][2], s[ni][3]));
        }
#pragma unroll
        for (int off = 1; off <= 2; off <<= 1) {
            rmax0 = fmaxf(rmax0, __shfl_xor_sync(0xffffffffu, rmax0, off));
            rmax1 = fmaxf(rmax1, __shfl_xor_sync(0xffffffffu, rmax1, off));
        }
        float mnew0 = fmaxf(m_i[0], rmax0);
        float mnew1 = fmaxf(m_i[1], rmax1);
        float al0 = __expf(m_i[0] - mnew0);
        float al1 = __expf(m_i[1] - mnew1);
        float sum0 = 0.f, sum1 = 0.f;
#pragma unroll
        for (int ni = 0; ni < 8; ni++) {
            s[ni][0] = __expf(s[ni][0] - mnew0);
            s[ni][1] = __expf(s[ni][1] - mnew0);
            s[ni][2] = __expf(s[ni][2] - mnew1);
            s[ni][3] = __expf(s[ni][3] - mnew1);
            sum0 += s[ni][0] + s[ni][1];
            sum1 += s[ni][2] + s[ni][3];
        }
#pragma unroll
        for (int off = 1; off <= 2; off <<= 1) {
            sum0 += __shfl_xor_sync(0xffffffffu, sum0, off);
            sum1 += __shfl_xor_sync(0xffffffffu, sum1, off);
        }
        l_i[0] = l_i[0] * al0 + sum0;
        l_i[1] = l_i[1] * al1 + sum1;
        m_i[0] = mnew0;
        m_i[1] = mnew1;
#pragma unroll
        for (int ni = 0; ni < 8; ni++) {
            O[ni][0] *= al0; O[ni][1] *= al0;
            O[ni][2] *= al1; O[ni][3] *= al1;
        }

        __syncwarp();
#pragma unroll
        for (int ni = 0; ni < 8; ni++) {
            const int col = ni * 8 + 2 * q;
            Ps[arow * AST + col]           = f2tf32(s[ni][0]);
            Ps[arow * AST + col + 1]       = f2tf32(s[ni][1]);
            Ps[(arow + 8) * AST + col]     = f2tf32(s[ni][2]);
            Ps[(arow + 8) * AST + col + 1] = f2tf32(s[ni][3]);
        }
        __syncwarp();

#pragma unroll
        for (int kk = 0; kk < 8; kk++) {
            uint32_t pa[4];
            const uint32_t* pp = Ps + arow * AST + kk * 8 + q;
            pa[0] = pp[0];
            pa[1] = pp[8 * AST];
            pa[2] = pp[4];
            pa[3] = pp[8 * AST + 4];
#pragma unroll
            for (int ni = 0; ni < 8; ni++) {
                const uint32_t* vp = Vs + (kk * 8 + q) * AST + ni * 8 + g;
                mma_tf32(O[ni], pa, vp[0], vp[4 * AST]);
            }
        }
    }

    const float inv0 = 1.0f / l_i[0];
    const float inv1 = 1.0f / l_i[1];
    const size_t row0 = (size_t)(q0 + arow);
#pragma unroll
    for (int ni = 0; ni < 8; ni++) {
        const int col = h * 64 + ni * 8 + 2 * q;
        *reinterpret_cast<float2*>(out + row0 * E_DIM + col) =
            make_float2(O[ni][0] * inv0, O[ni][1] * inv0);
        *reinterpret_cast<float2*>(out + (row0 + 8) * E_DIM + col) =
            make_float2(O[ni][2] * inv1, O[ni][3] * inv1);
    }
}

// ---------------- launcher --------------------------------------------------
extern "C" void kernel_launch(void* const* d_in, const int* in_sizes, int n_in,
                              void* d_out, int out_size)
{
    const float* query = (const float*)d_in[0];
    const float* in_w  = (const float*)d_in[1];
    const float* in_b  = (const float*)d_in[2];
    const float* out_w = (const float*)d_in[3];
    const float* out_b = (const float*)d_in[4];
    const float* up_w  = (const float*)d_in[5];
    const float* up_b  = (const float*)d_in[6];
    float* out = (float*)d_out;

    cudaFuncSetAttribute(gemm_qkv_all,    cudaFuncAttributeMaxDynamicSharedMemorySize, GEMM_SMEM);
    cudaFuncSetAttribute(gemm_out_all,    cudaFuncAttributeMaxDynamicSharedMemorySize, GEMM_SMEM);
    cudaFuncSetAttribute(gemm_proj,       cudaFuncAttributeMaxDynamicSharedMemorySize, GEMM_SMEM);
    cudaFuncSetAttribute(gemm_upadd_proj, cudaFuncAttributeMaxDynamicSharedMemorySize, GEMM_SMEM);
    cudaFuncSetAttribute(attn_all,        cudaFuncAttributeMaxDynamicSharedMemorySize, ATTN_SMEM);

    float *outs, *t2, *t1, *t0;
    cudaGetSymbolAddress((void**)&outs, g_outs);
    cudaGetSymbolAddress((void**)&t2,   g_t2);
    cudaGetSymbolAddress((void**)&t1,   g_t1);
    cudaGetSymbolAddress((void**)&t0,   g_t0);

    // pyramid: one launch per stage, all levels batched
    gemm_qkv_all<<<dim3(3 * E_DIM / BN, 30), 256, GEMM_SMEM>>>(query, in_w, in_b);
    attn_all<<<dim3(60, 16), 128, ATTN_SMEM>>>();
    gemm_out_all<<<dim3(E_DIM / BN, 30), 256, GEMM_SMEM>>>(out_w, out_b);

    // top-down combine at coarse resolution (projection commutes with upsample)
    const size_t off1 = 2048u * E_DIM, off2 = 3072u * E_DIM, off3 = 3584u * E_DIM;
    // t2 = o3 @ W2^T + b2            (256 rows)
    gemm_proj<<<dim3(E_DIM / BN, 256 / BM), 256, GEMM_SMEM>>>(
        outs + off3, up_w + 2u * E_DIM * E_DIM, up_b + 2u * E_DIM, t2);
    // t1 = (up(t2)+o2) @ W1^T + b1   (512 rows)
    gemm_upadd_proj<<<dim3(E_DIM / BN, 512 / BM), 256, GEMM_SMEM>>>(
        t2, 256, outs + off2, up_w + 1u * E_DIM * E_DIM, up_b + 1u * E_DIM, t1);
    // t0 = (up(t1)+o1) @ W0^T + b0   (1024 rows)
    gemm_upadd_proj<<<dim3(E_DIM / BN, 1024 / BM), 256, GEMM_SMEM>>>(
        t1, 512, outs + off1, up_w, up_b, t0);
    // out = up(t0) + o0              (2048 rows, elementwise)
    upadd_final<<<2048, 256>>>(t0, 1024, outs, out);
}

// round 6
// speedup vs baseline: 1.0058x; 1.0058x over previous
#include <cuda_runtime.h>
#include <cstdint>

#define E_DIM 1024
#define S_MAX 2048
#define LEVELS 4
#define R_TOT 3840   // 2048+1024+512+256

// ---------------- scratch ---------------------------------------------------
__device__ float g_qkv[R_TOT * 3 * E_DIM];
__device__ float g_attn[R_TOT * E_DIM];
__device__ float g_outs[R_TOT * E_DIM];
__device__ float g_W1T[E_DIM * E_DIM];
__device__ float g_W2T[E_DIM * E_DIM];
__device__ float g_P2[E_DIM * E_DIM];   // W0 @ W1   (M2 = P2^T)
__device__ float g_P3[E_DIM * E_DIM];   // P2 @ W2   (M3 = P3^T)
__device__ float g_Q1[1024 * E_DIM];    // o1 @ W0^T
__device__ float g_Q2[512 * E_DIM];     // o2 @ P2^T
__device__ float g_Q3[256 * E_DIM];     // o3 @ P3^T
__device__ float g_rrow[E_DIM];         // b2*M2 + b1*M1 + b0
__device__ float g_zb[E_DIM];           // zero bias (static-zeroed)

// ---------------- helpers ---------------------------------------------------
__device__ __forceinline__ uint32_t f2tf32(float f) {
    uint32_t r;
    asm("cvt.rna.tf32.f32 %0, %1;" : "=r"(r) : "f"(f));
    return r;
}

__device__ __forceinline__ void mma_tf32(float* c, const uint32_t* a,
                                         uint32_t b0, uint32_t b1) {
    asm volatile(
        "mma.sync.aligned.m16n8k8.row.col.f32.tf32.tf32.f32 "
        "{%0,%1,%2,%3}, {%4,%5,%6,%7}, {%8,%9}, {%0,%1,%2,%3};"
        : "+f"(c[0]), "+f"(c[1]), "+f"(c[2]), "+f"(c[3])
        : "r"(a[0]), "r"(a[1]), "r"(a[2]), "r"(a[3]), "r"(b0), "r"(b1));
}

// ---------------- shared GEMM core ------------------------------------------
#define BM 128
#define BN 128
#define BK 32
#define SST 36
#define GEMM_SMEM (2 * 2 * BM * SST * 4)

struct PlainFA {
    const float* X; int ldx;
    __device__ __forceinline__ float4 operator()(int r, int c) const {
        return *reinterpret_cast<const float4*>(X + (size_t)r * ldx + c);
    }
};

template <class FA>
__device__ __forceinline__ void gemm_core(
    FA fa,
    const float* __restrict__ Wp,       // W + bn*K
    const float* __restrict__ bias,
    float* __restrict__ Y,
    int N, int K, int bm, int bn,
    uint32_t* As, uint32_t* Bs)
{
    const int tid = threadIdx.x;
    const int lane = tid & 31;
    const int wid = tid >> 5;
    const int warp_row = (wid & 1) * 64;
    const int warp_col = (wid >> 1) * 32;

    const int lc = (tid & 7) * 4;
    const int lr = tid >> 3;

    float acc[4][4][4];
#pragma unroll
    for (int mi = 0; mi < 4; mi++)
#pragma unroll
        for (int ni = 0; ni < 4; ni++)
#pragma unroll
            for (int j = 0; j < 4; j++) acc[mi][ni][j] = 0.f;

    float4 ra[4], rb[4];

#define G_FETCH(k0)                                                            \
    {                                                                          \
        _Pragma("unroll") for (int it = 0; it < 4; it++) {                     \
            int r = lr + it * 32;                                              \
            ra[it] = fa(bm + r, (k0) + lc);                                    \
            rb[it] = *reinterpret_cast<const float4*>(Wp + (size_t)r * K + (k0) + lc); \
        }                                                                      \
    }

#define G_STORE(sg)                                                            \
    {                                                                          \
        _Pragma("unroll") for (int it = 0; it < 4; it++) {                     \
            int r = lr + it * 32;                                              \
            uint4 at = {f2tf32(ra[it].x), f2tf32(ra[it].y),                    \
                        f2tf32(ra[it].z), f2tf32(ra[it].w)};                   \
            *reinterpret_cast<uint4*>(As + (sg)*BM*SST + r*SST + lc) = at;     \
            uint4 bt = {f2tf32(rb[it].x), f2tf32(rb[it].y),                    \
                        f2tf32(rb[it].z), f2tf32(rb[it].w)};                   \
            *reinterpret_cast<uint4*>(Bs + (sg)*BN*SST + r*SST + lc) = bt;     \
        }                                                                      \
    }

    G_FETCH(0);
    G_STORE(0);
    __syncthreads();

    const int g = lane >> 2;
    const int q = lane & 3;

    for (int k0 = 0; k0 < K; k0 += BK) {
        const int s = (k0 / BK) & 1;
        const bool more = (k0 + BK) < K;
        if (more) G_FETCH(k0 + BK);

        const uint32_t* Ab = As + s * BM * SST;
        const uint32_t* Bb = Bs + s * BN * SST;
#pragma unroll
        for (int kk = 0; kk < 4; kk++) {
            uint32_t af[4][4], bf[4][2];
            const int kc = kk * 8 + q;
#pragma unroll
            for (int mi = 0; mi < 4; mi++) {
                const uint32_t* p = Ab + (warp_row + mi * 16 + g) * SST + kc;
                af[mi][0] = p[0];
                af[mi][1] = p[8 * SST];
                af[mi][2] = p[4];
                af[mi][3] = p[8 * SST + 4];
            }
#pragma unroll
            for (int ni = 0; ni < 4; ni++) {
                const uint32_t* p = Bb + (warp_col + ni * 8 + g) * SST + kc;
                bf[ni][0] = p[0];
                bf[ni][1] = p[4];
            }
#pragma unroll
            for (int mi = 0; mi < 4; mi++)
#pragma unroll
                for (int ni = 0; ni < 4; ni++)
                    mma_tf32(acc[mi][ni], af[mi], bf[ni][0], bf[ni][1]);
        }
        if (more) G_STORE(s ^ 1);
        __syncthreads();
    }

#pragma unroll
    for (int mi = 0; mi < 4; mi++) {
        const int row0 = bm + warp_row + mi * 16 + g;
#pragma unroll
        for (int ni = 0; ni < 4; ni++) {
            const int col = bn + warp_col + ni * 8 + 2 * q;
            float2 bb = *reinterpret_cast<const float2*>(bias + col);
            *reinterpret_cast<float2*>(Y + (size_t)row0 * N + col) =
                make_float2(acc[mi][ni][0] + bb.x, acc[mi][ni][1] + bb.y);
            *reinterpret_cast<float2*>(Y + (size_t)(row0 + 8) * N + col) =
                make_float2(acc[mi][ni][2] + bb.x, acc[mi][ni][3] + bb.y);
        }
    }
#undef G_FETCH
#undef G_STORE
}

// level tables
__device__ __constant__ int d_qoff[4] = {0, 2048, 3072, 3584};
__device__ __constant__ int d_rbCum[5] = {0, 16, 24, 28, 30};
__device__ __constant__ int d_qbCum[5] = {0, 32, 48, 56, 60};
__device__ __constant__ int d_Llvl[4] = {2048, 1024, 512, 256};

// ---------------- weight transpose (W1, W2) ---------------------------------
__global__ void __launch_bounds__(256) transpose_w(const float* __restrict__ up_w)
{
    __shared__ float t[32][33];
    const float* src = up_w + (size_t)(blockIdx.z + 1) * E_DIM * E_DIM;
    float* dst = blockIdx.z == 0 ? g_W1T : g_W2T;
    int x = blockIdx.x * 32 + threadIdx.x;
    int y = blockIdx.y * 32 + threadIdx.y;
#pragma unroll
    for (int i = 0; i < 32; i += 8)
        t[threadIdx.y + i][threadIdx.x] = src[(size_t)(y + i) * E_DIM + x];
    __syncthreads();
    x = blockIdx.y * 32 + threadIdx.x;
    y = blockIdx.x * 32 + threadIdx.y;
#pragma unroll
    for (int i = 0; i < 32; i += 8)
        dst[(size_t)(y + i) * E_DIM + x] = t[threadIdx.x][threadIdx.y + i];
}

// ---------------- batched QKV projection (+ hidden P2 = W0@W1) --------------
__global__ void __launch_bounds__(256) gemm_qkv_all(
    const float* __restrict__ query,
    const float* __restrict__ in_w,
    const float* __restrict__ in_b,
    const float* __restrict__ up_w)
{
    extern __shared__ uint32_t smem[];
    const int by = blockIdx.y;

    if (by >= 30) {   // P2 = W0 @ W1T^T
        int li = (by - 30) * gridDim.x + blockIdx.x;
        if (li >= 64) return;
        PlainFA fa{up_w, E_DIM};
        gemm_core(fa, g_W1T + (size_t)(li % 8) * BN * E_DIM, g_zb, g_P2,
                  E_DIM, E_DIM, (li / 8) * BM, (li % 8) * BN,
                  smem, smem + 2 * BM * SST);
        return;
    }

    int lvl = 0;
#pragma unroll
    for (int i = 0; i < 3; i++) if (by >= d_rbCum[i + 1]) lvl = i + 1;
    const int bm = (by - d_rbCum[lvl]) * BM;
    const int bn = blockIdx.x * BN;
    const int stride = 1 << lvl;

    PlainFA fa{query, stride * E_DIM};
    gemm_core(fa,
              in_w + (size_t)lvl * 3 * E_DIM * E_DIM + (size_t)bn * E_DIM,
              in_b + (size_t)lvl * 3 * E_DIM,
              g_qkv + (size_t)d_qoff[lvl] * 3 * E_DIM,
              3 * E_DIM, E_DIM, bm, bn,
              smem, smem + 2 * BM * SST);
}

// ---------------- batched out projection (+ hidden P3 = P2@W2) --------------
__global__ void __launch_bounds__(256) gemm_out_all(
    const float* __restrict__ out_w,
    const float* __restrict__ out_b)
{
    extern __shared__ uint32_t smem[];
    const int by = blockIdx.y;

    if (by >= 30) {   // P3 = P2 @ W2T^T   (gridDim.x == 8)
        int li = (by - 30) * 8 + blockIdx.x;
        PlainFA fa{g_P2, E_DIM};
        gemm_core(fa, g_W2T + (size_t)(li % 8) * BN * E_DIM, g_zb, g_P3,
                  E_DIM, E_DIM, (li / 8) * BM, (li % 8) * BN,
                  smem, smem + 2 * BM * SST);
        return;
    }

    int lvl = 0;
#pragma unroll
    for (int i = 0; i < 3; i++) if (by >= d_rbCum[i + 1]) lvl = i + 1;
    const int bm = (by - d_rbCum[lvl]) * BM;
    const int bn = blockIdx.x * BN;

    PlainFA fa{g_attn + (size_t)d_qoff[lvl] * E_DIM, E_DIM};
    gemm_core(fa,
              out_w + (size_t)lvl * E_DIM * E_DIM + (size_t)bn * E_DIM,
              out_b + (size_t)lvl * E_DIM,
              g_outs + (size_t)d_qoff[lvl] * E_DIM,
              E_DIM, E_DIM, bm, bn,
              smem, smem + 2 * BM * SST);
}

// ---------------- one-launch combine projections + bias row -----------------
// blocks [0,16): Q3 = o3@P3^T  | [16,48): Q2 = o2@P2^T | [48,112): Q1 = o1@W0^T
// blocks [112,116): rrow = b2*M2 + b1*M1 + b0
__global__ void __launch_bounds__(256) combine_proj(
    const float* __restrict__ up_w,
    const float* __restrict__ up_b)
{
    extern __shared__ uint32_t smem[];
    const int li = blockIdx.x;

    if (li < 16) {
        PlainFA fa{g_outs + (size_t)d_qoff[3] * E_DIM, E_DIM};
        gemm_core(fa, g_P3 + (size_t)(li % 8) * BN * E_DIM, g_zb, g_Q3,
                  E_DIM, E_DIM, (li / 8) * BM, (li % 8) * BN,
                  smem, smem + 2 * BM * SST);
    } else if (li < 48) {
        int t = li - 16;
        PlainFA fa{g_outs + (size_t)d_qoff[2] * E_DIM, E_DIM};
        gemm_core(fa, g_P2 + (size_t)(t % 8) * BN * E_DIM, g_zb, g_Q2,
                  E_DIM, E_DIM, (t / 8) * BM, (t % 8) * BN,
                  smem, smem + 2 * BM * SST);
    } else if (li < 112) {
        int t = li - 48;
        PlainFA fa{g_outs + (size_t)d_qoff[1] * E_DIM, E_DIM};
        gemm_core(fa, up_w + (size_t)(t % 8) * BN * E_DIM, g_zb, g_Q1,
                  E_DIM, E_DIM, (t / 8) * BM, (t % 8) * BN,
                  smem, smem + 2 * BM * SST);
    } else {
        // rrow[c] = dot(b2, P2[c,:]) + dot(b1, W0[c,:]) + b0[c]
        const float* b0 = up_b;
        const float* b1 = up_b + E_DIM;
        const float* b2 = up_b + 2 * E_DIM;
        int bi = li - 112;
        int warp = threadIdx.x >> 5, lane = threadIdx.x & 31;
        for (int cc = 0; cc < 32; cc++) {
            int c = bi * 256 + warp * 32 + cc;
            float s = 0.f;
            for (int k = lane; k < E_DIM; k += 32)
                s += b2[k] * g_P2[(size_t)c * E_DIM + k]
                   + b1[k] * up_w[(size_t)c * E_DIM + k];
#pragma unroll
            for (int off = 16; off; off >>= 1)
                s += __shfl_xor_sync(0xffffffffu, s, off);
            if (lane == 0) g_rrow[c] = s + b0[c];
        }
    }
}

// ---------------- final: out = up3(Q3) + up2(Q2) + up(Q1) + rrow + o0 -------
__device__ __forceinline__ void taps(float pos, int L, int& i0, int& i1, float& w)
{
    pos = fminf(fmaxf(pos, 0.f), (float)(L - 1));
    i0 = (int)floorf(pos);
    i1 = min(i0 + 1, L - 1);
    w = pos - (float)i0;
}

__global__ void __launch_bounds__(256) final_combine(float* __restrict__ out)
{
    const int r = blockIdx.x;
    const int c = threadIdx.x * 4;

    int j0, j1; float w1;
    taps(0.5f * r - 0.25f, 1024, j0, j1, w1);
    int jj[2] = {j0, j1};
    float wj[2] = {1.f - w1, w1};

    int kk2[4]; float wk2[4];
#pragma unroll
    for (int t = 0; t < 2; t++) {
        int a, b; float w;
        taps(0.5f * jj[t] - 0.25f, 512, a, b, w);
        kk2[2 * t] = a;     wk2[2 * t] = wj[t] * (1.f - w);
        kk2[2 * t + 1] = b; wk2[2 * t + 1] = wj[t] * w;
    }

    int mm[8]; float wm[8];
#pragma unroll
    for (int t = 0; t < 4; t++) {
        int a, b; float w;
        taps(0.5f * kk2[t] - 0.25f, 256, a, b, w);
        mm[2 * t] = a;     wm[2 * t] = wk2[t] * (1.f - w);
        mm[2 * t + 1] = b; wm[2 * t + 1] = wk2[t] * w;
    }

    float4 acc = *reinterpret_cast<const float4*>(g_outs + (size_t)r * E_DIM + c);
    float4 rr  = *reinterpret_cast<const float4*>(g_rrow + c);
    acc.x += rr.x; acc.y += rr.y; acc.z += rr.z; acc.w += rr.w;

#pragma unroll
    for (int t = 0; t < 2; t++) {
        float4 v = *reinterpret_cast<const float4*>(g_Q1 + (size_t)jj[t] * E_DIM + c);
        acc.x += wj[t] * v.x; acc.y += wj[t] * v.y;
        acc.z += wj[t] * v.z; acc.w += wj[t] * v.w;
    }
#pragma unroll
    for (int t = 0; t < 4; t++) {
        float4 v = *reinterpret_cast<const float4*>(g_Q2 + (size_t)kk2[t] * E_DIM + c);
        acc.x += wk2[t] * v.x; acc.y += wk2[t] * v.y;
        acc.z += wk2[t] * v.z; acc.w += wk2[t] * v.w;
    }
#pragma unroll
    for (int t = 0; t < 8; t++) {
        float4 v = *reinterpret_cast<const float4*>(g_Q3 + (size_t)mm[t] * E_DIM + c);
        acc.x += wm[t] * v.x; acc.y += wm[t] * v.y;
        acc.z += wm[t] * v.z; acc.w += wm[t] * v.w;
    }
    *reinterpret_cast<float4*>(out + (size_t)r * E_DIM + c) = acc;
}

// ---------------- batched tensor-core flash attention -----------------------
#define AST 68
#define ATTN_SMEM (3 * 64 * AST * 4)

__global__ void __launch_bounds__(128) attn_all()
{
    extern __shared__ uint32_t sm[];
    uint32_t* Qs = sm;
    uint32_t* Ks = sm + 64 * AST;
    uint32_t* Vs = sm + 2 * 64 * AST;
    uint32_t* Ps = Qs;

    const int bx = blockIdx.x;
    int lvl = 0;
#pragma unroll
    for (int i = 0; i < 3; i++) if (bx >= d_qbCum[i + 1]) lvl = i + 1;
    const int L = d_Llvl[lvl];
    const float* qkv = g_qkv + (size_t)d_qoff[lvl] * 3 * E_DIM;
    float* out = g_attn + (size_t)d_qoff[lvl] * E_DIM;

    const int h = blockIdx.y;
    const int q0 = (bx - d_qbCum[lvl]) * 64;
    const int tid = threadIdx.x;
    const int wid = tid >> 5;
    const int lane = tid & 31;
    const int g = lane >> 2;
    const int q = lane & 3;

    const int lc = (tid & 15) * 4;
    const int lr0 = tid >> 4;

#pragma unroll
    for (int it = 0; it < 8; it++) {
        int r = lr0 + it * 8;
        float4 v = *reinterpret_cast<const float4*>(
            qkv + (size_t)(q0 + r) * 3072 + h * 64 + lc);
        uint4 t = {f2tf32(v.x * 0.125f), f2tf32(v.y * 0.125f),
                   f2tf32(v.z * 0.125f), f2tf32(v.w * 0.125f)};
        *reinterpret_cast<uint4*>(Qs + r * AST + lc) = t;
    }
    __syncthreads();

    uint32_t qa[8][4];
    const int arow = wid * 16 + g;
#pragma unroll
    for (int kk = 0; kk < 8; kk++) {
        const uint32_t* p = Qs + arow * AST + kk * 8 + q;
        qa[kk][0] = p[0];
        qa[kk][1] = p[8 * AST];
        qa[kk][2] = p[4];
        qa[kk][3] = p[8 * AST + 4];
    }

    float m_i[2] = {-1e30f, -1e30f};
    float l_i[2] = {0.f, 0.f};
    float O[8][4];
#pragma unroll
    for (int ni = 0; ni < 8; ni++)
#pragma unroll
        for (int j = 0; j < 4; j++) O[ni][j] = 0.f;

    for (int kb = 0; kb < L; kb += 64) {
        __syncthreads();
#pragma unroll
        for (int it = 0; it < 8; it++) {
            int r = lr0 + it * 8;
            const float* base = qkv + (size_t)(kb + r) * 3072 + h * 64 + lc;
            float4 kv = *reinterpret_cast<const float4*>(base + 1024);
            uint4 kt = {f2tf32(kv.x), f2tf32(kv.y), f2tf32(kv.z), f2tf32(kv.w)};
            *reinterpret_cast<uint4*>(Ks + r * AST + lc) = kt;
            float4 vv = *reinterpret_cast<const float4*>(base + 2048);
            uint4 vt = {f2tf32(vv.x), f2tf32(vv.y), f2tf32(vv.z), f2tf32(vv.w)};
            *reinterpret_cast<uint4*>(Vs + r * AST + lc) = vt;
        }
        __syncthreads();

        float s[8][4];
#pragma unroll
        for (int ni = 0; ni < 8; ni++)
#pragma unroll
            for (int j = 0; j < 4; j++) s[ni][j] = 0.f;
#pragma unroll
        for (int kk = 0; kk < 8; kk++) {
            const int kc = kk * 8 + q;
#pragma unroll
            for (int ni = 0; ni < 8; ni++) {
                const uint32_t* p = Ks + (ni * 8 + g) * AST + kc;
                mma_tf32(s[ni], qa[kk], p[0], p[4]);
            }
        }

        float rmax0 = -1e30f, rmax1 = -1e30f;
#pragma unroll
        for (int ni = 0; ni < 8; ni++) {
            rmax0 = fmaxf(rmax0, fmaxf(s[ni][0], s[ni][1]));
            rmax1 = fmaxf(rmax1, fmaxf(s[ni][2], s[ni][3]));
        }
#pragma unroll
        for (int off = 1; off <= 2; off <<= 1) {
            rmax0 = fmaxf(rmax0, __shfl_xor_sync(0xffffffffu, rmax0, off));
            rmax1 = fmaxf(rmax1, __shfl_xor_sync(0xffffffffu, rmax1, off));
        }
        float mnew0 = fmaxf(m_i[0], rmax0);
        float mnew1 = fmaxf(m_i[1], rmax1);
        float al0 = __expf(m_i[0] - mnew0);
        float al1 = __expf(m_i[1] - mnew1);
        float sum0 = 0.f, sum1 = 0.f;
#pragma unroll
        for (int ni = 0; ni < 8; ni++) {
            s[ni][0] = __expf(s[ni][0] - mnew0);
            s[ni][1] = __expf(s[ni][1] - mnew0);
            s[ni][2] = __expf(s[ni][2] - mnew1);
            s[ni][3] = __expf(s[ni][3] - mnew1);
            sum0 += s[ni][0] + s[ni][1];
            sum1 += s[ni][2] + s[ni][3];
        }
#pragma unroll
        for (int off = 1; off <= 2; off <<= 1) {
            sum0 += __shfl_xor_sync(0xffffffffu, sum0, off);
            sum1 += __shfl_xor_sync(0xffffffffu, sum1, off);
        }
        l_i[0] = l_i[0] * al0 + sum0;
        l_i[1] = l_i[1] * al1 + sum1;
        m_i[0] = mnew0;
        m_i[1] = mnew1;
#pragma unroll
        for (int ni = 0; ni < 8; ni++) {
            O[ni][0] *= al0; O[ni][1] *= al0;
            O[ni][2] *= al1; O[ni][3] *= al1;
        }

        __syncwarp();
#pragma unroll
        for (int ni = 0; ni < 8; ni++) {
            const int col = ni * 8 + 2 * q;
            Ps[arow * AST + col]           = f2tf32(s[ni][0]);
            Ps[arow * AST + col + 1]       = f2tf32(s[ni][1]);
            Ps[(arow + 8) * AST + col]     = f2tf32(s[ni][2]);
            Ps[(arow + 8) * AST + col + 1] = f2tf32(s[ni][3]);
        }
        __syncwarp();

#pragma unroll
        for (int kk = 0; kk < 8; kk++) {
            uint32_t pa[4];
            const uint32_t* pp = Ps + arow * AST + kk * 8 + q;
            pa[0] = pp[0];
            pa[1] = pp[8 * AST];
            pa[2] = pp[4];
            pa[3] = pp[8 * AST + 4];
#pragma unroll
            for (int ni = 0; ni < 8; ni++) {
                const uint32_t* vp = Vs + (kk * 8 + q) * AST + ni * 8 + g;
                mma_tf32(O[ni], pa, vp[0], vp[4 * AST]);
            }
        }
    }

    const float inv0 = 1.0f / l_i[0];
    const float inv1 = 1.0f / l_i[1];
    const size_t row0 = (size_t)(q0 + arow);
#pragma unroll
    for (int ni = 0; ni < 8; ni++) {
        const int col = h * 64 + ni * 8 + 2 * q;
        *reinterpret_cast<float2*>(out + row0 * E_DIM + col) =
            make_float2(O[ni][0] * inv0, O[ni][1] * inv0);
        *reinterpret_cast<float2*>(out + (row0 + 8) * E_DIM + col) =
            make_float2(O[ni][2] * inv1, O[ni][3] * inv1);
    }
}

// ---------------- launcher --------------------------------------------------
extern "C" void kernel_launch(void* const* d_in, const int* in_sizes, int n_in,
                              void* d_out, int out_size)
{
    const float* query = (const float*)d_in[0];
    const float* in_w  = (const float*)d_in[1];
    const float* in_b  = (const float*)d_in[2];
    const float* out_w = (const float*)d_in[3];
    const float* out_b = (const float*)d_in[4];
    const float* up_w  = (const float*)d_in[5];
    const float* up_b  = (const float*)d_in[6];
    float* out = (float*)d_out;

    cudaFuncSetAttribute(gemm_qkv_all, cudaFuncAttributeMaxDynamicSharedMemorySize, GEMM_SMEM);
    cudaFuncSetAttribute(gemm_out_all, cudaFuncAttributeMaxDynamicSharedMemorySize, GEMM_SMEM);
    cudaFuncSetAttribute(combine_proj, cudaFuncAttributeMaxDynamicSharedMemorySize, GEMM_SMEM);
    cudaFuncSetAttribute(attn_all,     cudaFuncAttributeMaxDynamicSharedMemorySize, ATTN_SMEM);

    // 1. W1^T, W2^T
    transpose_w<<<dim3(32, 32, 2), dim3(32, 8)>>>(up_w);
    // 2. QKV all levels (+ P2 = W0@W1 hidden in grid)
    gemm_qkv_all<<<dim3(24, 33), 256, GEMM_SMEM>>>(query, in_w, in_b, up_w);
    // 3. attention all levels
    attn_all<<<dim3(60, 16), 128, ATTN_SMEM>>>();
    // 4. out-proj all levels (+ P3 = P2@W2 hidden in grid)
    gemm_out_all<<<dim3(8, 38), 256, GEMM_SMEM>>>(out_w, out_b);
    // 5. all combine projections + bias row, one launch
    combine_proj<<<116, 256, GEMM_SMEM>>>(up_w, up_b);
    // 6. final tap-composed upsample + residual sum
    final_combine<<<2048, 256>>>(out);
}

// round 8
// speedup vs baseline: 1.0563x; 1.0502x over previous
#include <cuda_runtime.h>
#include <cstdint>

#define E_DIM 1024
#define S_MAX 2048
#define LEVELS 4
#define R_TOT 3840   // 2048+1024+512+256

// ---------------- scratch ---------------------------------------------------
__device__ float g_qkv[R_TOT * 3 * E_DIM];
__device__ float g_attn[R_TOT * E_DIM];
__device__ float g_outs[R_TOT * E_DIM];
__device__ float g_W1T[E_DIM * E_DIM];
__device__ float g_W2T[E_DIM * E_DIM];
__device__ float g_P2[E_DIM * E_DIM];   // W0 @ W1   (M2 = P2^T)
__device__ float g_P3[E_DIM * E_DIM];   // P2 @ W2   (M3 = P3^T)
__device__ float g_Q1[1024 * E_DIM];    // o1 @ W0^T
__device__ float g_Q2[512 * E_DIM];     // o2 @ P2^T
__device__ float g_Q3[256 * E_DIM];     // o3 @ P3^T
__device__ float g_rrow[E_DIM];         // b2*M2 + b1*M1 + b0
__device__ float g_zb[E_DIM];           // zero bias

// ---------------- helpers ---------------------------------------------------
__device__ __forceinline__ uint32_t f2tf32(float f) {
    uint32_t r;
    asm("cvt.rna.tf32.f32 %0, %1;" : "=r"(r) : "f"(f));
    return r;
}

__device__ __forceinline__ void mma_tf32(float* c, const uint32_t* a,
                                         uint32_t b0, uint32_t b1) {
    asm volatile(
        "mma.sync.aligned.m16n8k8.row.col.f32.tf32.tf32.f32 "
        "{%0,%1,%2,%3}, {%4,%5,%6,%7}, {%8,%9}, {%0,%1,%2,%3};"
        : "+f"(c[0]), "+f"(c[1]), "+f"(c[2]), "+f"(c[3])
        : "r"(a[0]), "r"(a[1]), "r"(a[2]), "r"(a[3]), "r"(b0), "r"(b1));
}

__device__ __forceinline__ void cp_async16(uint32_t smem_addr, const void* gptr) {
    asm volatile("cp.async.cg.shared.global [%0], [%1], 16;\n"
                 :: "r"(smem_addr), "l"(gptr));
}
__device__ __forceinline__ void cp_commit() {
    asm volatile("cp.async.commit_group;\n" ::: "memory");
}
__device__ __forceinline__ void cp_wait0() {
    asm volatile("cp.async.wait_group 0;\n" ::: "memory");
}

// ---------------- shared GEMM core (cp.async, raw fp32 in smem) -------------
#define BM 128
#define BN 128
#define BK 32
#define SST 36
#define GEMM_SMEM (2 * 2 * BM * SST * 4)

__device__ __forceinline__ void gemm_core(
    const float* __restrict__ X, int ldx,   // A[bm.., K], row stride ldx
    const float* __restrict__ Wp,           // W + bn*K
    const float* __restrict__ bias,
    float* __restrict__ Y,
    int N, int K, int bm, int bn,
    uint32_t* As, uint32_t* Bs)
{
    const int tid = threadIdx.x;
    const int lane = tid & 31;
    const int wid = tid >> 5;
    const int warp_row = (wid & 1) * 64;
    const int warp_col = (wid >> 1) * 32;

    const int lc = (tid & 7) * 4;
    const int lr = tid >> 3;

    const uint32_t aBase = (uint32_t)__cvta_generic_to_shared(As);
    const uint32_t bBase = (uint32_t)__cvta_generic_to_shared(Bs);
    const float* Xp = X + (size_t)bm * ldx;

    float acc[4][4][4];
#pragma unroll
    for (int mi = 0; mi < 4; mi++)
#pragma unroll
        for (int ni = 0; ni < 4; ni++)
#pragma unroll
            for (int j = 0; j < 4; j++) acc[mi][ni][j] = 0.f;

#define G_PREFETCH(k0, sg)                                                     \
    {                                                                          \
        _Pragma("unroll") for (int it = 0; it < 4; it++) {                     \
            int r = lr + it * 32;                                              \
            cp_async16(aBase + ((sg)*BM*SST + r*SST + lc) * 4,                 \
                       Xp + (size_t)r * ldx + (k0) + lc);                      \
            cp_async16(bBase + ((sg)*BN*SST + r*SST + lc) * 4,                 \
                       Wp + (size_t)r * K + (k0) + lc);                        \
        }                                                                      \
        cp_commit();                                                           \
    }

    G_PREFETCH(0, 0);

    const int g = lane >> 2;
    const int q = lane & 3;

    for (int k0 = 0; k0 < K; k0 += BK) {
        const int s = (k0 / BK) & 1;
        const bool more = (k0 + BK) < K;

        cp_wait0();
        __syncthreads();
        if (more) G_PREFETCH(k0 + BK, s ^ 1);

        const uint32_t* Ab = As + s * BM * SST;
        const uint32_t* Bb = Bs + s * BN * SST;
#pragma unroll
        for (int kk = 0; kk < 4; kk++) {
            uint32_t af[4][4], bf[4][2];
            const int kc = kk * 8 + q;
#pragma unroll
            for (int mi = 0; mi < 4; mi++) {
                const uint32_t* p = Ab + (warp_row + mi * 16 + g) * SST + kc;
                af[mi][0] = f2tf32(__uint_as_float(p[0]));
                af[mi][1] = f2tf32(__uint_as_float(p[8 * SST]));
                af[mi][2] = f2tf32(__uint_as_float(p[4]));
                af[mi][3] = f2tf32(__uint_as_float(p[8 * SST + 4]));
            }
#pragma unroll
            for (int ni = 0; ni < 4; ni++) {
                const uint32_t* p = Bb + (warp_col + ni * 8 + g) * SST + kc;
                bf[ni][0] = f2tf32(__uint_as_float(p[0]));
                bf[ni][1] = f2tf32(__uint_as_float(p[4]));
            }
#pragma unroll
            for (int mi = 0; mi < 4; mi++)
#pragma unroll
                for (int ni = 0; ni < 4; ni++)
                    mma_tf32(acc[mi][ni], af[mi], bf[ni][0], bf[ni][1]);
        }
        __syncthreads();
    }

#pragma unroll
    for (int mi = 0; mi < 4; mi++) {
        const int row0 = bm + warp_row + mi * 16 + g;
#pragma unroll
        for (int ni = 0; ni < 4; ni++) {
            const int col = bn + warp_col + ni * 8 + 2 * q;
            float2 bb = *reinterpret_cast<const float2*>(bias + col);
            *reinterpret_cast<float2*>(Y + (size_t)row0 * N + col) =
                make_float2(acc[mi][ni][0] + bb.x, acc[mi][ni][1] + bb.y);
            *reinterpret_cast<float2*>(Y + (size_t)(row0 + 8) * N + col) =
                make_float2(acc[mi][ni][2] + bb.x, acc[mi][ni][3] + bb.y);
        }
    }
#undef G_PREFETCH
}

// level tables
__device__ __constant__ int d_qoff[4] = {0, 2048, 3072, 3584};
__device__ __constant__ int d_rbCum[5] = {0, 16, 24, 28, 30};
__device__ __constant__ int d_qbCum[5] = {0, 32, 48, 56, 60};
__device__ __constant__ int d_Llvl[4] = {2048, 1024, 512, 256};

// ---------------- weight transpose (W1, W2) ---------------------------------
__global__ void __launch_bounds__(256) transpose_w(const float* __restrict__ up_w)
{
    __shared__ float t[32][33];
    const float* src = up_w + (size_t)(blockIdx.z + 1) * E_DIM * E_DIM;
    float* dst = blockIdx.z == 0 ? g_W1T : g_W2T;
    int x = blockIdx.x * 32 + threadIdx.x;
    int y = blockIdx.y * 32 + threadIdx.y;
#pragma unroll
    for (int i = 0; i < 32; i += 8)
        t[threadIdx.y + i][threadIdx.x] = src[(size_t)(y + i) * E_DIM + x];
    __syncthreads();
    x = blockIdx.y * 32 + threadIdx.x;
    y = blockIdx.x * 32 + threadIdx.y;
#pragma unroll
    for (int i = 0; i < 32; i += 8)
        dst[(size_t)(y + i) * E_DIM + x] = t[threadIdx.x][threadIdx.y + i];
}

// ---------------- batched QKV projection (+ hidden P2 = W0@W1) --------------
__global__ void __launch_bounds__(256, 2) gemm_qkv_all(
    const float* __restrict__ query,
    const float* __restrict__ in_w,
    const float* __restrict__ in_b,
    const float* __restrict__ up_w)
{
    extern __shared__ uint32_t smem[];
    const int by = blockIdx.y;

    if (by >= 30) {   // P2 = W0 @ W1T^T
        int li = (by - 30) * gridDim.x + blockIdx.x;
        if (li >= 64) return;
        gemm_core(up_w, E_DIM, g_W1T + (size_t)(li % 8) * BN * E_DIM, g_zb, g_P2,
                  E_DIM, E_DIM, (li / 8) * BM, (li % 8) * BN,
                  smem, smem + 2 * BM * SST);
        return;
    }

    int lvl = 0;
#pragma unroll
    for (int i = 0; i < 3; i++) if (by >= d_rbCum[i + 1]) lvl = i + 1;
    const int bm = (by - d_rbCum[lvl]) * BM;
    const int bn = blockIdx.x * BN;
    const int stride = 1 << lvl;

    gemm_core(query, stride * E_DIM,
              in_w + (size_t)lvl * 3 * E_DIM * E_DIM + (size_t)bn * E_DIM,
              in_b + (size_t)lvl * 3 * E_DIM,
              g_qkv + (size_t)d_qoff[lvl] * 3 * E_DIM,
              3 * E_DIM, E_DIM, bm, bn,
              smem, smem + 2 * BM * SST);
}

// ---------------- batched out projection (+ hidden P3 = P2@W2) --------------
__global__ void __launch_bounds__(256, 2) gemm_out_all(
    const float* __restrict__ out_w,
    const float* __restrict__ out_b)
{
    extern __shared__ uint32_t smem[];
    const int by = blockIdx.y;

    if (by >= 30) {   // P3 = P2 @ W2T^T   (gridDim.x == 8)
        int li = (by - 30) * 8 + blockIdx.x;
        gemm_core(g_P2, E_DIM, g_W2T + (size_t)(li % 8) * BN * E_DIM, g_zb, g_P3,
                  E_DIM, E_DIM, (li / 8) * BM, (li % 8) * BN,
                  smem, smem + 2 * BM * SST);
        return;
    }

    int lvl = 0;
#pragma unroll
    for (int i = 0; i < 3; i++) if (by >= d_rbCum[i + 1]) lvl = i + 1;
    const int bm = (by - d_rbCum[lvl]) * BM;
    const int bn = blockIdx.x * BN;

    gemm_core(g_attn + (size_t)d_qoff[lvl] * E_DIM, E_DIM,
              out_w + (size_t)lvl * E_DIM * E_DIM + (size_t)bn * E_DIM,
              out_b + (size_t)lvl * E_DIM,
              g_outs + (size_t)d_qoff[lvl] * E_DIM,
              E_DIM, E_DIM, bm, bn,
              smem, smem + 2 * BM * SST);
}

// ---------------- one-launch combine projections + bias row -----------------
__global__ void __launch_bounds__(256, 2) combine_proj(
    const float* __restrict__ up_w,
    const float* __restrict__ up_b)
{
    extern __shared__ uint32_t smem[];
    const int li = blockIdx.x;

    if (li < 16) {
        gemm_core(g_outs + (size_t)d_qoff[3] * E_DIM, E_DIM,
                  g_P3 + (size_t)(li % 8) * BN * E_DIM, g_zb, g_Q3,
                  E_DIM, E_DIM, (li / 8) * BM, (li % 8) * BN,
                  smem, smem + 2 * BM * SST);
    } else if (li < 48) {
        int t = li - 16;
        gemm_core(g_outs + (size_t)d_qoff[2] * E_DIM, E_DIM,
                  g_P2 + (size_t)(t % 8) * BN * E_DIM, g_zb, g_Q2,
                  E_DIM, E_DIM, (t / 8) * BM, (t % 8) * BN,
                  smem, smem + 2 * BM * SST);
    } else if (li < 112) {
        int t = li - 48;
        gemm_core(g_outs + (size_t)d_qoff[1] * E_DIM, E_DIM,
                  up_w + (size_t)(t % 8) * BN * E_DIM, g_zb, g_Q1,
                  E_DIM, E_DIM, (t / 8) * BM, (t % 8) * BN,
                  smem, smem + 2 * BM * SST);
    } else {
        const float* b0 = up_b;
        const float* b1 = up_b + E_DIM;
        const float* b2 = up_b + 2 * E_DIM;
        int bi = li - 112;
        int warp = threadIdx.x >> 5, lane = threadIdx.x & 31;
        for (int cc = 0; cc < 32; cc++) {
            int c = bi * 256 + warp * 32 + cc;
            float s = 0.f;
            for (int k = lane; k < E_DIM; k += 32)
                s += b2[k] * g_P2[(size_t)c * E_DIM + k]
                   + b1[k] * up_w[(size_t)c * E_DIM + k];
#pragma unroll
            for (int off = 16; off; off >>= 1)
                s += __shfl_xor_sync(0xffffffffu, s, off);
            if (lane == 0) g_rrow[c] = s + b0[c];
        }
    }
}

// ---------------- final: out = up3(Q3) + up2(Q2) + up(Q1) + rrow + o0 -------
__device__ __forceinline__ void taps(float pos, int L, int& i0, int& i1, float& w)
{
    pos = fminf(fmaxf(pos, 0.f), (float)(L - 1));
    i0 = (int)floorf(pos);
    i1 = min(i0 + 1, L - 1);
    w = pos - (float)i0;
}

__global__ void __launch_bounds__(256) final_combine(float* __restrict__ out)
{
    const int r = blockIdx.x;
    const int c = threadIdx.x * 4;

    int j0, j1; float w1;
    taps(0.5f * r - 0.25f, 1024, j0, j1, w1);
    int jj[2] = {j0, j1};
    float wj[2] = {1.f - w1, w1};

    int kk2[4]; float wk2[4];
#pragma unroll
    for (int t = 0; t < 2; t++) {
        int a, b; float w;
        taps(0.5f * jj[t] - 0.25f, 512, a, b, w);
        kk2[2 * t] = a;     wk2[2 * t] = wj[t] * (1.f - w);
        kk2[2 * t + 1] = b; wk2[2 * t + 1] = wj[t] * w;
    }

    int mm[8]; float wm[8];
#pragma unroll
    for (int t = 0; t < 4; t++) {
        int a, b; float w;
        taps(0.5f * kk2[t] - 0.25f, 256, a, b, w);
        mm[2 * t] = a;     wm[2 * t] = wk2[t] * (1.f - w);
        mm[2 * t + 1] = b; wm[2 * t + 1] = wk2[t] * w;
    }

    float4 acc = *reinterpret_cast<const float4*>(g_outs + (size_t)r * E_DIM + c);
    float4 rr  = *reinterpret_cast<const float4*>(g_rrow + c);
    acc.x += rr.x; acc.y += rr.y; acc.z += rr.z; acc.w += rr.w;

#pragma unroll
    for (int t = 0; t < 2; t++) {
        float4 v = *reinterpret_cast<const float4*>(g_Q1 + (size_t)jj[t] * E_DIM + c);
        acc.x += wj[t] * v.x; acc.y += wj[t] * v.y;
        acc.z += wj[t] * v.z; acc.w += wj[t] * v.w;
    }
#pragma unroll
    for (int t = 0; t < 4; t++) {
        float4 v = *reinterpret_cast<const float4*>(g_Q2 + (size_t)kk2[t] * E_DIM + c);
        acc.x += wk2[t] * v.x; acc.y += wk2[t] * v.y;
        acc.z += wk2[t] * v.z; acc.w += wk2[t] * v.w;
    }
#pragma unroll
    for (int t = 0; t < 8; t++) {
        float4 v = *reinterpret_cast<const float4*>(g_Q3 + (size_t)mm[t] * E_DIM + c);
        acc.x += wm[t] * v.x; acc.y += wm[t] * v.y;
        acc.z += wm[t] * v.z; acc.w += wm[t] * v.w;
    }
    *reinterpret_cast<float4*>(out + (size_t)r * E_DIM + c) = acc;
}

// ---------------- batched tensor-core flash attention -----------------------
#define AST 68
#define ATTN_SMEM (3 * 64 * AST * 4)

__global__ void __launch_bounds__(128) attn_all()
{
    extern __shared__ uint32_t sm[];
    uint32_t* Qs = sm;
    uint32_t* Ks = sm + 64 * AST;
    uint32_t* Vs = sm + 2 * 64 * AST;
    uint32_t* Ps = Qs;

    const int bx = blockIdx.x;
    int lvl = 0;
#pragma unroll
    for (int i = 0; i < 3; i++) if (bx >= d_qbCum[i + 1]) lvl = i + 1;
    const int L = d_Llvl[lvl];
    const float* qkv = g_qkv + (size_t)d_qoff[lvl] * 3 * E_DIM;
    float* out = g_attn + (size_t)d_qoff[lvl] * E_DIM;

    const int h = blockIdx.y;
    const int q0 = (bx - d_qbCum[lvl]) * 64;
    const int tid = threadIdx.x;
    const int wid = tid >> 5;
    const int lane = tid & 31;
    const int g = lane >> 2;
    const int q = lane & 3;

    const int lc = (tid & 15) * 4;
    const int lr0 = tid >> 4;

#pragma unroll
    for (int it = 0; it < 8; it++) {
        int r = lr0 + it * 8;
        float4 v = *reinterpret_cast<const float4*>(
            qkv + (size_t)(q0 + r) * 3072 + h * 64 + lc);
        uint4 t = {f2tf32(v.x * 0.125f), f2tf32(v.y * 0.125f),
                   f2tf32(v.z * 0.125f), f2tf32(v.w * 0.125f)};
        *reinterpret_cast<uint4*>(Qs + r * AST + lc) = t;
    }
    __syncthreads();

    uint32_t qa[8][4];
    const int arow = wid * 16 + g;
#pragma unroll
    for (int kk = 0; kk < 8; kk++) {
        const uint32_t* p = Qs + arow * AST + kk * 8 + q;
        qa[kk][0] = p[0];
        qa[kk][1] = p[8 * AST];
        qa[kk][2] = p[4];
        qa[kk][3] = p[8 * AST + 4];
    }

    float m_i[2] = {-1e30f, -1e30f};
    float l_i[2] = {0.f, 0.f};
    float O[8][4];
#pragma unroll
    for (int ni = 0; ni < 8; ni++)
#pragma unroll
        for (int j = 0; j < 4; j++) O[ni][j] = 0.f;

    for (int kb = 0; kb < L; kb += 64) {
        __syncthreads();
#pragma unroll
        for (int it = 0; it < 8; it++) {
            int r = lr0 + it * 8;
            const float* base = qkv + (size_t)(kb + r) * 3072 + h * 64 + lc;
            float4 kv = *reinterpret_cast<const float4*>(base + 1024);
            uint4 kt = {f2tf32(kv.x), f2tf32(kv.y), f2tf32(kv.z), f2tf32(kv.w)};
            *reinterpret_cast<uint4*>(Ks + r * AST + lc) = kt;
            float4 vv = *reinterpret_cast<const float4*>(base + 2048);
            uint4 vt = {f2tf32(vv.x), f2tf32(vv.y), f2tf32(vv.z), f2tf32(vv.w)};
            *reinterpret_cast<uint4*>(Vs + r * AST + lc) = vt;
        }
        __syncthreads();

        float s[8][4];
#pragma unroll
        for (int ni = 0; ni < 8; ni++)
#pragma unroll
            for (int j = 0; j < 4; j++) s[ni][j] = 0.f;
#pragma unroll
        for (int kk = 0; kk < 8; kk++) {
            const int kc = kk * 8 + q;
#pragma unroll
            for (int ni = 0; ni < 8; ni++) {
                const uint32_t* p = Ks + (ni * 8 + g) * AST + kc;
                mma_tf32(s[ni], qa[kk], p[0], p[4]);
            }
        }

        float rmax0 = -1e30f, rmax1 = -1e30f;
#pragma unroll
        for (int ni = 0; ni < 8; ni++) {
            rmax0 = fmaxf(rmax0, fmaxf(s[ni][0], s[ni][1]));
            rmax1 = fmaxf(rmax1, fmaxf(s[ni][2], s[ni][3]));
        }
#pragma unroll
        for (int off = 1; off <= 2; off <<= 1) {
            rmax0 = fmaxf(rmax0, __shfl_xor_sync(0xffffffffu, rmax0, off));
            rmax1 = fmaxf(rmax1, __shfl_xor_sync(0xffffffffu, rmax1, off));
        }
        float mnew0 = fmaxf(m_i[0], rmax0);
        float mnew1 = fmaxf(m_i[1], rmax1);
        float al0 = __expf(m_i[0] - mnew0);
        float al1 = __expf(m_i[1] - mnew1);
        float sum0 = 0.f, sum1 = 0.f;
#pragma unroll
        for (int ni = 0; ni < 8; ni++) {
            s[ni][0] = __expf(s[ni][0] - mnew0);
            s[ni][1] = __expf(s[ni][1] - mnew0);
            s[ni][2] = __expf(s[ni][2] - mnew1);
            s[ni][3] = __expf(s[ni][3] - mnew1);
            sum0 += s[ni][0] + s[ni][1];
            sum1 += s[ni][2] + s[ni][3];
        }
#pragma unroll
        for (int off = 1; off <= 2; off <<= 1) {
            sum0 += __shfl_xor_sync(0xffffffffu, sum0, off);
            sum1 += __shfl_xor_sync(0xffffffffu, sum1, off);
        }
        l_i[0] = l_i[0] * al0 + sum0;
        l_i[1] = l_i[1] * al1 + sum1;
        m_i[0] = mnew0;
        m_i[1] = mnew1;
#pragma unroll
        for (int ni = 0; ni < 8; ni++) {
            O[ni][0] *= al0; O[ni][1] *= al0;
            O[ni][2] *= al1; O[ni][3] *= al1;
        }

        __syncwarp();
#pragma unroll
        for (int ni = 0; ni < 8; ni++) {
            const int col = ni * 8 + 2 * q;
            Ps[arow * AST + col]           = f2tf32(s[ni][0]);
            Ps[arow * AST + col + 1]       = f2tf32(s[ni][1]);
            Ps[(arow + 8) * AST + col]     = f2tf32(s[ni][2]);
            Ps[(arow + 8) * AST + col + 1] = f2tf32(s[ni][3]);
        }
        __syncwarp();

#pragma unroll
        for (int kk = 0; kk < 8; kk++) {
            uint32_t pa[4];
            const uint32_t* pp = Ps + arow * AST + kk * 8 + q;
            pa[0] = pp[0];
            pa[1] = pp[8 * AST];
            pa[2] = pp[4];
            pa[3] = pp[8 * AST + 4];
#pragma unroll
            for (int ni = 0; ni < 8; ni++) {
                const uint32_t* vp = Vs + (kk * 8 + q) * AST + ni * 8 + g;
                mma_tf32(O[ni], pa, vp[0], vp[4 * AST]);
            }
        }
    }

    const float inv0 = 1.0f / l_i[0];
    const float inv1 = 1.0f / l_i[1];
    const size_t row0 = (size_t)(q0 + arow);
#pragma unroll
    for (int ni = 0; ni < 8; ni++) {
        const int col = h * 64 + ni * 8 + 2 * q;
        *reinterpret_cast<float2*>(out + row0 * E_DIM + col) =
            make_float2(O[ni][0] * inv0, O[ni][1] * inv0);
        *reinterpret_cast<float2*>(out + (row0 + 8) * E_DIM + col) =
            make_float2(O[ni][2] * inv1, O[ni][3] * inv1);
    }
}

// ---------------- launcher --------------------------------------------------
extern "C" void kernel_launch(void* const* d_in, const int* in_sizes, int n_in,
                              void* d_out, int out_size)
{
    const float* query = (const float*)d_in[0];
    const float* in_w  = (const float*)d_in[1];
    const float* in_b  = (const float*)d_in[2];
    const float* out_w = (const float*)d_in[3];
    const float* out_b = (const float*)d_in[4];
    const float* up_w  = (const float*)d_in[5];
    const float* up_b  = (const float*)d_in[6];
    float* out = (float*)d_out;

    cudaFuncSetAttribute(gemm_qkv_all, cudaFuncAttributeMaxDynamicSharedMemorySize, GEMM_SMEM);
    cudaFuncSetAttribute(gemm_out_all, cudaFuncAttributeMaxDynamicSharedMemorySize, GEMM_SMEM);
    cudaFuncSetAttribute(combine_proj, cudaFuncAttributeMaxDynamicSharedMemorySize, GEMM_SMEM);
    cudaFuncSetAttribute(attn_all,     cudaFuncAttributeMaxDynamicSharedMemorySize, ATTN_SMEM);

    // 1. W1^T, W2^T
    transpose_w<<<dim3(32, 32, 2), dim3(32, 8)>>>(up_w);
    // 2. QKV all levels (+ P2 = W0@W1 hidden in grid)
    gemm_qkv_all<<<dim3(24, 33), 256, GEMM_SMEM>>>(query, in_w, in_b, up_w);
    // 3. attention all levels
    attn_all<<<dim3(60, 16), 128, ATTN_SMEM>>>();
    // 4. out-proj all levels (+ P3 = P2@W2 hidden in grid)
    gemm_out_all<<<dim3(8, 38), 256, GEMM_SMEM>>>(out_w, out_b);
    // 5. all combine projections + bias row, one launch
    combine_proj<<<116, 256, GEMM_SMEM>>>(up_w, up_b);
    // 6. final tap-composed upsample + residual sum
    final_combine<<<2048, 256>>>(out);
}

// round 11
// speedup vs baseline: 1.0654x; 1.0086x over previous
#include <cuda_runtime.h>
#include <cstdint>

#define E_DIM 1024
#define S_MAX 2048
#define LEVELS 4
#define R_TOT 3840   // 2048+1024+512+256

// ---------------- scratch ---------------------------------------------------
__device__ float g_qkv[R_TOT * 3 * E_DIM];
__device__ float g_attn[R_TOT * E_DIM];
__device__ float g_outs[R_TOT * E_DIM];
__device__ float g_W1T[E_DIM * E_DIM];
__device__ float g_W2T[E_DIM * E_DIM];
__device__ float g_P2[E_DIM * E_DIM];   // W0 @ W1   (M2 = P2^T)
__device__ float g_P3[E_DIM * E_DIM];   // P2 @ W2   (M3 = P3^T)
__device__ float g_Q1[1024 * E_DIM];    // o1 @ W0^T
__device__ float g_Q2[512 * E_DIM];     // o2 @ P2^T
__device__ float g_Q3[256 * E_DIM];     // o3 @ P3^T
__device__ float g_rrow[E_DIM];         // b2*M2 + b1*M1 + b0
__device__ float g_zb[E_DIM];           // zero bias
// tf32-pre-rounded copies of inputs
__device__ float g_qr[S_MAX * E_DIM];
__device__ float g_inw[LEVELS * 3 * E_DIM * E_DIM];
__device__ float g_outw[LEVELS * E_DIM * E_DIM];
__device__ float g_upw[(LEVELS - 1) * E_DIM * E_DIM];

// ---------------- helpers ---------------------------------------------------
__device__ __forceinline__ uint32_t f2tf32(float f) {
    uint32_t r;
    asm("cvt.rna.tf32.f32 %0, %1;" : "=r"(r) : "f"(f));
    return r;
}
__device__ __forceinline__ float rnd32(float f) {
    return __uint_as_float(f2tf32(f));
}

__device__ __forceinline__ void mma_tf32(float* c, const uint32_t* a,
                                         uint32_t b0, uint32_t b1) {
    asm volatile(
        "mma.sync.aligned.m16n8k8.row.col.f32.tf32.tf32.f32 "
        "{%0,%1,%2,%3}, {%4,%5,%6,%7}, {%8,%9}, {%0,%1,%2,%3};"
        : "+f"(c[0]), "+f"(c[1]), "+f"(c[2]), "+f"(c[3])
        : "r"(a[0]), "r"(a[1]), "r"(a[2]), "r"(a[3]), "r"(b0), "r"(b1));
}

__device__ __forceinline__ void cp_async16(uint32_t smem_addr, const void* gptr) {
    asm volatile("cp.async.cg.shared.global [%0], [%1], 16;\n"
                 :: "r"(smem_addr), "l"(gptr));
}
__device__ __forceinline__ void cp_commit() {
    asm volatile("cp.async.commit_group;\n" ::: "memory");
}
__device__ __forceinline__ void cp_wait0() {
    asm volatile("cp.async.wait_group 0;\n" ::: "memory");
}

// ---------------- tf32 pre-round kernel --------------------------------------
__global__ void __launch_bounds__(256) round_tf32(
    const float4* __restrict__ src, float4* __restrict__ dst, int n4)
{
    int i = blockIdx.x * blockDim.x + threadIdx.x;
    if (i < n4) {
        float4 v = src[i];
        float4 o;
        o.x = rnd32(v.x); o.y = rnd32(v.y);
        o.z = rnd32(v.z); o.w = rnd32(v.w);
        dst[i] = o;
    }
}

// ---------------- shared GEMM core (cp.async; operands pre-rounded) ---------
#define BM 128
#define BN 128
#define BK 32
#define SST 36
#define GEMM_SMEM (2 * 2 * BM * SST * 4)

__device__ __forceinline__ void gemm_core(
    const float* __restrict__ X, int ldx,   // A[bm.., K], row stride ldx
    const float* __restrict__ Wp,           // W + bn*K
    const float* __restrict__ bias,
    float* __restrict__ Y,
    int N, int K, int bm, int bn,
    uint32_t* As, uint32_t* Bs)
{
    const int tid = threadIdx.x;
    const int lane = tid & 31;
    const int wid = tid >> 5;
    const int warp_row = (wid & 1) * 64;
    const int warp_col = (wid >> 1) * 32;

    const int lc = (tid & 7) * 4;
    const int lr = tid >> 3;

    const uint32_t aBase = (uint32_t)__cvta_generic_to_shared(As);
    const uint32_t bBase = (uint32_t)__cvta_generic_to_shared(Bs);
    const float* Xp = X + (size_t)bm * ldx;

    float acc[4][4][4];
#pragma unroll
    for (int mi = 0; mi < 4; mi++)
#pragma unroll
        for (int ni = 0; ni < 4; ni++)
#pragma unroll
            for (int j = 0; j < 4; j++) acc[mi][ni][j] = 0.f;

#define G_PREFETCH(k0, sg)                                                     \
    {                                                                          \
        _Pragma("unroll") for (int it = 0; it < 4; it++) {                     \
            int r = lr + it * 32;                                              \
            cp_async16(aBase + ((sg)*BM*SST + r*SST + lc) * 4,                 \
                       Xp + (size_t)r * ldx + (k0) + lc);                      \
            cp_async16(bBase + ((sg)*BN*SST + r*SST + lc) * 4,                 \
                       Wp + (size_t)r * K + (k0) + lc);                        \
        }                                                                      \
        cp_commit();                                                           \
    }

    G_PREFETCH(0, 0);

    const int g = lane >> 2;
    const int q = lane & 3;

    for (int k0 = 0; k0 < K; k0 += BK) {
        const int s = (k0 / BK) & 1;
        const bool more = (k0 + BK) < K;

        cp_wait0();
        __syncthreads();
        if (more) G_PREFETCH(k0 + BK, s ^ 1);

        const uint32_t* Ab = As + s * BM * SST;
        const uint32_t* Bb = Bs + s * BN * SST;
#pragma unroll
        for (int kk = 0; kk < 4; kk++) {
            uint32_t af[4][4], bf[4][2];
            const int kc = kk * 8 + q;
#pragma unroll
            for (int mi = 0; mi < 4; mi++) {
                const uint32_t* p = Ab + (warp_row + mi * 16 + g) * SST + kc;
                af[mi][0] = p[0];
                af[mi][1] = p[8 * SST];
                af[mi][2] = p[4];
                af[mi][3] = p[8 * SST + 4];
            }
#pragma unroll
            for (int ni = 0; ni < 4; ni++) {
                const uint32_t* p = Bb + (warp_col + ni * 8 + g) * SST + kc;
                bf[ni][0] = p[0];
                bf[ni][1] = p[4];
            }
#pragma unroll
            for (int mi = 0; mi < 4; mi++)
#pragma unroll
                for (int ni = 0; ni < 4; ni++)
                    mma_tf32(acc[mi][ni], af[mi], bf[ni][0], bf[ni][1]);
        }
        __syncthreads();
    }

    // epilogue: add bias, tf32-round outputs (they feed later GEMMs as operands)
#pragma unroll
    for (int mi = 0; mi < 4; mi++) {
        const int row0 = bm + warp_row + mi * 16 + g;
#pragma unroll
        for (int ni = 0; ni < 4; ni++) {
            const int col = bn + warp_col + ni * 8 + 2 * q;
            float2 bb = *reinterpret_cast<const float2*>(bias + col);
            *reinterpret_cast<float2*>(Y + (size_t)row0 * N + col) =
                make_float2(rnd32(acc[mi][ni][0] + bb.x), rnd32(acc[mi][ni][1] + bb.y));
            *reinterpret_cast<float2*>(Y + (size_t)(row0 + 8) * N + col) =
                make_float2(rnd32(acc[mi][ni][2] + bb.x), rnd32(acc[mi][ni][3] + bb.y));
        }
    }
#undef G_PREFETCH
}

// level tables
__device__ __constant__ int d_qoff[4] = {0, 2048, 3072, 3584};
__device__ __constant__ int d_rbCum[5] = {0, 16, 24, 28, 30};
__device__ __constant__ int d_qbCum[5] = {0, 32, 48, 56, 60};
__device__ __constant__ int d_Llvl[4] = {2048, 1024, 512, 256};

// ---------------- weight transpose (W1, W2; src already rounded) ------------
__global__ void __launch_bounds__(256) transpose_w()
{
    __shared__ float t[32][33];
    const float* src = g_upw + (size_t)(blockIdx.z + 1) * E_DIM * E_DIM;
    float* dst = blockIdx.z == 0 ? g_W1T : g_W2T;
    int x = blockIdx.x * 32 + threadIdx.x;
    int y = blockIdx.y * 32 + threadIdx.y;
#pragma unroll
    for (int i = 0; i < 32; i += 8)
        t[threadIdx.y + i][threadIdx.x] = src[(size_t)(y + i) * E_DIM + x];
    __syncthreads();
    x = blockIdx.y * 32 + threadIdx.x;
    y = blockIdx.x * 32 + threadIdx.y;
#pragma unroll
    for (int i = 0; i < 32; i += 8)
        dst[(size_t)(y + i) * E_DIM + x] = t[threadIdx.x][threadIdx.y + i];
}

// ---------------- batched QKV projection (+ hidden P2 = W0@W1) --------------
__global__ void __launch_bounds__(256, 2) gemm_qkv_all(
    const float* __restrict__ in_b)
{
    extern __shared__ uint32_t smem[];
    const int by = blockIdx.y;

    if (by >= 30) {   // P2 = W0 @ W1T^T
        int li = (by - 30) * gridDim.x + blockIdx.x;
        if (li >= 64) return;
        gemm_core(g_upw, E_DIM, g_W1T + (size_t)(li % 8) * BN * E_DIM, g_zb, g_P2,
                  E_DIM, E_DIM, (li / 8) * BM, (li % 8) * BN,
                  smem, smem + 2 * BM * SST);
        return;
    }

    int lvl = 0;
#pragma unroll
    for (int i = 0; i < 3; i++) if (by >= d_rbCum[i + 1]) lvl = i + 1;
    const int bm = (by - d_rbCum[lvl]) * BM;
    const int bn = blockIdx.x * BN;
    const int stride = 1 << lvl;

    gemm_core(g_qr, stride * E_DIM,
              g_inw + (size_t)lvl * 3 * E_DIM * E_DIM + (size_t)bn * E_DIM,
              in_b + (size_t)lvl * 3 * E_DIM,
              g_qkv + (size_t)d_qoff[lvl] * 3 * E_DIM,
              3 * E_DIM, E_DIM, bm, bn,
              smem, smem + 2 * BM * SST);
}

// ---------------- batched out projection (+ hidden P3 = P2@W2) --------------
__global__ void __launch_bounds__(256, 2) gemm_out_all(
    const float* __restrict__ out_b)
{
    extern __shared__ uint32_t smem[];
    const int by = blockIdx.y;

    if (by >= 30) {   // P3 = P2 @ W2T^T   (gridDim.x == 8)
        int li = (by - 30) * 8 + blockIdx.x;
        gemm_core(g_P2, E_DIM, g_W2T + (size_t)(li % 8) * BN * E_DIM, g_zb, g_P3,
                  E_DIM, E_DIM, (li / 8) * BM, (li % 8) * BN,
                  smem, smem + 2 * BM * SST);
        return;
    }

    int lvl = 0;
#pragma unroll
    for (int i = 0; i < 3; i++) if (by >= d_rbCum[i + 1]) lvl = i + 1;
    const int bm = (by - d_rbCum[lvl]) * BM;
    const int bn = blockIdx.x * BN;

    gemm_core(g_attn + (size_t)d_qoff[lvl] * E_DIM, E_DIM,
              g_outw + (size_t)lvl * E_DIM * E_DIM + (size_t)bn * E_DIM,
              out_b + (size_t)lvl * E_DIM,
              g_outs + (size_t)d_qoff[lvl] * E_DIM,
              E_DIM, E_DIM, bm, bn,
              smem, smem + 2 * BM * SST);
}

// ---------------- one-launch combine projections + bias row -----------------
__global__ void __launch_bounds__(256, 2) combine_proj(
    const float* __restrict__ up_b)
{
    extern __shared__ uint32_t smem[];
    const int li = blockIdx.x;

    if (li < 16) {
        gemm_core(g_outs + (size_t)d_qoff[3] * E_DIM, E_DIM,
                  g_P3 + (size_t)(li % 8) * BN * E_DIM, g_zb, g_Q3,
                  E_DIM, E_DIM, (li / 8) * BM, (li % 8) * BN,
                  smem, smem + 2 * BM * SST);
    } else if (li < 48) {
        int t = li - 16;
        gemm_core(g_outs + (size_t)d_qoff[2] * E_DIM, E_DIM,
                  g_P2 + (size_t)(t % 8) * BN * E_DIM, g_zb, g_Q2,
                  E_DIM, E_DIM, (t / 8) * BM, (t % 8) * BN,
                  smem, smem + 2 * BM * SST);
    } else if (li < 112) {
        int t = li - 48;
        gemm_core(g_outs + (size_t)d_qoff[1] * E_DIM, E_DIM,
                  g_upw + (size_t)(t % 8) * BN * E_DIM, g_zb, g_Q1,
                  E_DIM, E_DIM, (t / 8) * BM, (t % 8) * BN,
                  smem, smem + 2 * BM * SST);
    } else {
        const float* b0 = up_b;
        const float* b1 = up_b + E_DIM;
        const float* b2 = up_b + 2 * E_DIM;
        int bi = li - 112;
        int warp = threadIdx.x >> 5, lane = threadIdx.x & 31;
        for (int cc = 0; cc < 32; cc++) {
            int c = bi * 256 + warp * 32 + cc;
            float s = 0.f;
            for (int k = lane; k < E_DIM; k += 32)
                s += b2[k] * g_P2[(size_t)c * E_DIM + k]
                   + b1[k] * g_upw[(size_t)c * E_DIM + k];
#pragma unroll
            for (int off = 16; off; off >>= 1)
                s += __shfl_xor_sync(0xffffffffu, s, off);
            if (lane == 0) g_rrow[c] = s + b0[c];
        }
    }
}

// ---------------- final: out = up3(Q3) + up2(Q2) + up(Q1) + rrow + o0 -------
__device__ __forceinline__ void taps(float pos, int L, int& i0, int& i1, float& w)
{
    pos = fminf(fmaxf(pos, 0.f), (float)(L - 1));
    i0 = (int)floorf(pos);
    i1 = min(i0 + 1, L - 1);
    w = pos - (float)i0;
}

__global__ void __launch_bounds__(256) final_combine(float* __restrict__ out)
{
    const int r = blockIdx.x;
    const int c = threadIdx.x * 4;

    int j0, j1; float w1;
    taps(0.5f * r - 0.25f, 1024, j0, j1, w1);
    int jj[2] = {j0, j1};
    float wj[2] = {1.f - w1, w1};

    int kk2[4]; float wk2[4];
#pragma unroll
    for (int t = 0; t < 2; t++) {
        int a, b; float w;
        taps(0.5f * jj[t] - 0.25f, 512, a, b, w);
        kk2[2 * t] = a;     wk2[2 * t] = wj[t] * (1.f - w);
        kk2[2 * t + 1] = b; wk2[2 * t + 1] = wj[t] * w;
    }

    int mm[8]; float wm[8];
#pragma unroll
    for (int t = 0; t < 4; t++) {
        int a, b; float w;
        taps(0.5f * kk2[t] - 0.25f, 256, a, b, w);
        mm[2 * t] = a;     wm[2 * t] = wk2[t] * (1.f - w);
        mm[2 * t + 1] = b; wm[2 * t + 1] = wk2[t] * w;
    }

    float4 acc = *reinterpret_cast<const float4*>(g_outs + (size_t)r * E_DIM + c);
    float4 rr  = *reinterpret_cast<const float4*>(g_rrow + c);
    acc.x += rr.x; acc.y += rr.y; acc.z += rr.z; acc.w += rr.w;

#pragma unroll
    for (int t = 0; t < 2; t++) {
        float4 v = *reinterpret_cast<const float4*>(g_Q1 + (size_t)jj[t] * E_DIM + c);
        acc.x += wj[t] * v.x; acc.y += wj[t] * v.y;
        acc.z += wj[t] * v.z; acc.w += wj[t] * v.w;
    }
#pragma unroll
    for (int t = 0; t < 4; t++) {
        float4 v = *reinterpret_cast<const float4*>(g_Q2 + (size_t)kk2[t] * E_DIM + c);
        acc.x += wk2[t] * v.x; acc.y += wk2[t] * v.y;
        acc.z += wk2[t] * v.z; acc.w += wk2[t] * v.w;
    }
#pragma unroll
    for (int t = 0; t < 8; t++) {
        float4 v = *reinterpret_cast<const float4*>(g_Q3 + (size_t)mm[t] * E_DIM + c);
        acc.x += wm[t] * v.x; acc.y += wm[t] * v.y;
        acc.z += wm[t] * v.z; acc.w += wm[t] * v.w;
    }
    *reinterpret_cast<float4*>(out + (size_t)r * E_DIM + c) = acc;
}

// ---------------- batched tensor-core flash attention -----------------------
#define AST 68
#define ATTN_SMEM (3 * 64 * AST * 4)

__global__ void __launch_bounds__(128) attn_all()
{
    extern __shared__ uint32_t sm[];
    uint32_t* Qs = sm;
    uint32_t* Ks = sm + 64 * AST;
    uint32_t* Vs = sm + 2 * 64 * AST;
    uint32_t* Ps = Qs;

    const int bx = blockIdx.x;
    int lvl = 0;
#pragma unroll
    for (int i = 0; i < 3; i++) if (bx >= d_qbCum[i + 1]) lvl = i + 1;
    const int L = d_Llvl[lvl];
    const float* qkv = g_qkv + (size_t)d_qoff[lvl] * 3 * E_DIM;
    float* out = g_attn + (size_t)d_qoff[lvl] * E_DIM;

    const int h = blockIdx.y;
    const int q0 = (bx - d_qbCum[lvl]) * 64;
    const int tid = threadIdx.x;
    const int wid = tid >> 5;
    const int lane = tid & 31;
    const int g = lane >> 2;
    const int q = lane & 3;

    const int lc = (tid & 15) * 4;
    const int lr0 = tid >> 4;

#pragma unroll
    for (int it = 0; it < 8; it++) {
        int r = lr0 + it * 8;
        float4 v = *reinterpret_cast<const float4*>(
            qkv + (size_t)(q0 + r) * 3072 + h * 64 + lc);
        uint4 t = {f2tf32(v.x * 0.125f), f2tf32(v.y * 0.125f),
                   f2tf32(v.z * 0.125f), f2tf32(v.w * 0.125f)};
        *reinterpret_cast<uint4*>(Qs + r * AST + lc) = t;
    }
    __syncthreads();

    uint32_t qa[8][4];
    const int arow = wid * 16 + g;
#pragma unroll
    for (int kk = 0; kk < 8; kk++) {
        const uint32_t* p = Qs + arow * AST + kk * 8 + q;
        qa[kk][0] = p[0];
        qa[kk][1] = p[8 * AST];
        qa[kk][2] = p[4];
        qa[kk][3] = p[8 * AST + 4];
    }

    float m_i[2] = {-1e30f, -1e30f};
    float l_i[2] = {0.f, 0.f};
    float O[8][4];
#pragma unroll
    for (int ni = 0; ni < 8; ni++)
#pragma unroll
        for (int j = 0; j < 4; j++) O[ni][j] = 0.f;

    for (int kb = 0; kb < L; kb += 64) {
        __syncthreads();
#pragma unroll
        for (int it = 0; it < 8; it++) {
            int r = lr0 + it * 8;
            const float* base = qkv + (size_t)(kb + r) * 3072 + h * 64 + lc;
            float4 kv = *reinterpret_cast<const float4*>(base + 1024);
            uint4 kt = {f2tf32(kv.x), f2tf32(kv.y), f2tf32(kv.z), f2tf32(kv.w)};
            *reinterpret_cast<uint4*>(Ks + r * AST + lc) = kt;
            float4 vv = *reinterpret_cast<const float4*>(base + 2048);
            uint4 vt = {f2tf32(vv.x), f2tf32(vv.y), f2tf32(vv.z), f2tf32(vv.w)};
            *reinterpret_cast<uint4*>(Vs + r * AST + lc) = vt;
        }
        __syncthreads();

        float s[8][4];
#pragma unroll
        for (int ni = 0; ni < 8; ni++)
#pragma unroll
            for (int j = 0; j < 4; j++) s[ni][j] = 0.f;
#pragma unroll
        for (int kk = 0; kk < 8; kk++) {
            const int kc = kk * 8 + q;
#pragma unroll
            for (int ni = 0; ni < 8; ni++) {
                const uint32_t* p = Ks + (ni * 8 + g) * AST + kc;
                mma_tf32(s[ni], qa[kk], p[0], p[4]);
            }
        }

        float rmax0 = -1e30f, rmax1 = -1e30f;
#pragma unroll
        for (int ni = 0; ni < 8; ni++) {
            rmax0 = fmaxf(rmax0, fmaxf(s[ni][0], s[ni][1]));
            rmax1 = fmaxf(rmax1, fmaxf(s[ni][2], s[ni][3]));
        }
#pragma unroll
        for (int off = 1; off <= 2; off <<= 1) {
            rmax0 = fmaxf(rmax0, __shfl_xor_sync(0xffffffffu, rmax0, off));
            rmax1 = fmaxf(rmax1, __shfl_xor_sync(0xffffffffu, rmax1, off));
        }
        float mnew0 = fmaxf(m_i[0], rmax0);
        float mnew1 = fmaxf(m_i[1], rmax1);
        float al0 = __expf(m_i[0] - mnew0);
        float al1 = __expf(m_i[1] - mnew1);
        float sum0 = 0.f, sum1 = 0.f;
#pragma unroll
        for (int ni = 0; ni < 8; ni++) {
            s[ni][0] = __expf(s[ni][0] - mnew0);
            s[ni][1] = __expf(s[ni][1] - mnew0);
            s[ni][2] = __expf(s[ni][2] - mnew1);
            s[ni][3] = __expf(s[ni][3] - mnew1);
            sum0 += s[ni][0] + s[ni][1];
            sum1 += s[ni][2] + s[ni][3];
        }
#pragma unroll
        for (int off = 1; off <= 2; off <<= 1) {
            sum0 += __shfl_xor_sync(0xffffffffu, sum0, off);
            sum1 += __shfl_xor_sync(0xffffffffu, sum1, off);
        }
        l_i[0] = l_i[0] * al0 + sum0;
        l_i[1] = l_i[1] * al1 + sum1;
        m_i[0] = mnew0;
        m_i[1] = mnew1;
#pragma unroll
        for (int ni = 0; ni < 8; ni++) {
            O[ni][0] *= al0; O[ni][1] *= al0;
            O[ni][2] *= al1; O[ni][3] *= al1;
        }

        __syncwarp();
#pragma unroll
        for (int ni = 0; ni < 8; ni++) {
            const int col = ni * 8 + 2 * q;
            Ps[arow * AST + col]           = f2tf32(s[ni][0]);
            Ps[arow * AST + col + 1]       = f2tf32(s[ni][1]);
            Ps[(arow + 8) * AST + col]     = f2tf32(s[ni][2]);
            Ps[(arow + 8) * AST + col + 1] = f2tf32(s[ni][3]);
        }
        __syncwarp();

#pragma unroll
        for (int kk = 0; kk < 8; kk++) {
            uint32_t pa[4];
            const uint32_t* pp = Ps + arow * AST + kk * 8 + q;
            pa[0] = pp[0];
            pa[1] = pp[8 * AST];
            pa[2] = pp[4];
            pa[3] = pp[8 * AST + 4];
#pragma unroll
            for (int ni = 0; ni < 8; ni++) {
                const uint32_t* vp = Vs + (kk * 8 + q) * AST + ni * 8 + g;
                mma_tf32(O[ni], pa, vp[0], vp[4 * AST]);
            }
        }
    }

    // normalize + tf32-round (g_attn feeds out-proj as an A operand)
    const float inv0 = 1.0f / l_i[0];
    const float inv1 = 1.0f / l_i[1];
    const size_t row0 = (size_t)(q0 + arow);
#pragma unroll
    for (int ni = 0; ni < 8; ni++) {
        const int col = h * 64 + ni * 8 + 2 * q;
        *reinterpret_cast<float2*>(out + row0 * E_DIM + col) =
            make_float2(rnd32(O[ni][0] * inv0), rnd32(O[ni][1] * inv0));
        *reinterpret_cast<float2*>(out + (row0 + 8) * E_DIM + col) =
            make_float2(rnd32(O[ni][2] * inv1), rnd32(O[ni][3] * inv1));
    }
}

// ---------------- launcher --------------------------------------------------
extern "C" void kernel_launch(void* const* d_in, const int* in_sizes, int n_in,
                              void* d_out, int out_size)
{
    const float* query = (const float*)d_in[0];
    const float* in_w  = (const float*)d_in[1];
    const float* in_b  = (const float*)d_in[2];
    const float* out_w = (const float*)d_in[3];
    const float* out_b = (const float*)d_in[4];
    const float* up_w  = (const float*)d_in[5];
    const float* up_b  = (const float*)d_in[6];
    float* out = (float*)d_out;

    cudaFuncSetAttribute(gemm_qkv_all, cudaFuncAttributeMaxDynamicSharedMemorySize, GEMM_SMEM);
    cudaFuncSetAttribute(gemm_out_all, cudaFuncAttributeMaxDynamicSharedMemorySize, GEMM_SMEM);
    cudaFuncSetAttribute(combine_proj, cudaFuncAttributeMaxDynamicSharedMemorySize, GEMM_SMEM);
    cudaFuncSetAttribute(attn_all,     cudaFuncAttributeMaxDynamicSharedMemorySize, ATTN_SMEM);

    float *qr, *inw, *outw, *upw;
    cudaGetSymbolAddress((void**)&qr,   g_qr);
    cudaGetSymbolAddress((void**)&inw,  g_inw);
    cudaGetSymbolAddress((void**)&outw, g_outw);
    cudaGetSymbolAddress((void**)&upw,  g_upw);

    // 0. tf32 pre-round inputs (operand rounding moves here; mainloops go cvt-free)
    {
        int n4;
        n4 = S_MAX * E_DIM / 4;
        round_tf32<<<(n4 + 255) / 256, 256>>>((const float4*)query, (float4*)qr, n4);
        n4 = LEVELS * 3 * E_DIM * E_DIM / 4;
        round_tf32<<<(n4 + 255) / 256, 256>>>((const float4*)in_w, (float4*)inw, n4);
        n4 = LEVELS * E_DIM * E_DIM / 4;
        round_tf32<<<(n4 + 255) / 256, 256>>>((const float4*)out_w, (float4*)outw, n4);
        n4 = (LEVELS - 1) * E_DIM * E_DIM / 4;
        round_tf32<<<(n4 + 255) / 256, 256>>>((const float4*)up_w, (float4*)upw, n4);
    }

    // 1. W1^T, W2^T (from rounded up_w)
    transpose_w<<<dim3(32, 32, 2), dim3(32, 8)>>>();
    // 2. QKV all levels (+ P2 = W0@W1 hidden in grid)
    gemm_qkv_all<<<dim3(24, 33), 256, GEMM_SMEM>>>(in_b);
    // 3. attention all levels
    attn_all<<<dim3(60, 16), 128, ATTN_SMEM>>>();
    // 4. out-proj all levels (+ P3 = P2@W2 hidden in grid)
    gemm_out_all<<<dim3(8, 38), 256, GEMM_SMEM>>>(out_b);
    // 5. all combine projections + bias row, one launch
    combine_proj<<<116, 256, GEMM_SMEM>>>(up_b);
    // 6. final tap-composed upsample + residual sum
    final_combine<<<2048, 256>>>(out);
}

// round 13
// speedup vs baseline: 1.3055x; 1.2253x over previous
#include <cuda_runtime.h>
#include <cuda_fp16.h>
#include <cstdint>

#define E_DIM 1024
#define S_MAX 2048
#define LEVELS 4
#define R_TOT 3840   // 2048+1024+512+256

// ---------------- scratch ---------------------------------------------------
__device__ __half g_qkvh[R_TOT * 3 * E_DIM];
__device__ __half g_attnh[R_TOT * E_DIM];
__device__ __half g_outsh[R_TOT * E_DIM];
__device__ float  g_outsf[R_TOT * E_DIM];
__device__ __half g_W1T[E_DIM * E_DIM];
__device__ __half g_W2T[E_DIM * E_DIM];
__device__ __half g_P2h[E_DIM * E_DIM];   // W0 @ W1
__device__ __half g_P3h[E_DIM * E_DIM];   // P2 @ W2
__device__ float  g_Q1[1024 * E_DIM];
__device__ float  g_Q2[512 * E_DIM];
__device__ float  g_Q3[256 * E_DIM];
__device__ float  g_rrow[E_DIM];
__device__ float  g_zb[E_DIM];
// fp16 copies of inputs
__device__ __half g_qrh[S_MAX * E_DIM];
__device__ __half g_inwh[LEVELS * 3 * E_DIM * E_DIM];
__device__ __half g_outwh[LEVELS * E_DIM * E_DIM];
__device__ __half g_upwh[(LEVELS - 1) * E_DIM * E_DIM];

// ---------------- helpers ---------------------------------------------------
__device__ __forceinline__ void mma_f16(float* c, const uint32_t* a,
                                        uint32_t b0, uint32_t b1) {
    asm volatile(
        "mma.sync.aligned.m16n8k16.row.col.f32.f16.f16.f32 "
        "{%0,%1,%2,%3}, {%4,%5,%6,%7}, {%8,%9}, {%0,%1,%2,%3};"
        : "+f"(c[0]), "+f"(c[1]), "+f"(c[2]), "+f"(c[3])
        : "r"(a[0]), "r"(a[1]), "r"(a[2]), "r"(a[3]), "r"(b0), "r"(b1));
}

__device__ __forceinline__ void cp_async16(uint32_t smem_addr, const void* gptr) {
    asm volatile("cp.async.cg.shared.global [%0], [%1], 16;\n"
                 :: "r"(smem_addr), "l"(gptr));
}
__device__ __forceinline__ void cp_commit() {
    asm volatile("cp.async.commit_group;\n" ::: "memory");
}
__device__ __forceinline__ void cp_wait0() {
    asm volatile("cp.async.wait_group 0;\n" ::: "memory");
}

// ---------------- fp32 -> fp16 prep kernel ----------------------------------
__global__ void __launch_bounds__(256) round_h(
    const float4* __restrict__ src, __half* __restrict__ dst, int n4)
{
    int i = blockIdx.x * blockDim.x + threadIdx.x;
    if (i < n4) {
        float4 v = src[i];
        __half2* d = reinterpret_cast<__half2*>(dst + (size_t)i * 4);
        d[0] = __floats2half2_rn(v.x, v.y);
        d[1] = __floats2half2_rn(v.z, v.w);
    }
}

// ---------------- fp16 GEMM core ---------------------------------------------
// Y = X[half] @ W[half,N rows of K]^T + bias ; BK=32, padded rows SSTH=40 halfs.
#define BM 128
#define BN 128
#define BK 32
#define SSTH 40
#define GEMM_SMEM (2 * 2 * BM * SSTH * 2)   // 40960 B

__device__ __forceinline__ void gemm_core(
    const __half* __restrict__ X, int ldx,
    const __half* __restrict__ Wp,          // W + bn*K
    const float* __restrict__ bias,
    __half* __restrict__ Yh,                // nullable
    float* __restrict__ Yf,                 // nullable
    int N, int K, int bm, int bn,
    __half* As, __half* Bs)
{
    const int tid = threadIdx.x;
    const int lane = tid & 31;
    const int wid = tid >> 5;
    const int warp_row = (wid & 1) * 64;
    const int warp_col = (wid >> 1) * 32;

    const int lr = tid >> 2;        // 0..63 row base (2 its of 64 rows)
    const int kb = (tid & 3) * 8;   // half offset in 32-half row

    const uint32_t aBase = (uint32_t)__cvta_generic_to_shared(As);
    const uint32_t bBase = (uint32_t)__cvta_generic_to_shared(Bs);
    const __half* Xp = X + (size_t)bm * ldx;

    float acc[4][4][4];
#pragma unroll
    for (int mi = 0; mi < 4; mi++)
#pragma unroll
        for (int ni = 0; ni < 4; ni++)
#pragma unroll
            for (int j = 0; j < 4; j++) acc[mi][ni][j] = 0.f;

#define G_PREFETCH(k0, sg)                                                     \
    {                                                                          \
        _Pragma("unroll") for (int it = 0; it < 2; it++) {                     \
            int r = lr + it * 64;                                              \
            cp_async16(aBase + ((sg)*BM*SSTH + r*SSTH + kb) * 2,               \
                       Xp + (size_t)r * ldx + (k0) + kb);                      \
            cp_async16(bBase + ((sg)*BN*SSTH + r*SSTH + kb) * 2,               \
                       Wp + (size_t)r * K + (k0) + kb);                        \
        }                                                                      \
        cp_commit();                                                           \
    }

    G_PREFETCH(0, 0);

    const int g = lane >> 2;
    const int q = lane & 3;

    for (int k0 = 0; k0 < K; k0 += BK) {
        const int s = (k0 / BK) & 1;
        const bool more = (k0 + BK) < K;

        cp_wait0();
        __syncthreads();
        if (more) G_PREFETCH(k0 + BK, s ^ 1);

        const __half* Ab = As + s * BM * SSTH;
        const __half* Bb = Bs + s * BN * SSTH;
#pragma unroll
        for (int ks = 0; ks < 2; ks++) {
            const int kc = ks * 16 + 2 * q;
            uint32_t af[4][4], bf[4][2];
#pragma unroll
            for (int mi = 0; mi < 4; mi++) {
                const __half* p = Ab + (warp_row + mi * 16 + g) * SSTH + kc;
                af[mi][0] = *reinterpret_cast<const uint32_t*>(p);
                af[mi][1] = *reinterpret_cast<const uint32_t*>(p + 8 * SSTH);
                af[mi][2] = *reinterpret_cast<const uint32_t*>(p + 8);
                af[mi][3] = *reinterpret_cast<const uint32_t*>(p + 8 * SSTH + 8);
            }
#pragma unroll
            for (int ni = 0; ni < 4; ni++) {
                const __half* p = Bb + (warp_col + ni * 8 + g) * SSTH + kc;
                bf[ni][0] = *reinterpret_cast<const uint32_t*>(p);
                bf[ni][1] = *reinterpret_cast<const uint32_t*>(p + 8);
            }
#pragma unroll
            for (int mi = 0; mi < 4; mi++)
#pragma unroll
                for (int ni = 0; ni < 4; ni++)
                    mma_f16(acc[mi][ni], af[mi], bf[ni][0], bf[ni][1]);
        }
        __syncthreads();
    }

#pragma unroll
    for (int mi = 0; mi < 4; mi++) {
        const int row0 = bm + warp_row + mi * 16 + g;
#pragma unroll
        for (int ni = 0; ni < 4; ni++) {
            const int col = bn + warp_col + ni * 8 + 2 * q;
            float2 bb = *reinterpret_cast<const float2*>(bias + col);
            float v0 = acc[mi][ni][0] + bb.x;
            float v1 = acc[mi][ni][1] + bb.y;
            float v2 = acc[mi][ni][2] + bb.x;
            float v3 = acc[mi][ni][3] + bb.y;
            if (Yh) {
                *reinterpret_cast<__half2*>(Yh + (size_t)row0 * N + col) =
                    __floats2half2_rn(v0, v1);
                *reinterpret_cast<__half2*>(Yh + (size_t)(row0 + 8) * N + col) =
                    __floats2half2_rn(v2, v3);
            }
            if (Yf) {
                *reinterpret_cast<float2*>(Yf + (size_t)row0 * N + col) =
                    make_float2(v0, v1);
                *reinterpret_cast<float2*>(Yf + (size_t)(row0 + 8) * N + col) =
                    make_float2(v2, v3);
            }
        }
    }
#undef G_PREFETCH
}

// level tables
__device__ __constant__ int d_qoff[4] = {0, 2048, 3072, 3584};
__device__ __constant__ int d_rbCum[5] = {0, 16, 24, 28, 30};
__device__ __constant__ int d_qbCum[5] = {0, 32, 48, 56, 60};
__device__ __constant__ int d_Llvl[4] = {2048, 1024, 512, 256};

// ---------------- weight transpose (W1, W2; half) ---------------------------
__global__ void __launch_bounds__(256) transpose_w()
{
    __shared__ __half t[32][33];
    const __half* src = g_upwh + (size_t)(blockIdx.z + 1) * E_DIM * E_DIM;
    __half* dst = blockIdx.z == 0 ? g_W1T : g_W2T;
    int x = blockIdx.x * 32 + threadIdx.x;
    int y = blockIdx.y * 32 + threadIdx.y;
#pragma unroll
    for (int i = 0; i < 32; i += 8)
        t[threadIdx.y + i][threadIdx.x] = src[(size_t)(y + i) * E_DIM + x];
    __syncthreads();
    x = blockIdx.y * 32 + threadIdx.x;
    y = blockIdx.x * 32 + threadIdx.y;
#pragma unroll
    for (int i = 0; i < 32; i += 8)
        dst[(size_t)(y + i) * E_DIM + x] = t[threadIdx.x][threadIdx.y + i];
}

// ---------------- batched QKV projection (+ hidden P2 = W0@W1) --------------
__global__ void __launch_bounds__(256, 2) gemm_qkv_all(
    const float* __restrict__ in_b)
{
    extern __shared__ __half smem[];
    const int by = blockIdx.y;

    if (by >= 30) {   // P2 = W0 @ W1T^T
        int li = (by - 30) * gridDim.x + blockIdx.x;
        if (li >= 64) return;
        gemm_core(g_upwh, E_DIM, g_W1T + (size_t)(li % 8) * BN * E_DIM, g_zb,
                  g_P2h, nullptr,
                  E_DIM, E_DIM, (li / 8) * BM, (li % 8) * BN,
                  smem, smem + 2 * BM * SSTH);
        return;
    }

    int lvl = 0;
#pragma unroll
    for (int i = 0; i < 3; i++) if (by >= d_rbCum[i + 1]) lvl = i + 1;
    const int bm = (by - d_rbCum[lvl]) * BM;
    const int bn = blockIdx.x * BN;
    const int stride = 1 << lvl;

    gemm_core(g_qrh, stride * E_DIM,
              g_inwh + (size_t)lvl * 3 * E_DIM * E_DIM + (size_t)bn * E_DIM,
              in_b + (size_t)lvl * 3 * E_DIM,
              g_qkvh + (size_t)d_qoff[lvl] * 3 * E_DIM, nullptr,
              3 * E_DIM, E_DIM, bm, bn,
              smem, smem + 2 * BM * SSTH);
}

// ---------------- batched out projection (+ hidden P3 = P2@W2) --------------
__global__ void __launch_bounds__(256, 2) gemm_out_all(
    const float* __restrict__ out_b)
{
    extern __shared__ __half smem[];
    const int by = blockIdx.y;

    if (by >= 30) {   // P3 = P2 @ W2T^T   (gridDim.x == 8)
        int li = (by - 30) * 8 + blockIdx.x;
        gemm_core(g_P2h, E_DIM, g_W2T + (size_t)(li % 8) * BN * E_DIM, g_zb,
                  g_P3h, nullptr,
                  E_DIM, E_DIM, (li / 8) * BM, (li % 8) * BN,
                  smem, smem + 2 * BM * SSTH);
        return;
    }

    int lvl = 0;
#pragma unroll
    for (int i = 0; i < 3; i++) if (by >= d_rbCum[i + 1]) lvl = i + 1;
    const int bm = (by - d_rbCum[lvl]) * BM;
    const int bn = blockIdx.x * BN;

    gemm_core(g_attnh + (size_t)d_qoff[lvl] * E_DIM, E_DIM,
              g_outwh + (size_t)lvl * E_DIM * E_DIM + (size_t)bn * E_DIM,
              out_b + (size_t)lvl * E_DIM,
              g_outsh + (size_t)d_qoff[lvl] * E_DIM,
              g_outsf + (size_t)d_qoff[lvl] * E_DIM,
              E_DIM, E_DIM, bm, bn,
              smem, smem + 2 * BM * SSTH);
}

// ---------------- one-launch combine projections + bias row -----------------
__global__ void __launch_bounds__(256, 2) combine_proj(
    const float* __restrict__ up_b)
{
    extern __shared__ __half smem[];
    const int li = blockIdx.x;

    if (li < 16) {
        gemm_core(g_outsh + (size_t)d_qoff[3] * E_DIM, E_DIM,
                  g_P3h + (size_t)(li % 8) * BN * E_DIM, g_zb,
                  nullptr, g_Q3,
                  E_DIM, E_DIM, (li / 8) * BM, (li % 8) * BN,
                  smem, smem + 2 * BM * SSTH);
    } else if (li < 48) {
        int t = li - 16;
        gemm_core(g_outsh + (size_t)d_qoff[2] * E_DIM, E_DIM,
                  g_P2h + (size_t)(t % 8) * BN * E_DIM, g_zb,
                  nullptr, g_Q2,
                  E_DIM, E_DIM, (t / 8) * BM, (t % 8) * BN,
                  smem, smem + 2 * BM * SSTH);
    } else if (li < 112) {
        int t = li - 48;
        gemm_core(g_outsh + (size_t)d_qoff[1] * E_DIM, E_DIM,
                  g_upwh + (size_t)(t % 8) * BN * E_DIM, g_zb,
                  nullptr, g_Q1,
                  E_DIM, E_DIM, (t / 8) * BM, (t % 8) * BN,
                  smem, smem + 2 * BM * SSTH);
    } else {
        const float* b0 = up_b;
        const float* b1 = up_b + E_DIM;
        const float* b2 = up_b + 2 * E_DIM;
        int bi = li - 112;
        int warp = threadIdx.x >> 5, lane = threadIdx.x & 31;
        for (int cc = 0; cc < 32; cc++) {
            int c = bi * 256 + warp * 32 + cc;
            float s = 0.f;
            for (int k = lane; k < E_DIM; k += 32)
                s += b2[k] * __half2float(g_P2h[(size_t)c * E_DIM + k])
                   + b1[k] * __half2float(g_upwh[(size_t)c * E_DIM + k]);
#pragma unroll
            for (int off = 16; off; off >>= 1)
                s += __shfl_xor_sync(0xffffffffu, s, off);
            if (lane == 0) g_rrow[c] = s + b0[c];
        }
    }
}

// ---------------- final: out = up3(Q3) + up2(Q2) + up(Q1) + rrow + o0 -------
__device__ __forceinline__ void taps(float pos, int L, int& i0, int& i1, float& w)
{
    pos = fminf(fmaxf(pos, 0.f), (float)(L - 1));
    i0 = (int)floorf(pos);
    i1 = min(i0 + 1, L - 1);
    w = pos - (float)i0;
}

__global__ void __launch_bounds__(256) final_combine(float* __restrict__ out)
{
    const int r = blockIdx.x;
    const int c = threadIdx.x * 4;

    int j0, j1; float w1;
    taps(0.5f * r - 0.25f, 1024, j0, j1, w1);
    int jj[2] = {j0, j1};
    float wj[2] = {1.f - w1, w1};

    int kk2[4]; float wk2[4];
#pragma unroll
    for (int t = 0; t < 2; t++) {
        int a, b; float w;
        taps(0.5f * jj[t] - 0.25f, 512, a, b, w);
        kk2[2 * t] = a;     wk2[2 * t] = wj[t] * (1.f - w);
        kk2[2 * t + 1] = b; wk2[2 * t + 1] = wj[t] * w;
    }

    int mm[8]; float wm[8];
#pragma unroll
    for (int t = 0; t < 4; t++) {
        int a, b; float w;
        taps(0.5f * kk2[t] - 0.25f, 256, a, b, w);
        mm[2 * t] = a;     wm[2 * t] = wk2[t] * (1.f - w);
        mm[2 * t + 1] = b; wm[2 * t + 1] = wk2[t] * w;
    }

    float4 acc = *reinterpret_cast<const float4*>(g_outsf + (size_t)r * E_DIM + c);
    float4 rr  = *reinterpret_cast<const float4*>(g_rrow + c);
    acc.x += rr.x; acc.y += rr.y; acc.z += rr.z; acc.w += rr.w;

#pragma unroll
    for (int t = 0; t < 2; t++) {
        float4 v = *reinterpret_cast<const float4*>(g_Q1 + (size_t)jj[t] * E_DIM + c);
        acc.x += wj[t] * v.x; acc.y += wj[t] * v.y;
        acc.z += wj[t] * v.z; acc.w += wj[t] * v.w;
    }
#pragma unroll
    for (int t = 0; t < 4; t++) {
        float4 v = *reinterpret_cast<const float4*>(g_Q2 + (size_t)kk2[t] * E_DIM + c);
        acc.x += wk2[t] * v.x; acc.y += wk2[t] * v.y;
        acc.z += wk2[t] * v.z; acc.w += wk2[t] * v.w;
    }
#pragma unroll
    for (int t = 0; t < 8; t++) {
        float4 v = *reinterpret_cast<const float4*>(g_Q3 + (size_t)mm[t] * E_DIM + c);
        acc.x += wm[t] * v.x; acc.y += wm[t] * v.y;
        acc.z += wm[t] * v.z; acc.w += wm[t] * v.w;
    }
    *reinterpret_cast<float4*>(out + (size_t)r * E_DIM + c) = acc;
}

// ---------------- batched fp16 flash attention -------------------------------
#define SA 72   // smem row stride in halfs
#define ATTN_SMEM (3 * 64 * SA * 2)   // Q(=P), K, Vt

__global__ void __launch_bounds__(128) attn_all()
{
    extern __shared__ __half sm[];
    __half* Qs = sm;                // [64 q rows][SA]   (reused as P)
    __half* Ks = sm + 64 * SA;      // [64 key rows][SA] (d along row)
    __half* Vt = sm + 2 * 64 * SA;  // [64 d rows][SA]   (keys along row)
    __half* Ps = Qs;

    const int bx = blockIdx.x;
    int lvl = 0;
#pragma unroll
    for (int i = 0; i < 3; i++) if (bx >= d_qbCum[i + 1]) lvl = i + 1;
    const int L = d_Llvl[lvl];
    const __half* qkv = g_qkvh + (size_t)d_qoff[lvl] * 3 * E_DIM;
    __half* outp = g_attnh + (size_t)d_qoff[lvl] * E_DIM;

    const int h = blockIdx.y;
    const int q0 = (bx - d_qbCum[lvl]) * 64;
    const int tid = threadIdx.x;
    const int wid = tid >> 5;
    const int lane = tid & 31;
    const int g = lane >> 2;
    const int q = lane & 3;

    const int lc8 = (tid & 7) * 8;  // half offset within 64-half row
    const int lrw = tid >> 3;       // 0..15, 4 passes of 16 rows

    // load Q (scaled by 1/8, exact in fp16)
    const __half2 sc2 = __floats2half2_rn(0.125f, 0.125f);
#pragma unroll
    for (int it = 0; it < 4; it++) {
        int r = lrw + it * 16;
        const __half2* src = reinterpret_cast<const __half2*>(
            qkv + (size_t)(q0 + r) * 3072 + h * 64 + lc8);
        __half2* dst = reinterpret_cast<__half2*>(Qs + r * SA + lc8);
#pragma unroll
        for (int j = 0; j < 4; j++) dst[j] = __hmul2(src[j], sc2);
    }
    __syncthreads();

    // preload Q fragments (4 ksteps of 16)
    uint32_t qa[4][4];
    const int arow = wid * 16 + g;
#pragma unroll
    for (int ks = 0; ks < 4; ks++) {
        const __half* p = Qs + arow * SA + ks * 16 + 2 * q;
        qa[ks][0] = *reinterpret_cast<const uint32_t*>(p);
        qa[ks][1] = *reinterpret_cast<const uint32_t*>(p + 8 * SA);
        qa[ks][2] = *reinterpret_cast<const uint32_t*>(p + 8);
        qa[ks][3] = *reinterpret_cast<const uint32_t*>(p + 8 * SA + 8);
    }

    float m_i[2] = {-1e30f, -1e30f};
    float l_i[2] = {0.f, 0.f};
    float O[8][4];
#pragma unroll
    for (int ni = 0; ni < 8; ni++)
#pragma unroll
        for (int j = 0; j < 4; j++) O[ni][j] = 0.f;

    for (int kb = 0; kb < L; kb += 64) {
        __syncthreads();   // prior block's K/Vt reads complete
#pragma unroll
        for (int it = 0; it < 4; it++) {
            int r = lrw + it * 16;
            const __half* base = qkv + (size_t)(kb + r) * 3072 + h * 64 + lc8;
            // K natural [c][d]
            *reinterpret_cast<uint4*>(Ks + r * SA + lc8) =
                *reinterpret_cast<const uint4*>(base + 1024);
            // V transposed [d][c]
            const __half* vsrc = base + 2048;
#pragma unroll
            for (int j = 0; j < 8; j++)
                Vt[(lc8 + j) * SA + r] = vsrc[j];
        }
        __syncthreads();

        // S = Q @ K^T   (fp32 accum)
        float s[8][4];
#pragma unroll
        for (int ni = 0; ni < 8; ni++)
#pragma unroll
            for (int j = 0; j < 4; j++) s[ni][j] = 0.f;
#pragma unroll
        for (int ks = 0; ks < 4; ks++) {
            const int kc = ks * 16 + 2 * q;
#pragma unroll
            for (int ni = 0; ni < 8; ni++) {
                const __half* p = Ks + (ni * 8 + g) * SA + kc;
                mma_f16(s[ni], qa[ks],
                        *reinterpret_cast<const uint32_t*>(p),
                        *reinterpret_cast<const uint32_t*>(p + 8));
            }
        }

        // online softmax (rows arow, arow+8; reduce across q lanes)
        float rmax0 = -1e30f, rmax1 = -1e30f;
#pragma unroll
        for (int ni = 0; ni < 8; ni++) {
            rmax0 = fmaxf(rmax0, fmaxf(s[ni][0], s[ni][1]));
            rmax1 = fmaxf(rmax1, fmaxf(s[ni][2], s[ni][3]));
        }
#pragma unroll
        for (int off = 1; off <= 2; off <<= 1) {
            rmax0 = fmaxf(rmax0, __shfl_xor_sync(0xffffffffu, rmax0, off));
            rmax1 = fmaxf(rmax1, __shfl_xor_sync(0xffffffffu, rmax1, off));
        }
        float mnew0 = fmaxf(m_i[0], rmax0);
        float mnew1 = fmaxf(m_i[1], rmax1);
        float al0 = __expf(m_i[0] - mnew0);
        float al1 = __expf(m_i[1] - mnew1);
        float sum0 = 0.f, sum1 = 0.f;
#pragma unroll
        for (int ni = 0; ni < 8; ni++) {
            s[ni][0] = __expf(s[ni][0] - mnew0);
            s[ni][1] = __expf(s[ni][1] - mnew0);
            s[ni][2] = __expf(s[ni][2] - mnew1);
            s[ni][3] = __expf(s[ni][3] - mnew1);
            sum0 += s[ni][0] + s[ni][1];
            sum1 += s[ni][2] + s[ni][3];
        }
#pragma unroll
        for (int off = 1; off <= 2; off <<= 1) {
            sum0 += __shfl_xor_sync(0xffffffffu, sum0, off);
            sum1 += __shfl_xor_sync(0xffffffffu, sum1, off);
        }
        l_i[0] = l_i[0] * al0 + sum0;
        l_i[1] = l_i[1] * al1 + sum1;
        m_i[0] = mnew0;
        m_i[1] = mnew1;
#pragma unroll
        for (int ni = 0; ni < 8; ni++) {
            O[ni][0] *= al0; O[ni][1] *= al0;
            O[ni][2] *= al1; O[ni][3] *= al1;
        }

        // write P (half) into warp-local rows of reused Q region
        __syncwarp();
#pragma unroll
        for (int ni = 0; ni < 8; ni++) {
            const int col = ni * 8 + 2 * q;
            *reinterpret_cast<__half2*>(Ps + arow * SA + col) =
                __floats2half2_rn(s[ni][0], s[ni][1]);
            *reinterpret_cast<__half2*>(Ps + (arow + 8) * SA + col) =
                __floats2half2_rn(s[ni][2], s[ni][3]);
        }
        __syncwarp();

        // O += P @ V   (A = P rows, B = Vt rows)
#pragma unroll
        for (int ks = 0; ks < 4; ks++) {
            const int kc = ks * 16 + 2 * q;
            uint32_t pa[4];
            const __half* pp = Ps + arow * SA + kc;
            pa[0] = *reinterpret_cast<const uint32_t*>(pp);
            pa[1] = *reinterpret_cast<const uint32_t*>(pp + 8 * SA);
            pa[2] = *reinterpret_cast<const uint32_t*>(pp + 8);
            pa[3] = *reinterpret_cast<const uint32_t*>(pp + 8 * SA + 8);
#pragma unroll
            for (int ni = 0; ni < 8; ni++) {
                const __half* vp = Vt + (ni * 8 + g) * SA + kc;
                mma_f16(O[ni], pa,
                        *reinterpret_cast<const uint32_t*>(vp),
                        *reinterpret_cast<const uint32_t*>(vp + 8));
            }
        }
    }

    // normalize + write fp16 (g_attnh feeds out-proj)
    const float inv0 = 1.0f / l_i[0];
    const float inv1 = 1.0f / l_i[1];
    const size_t row0 = (size_t)(q0 + arow);
#pragma unroll
    for (int ni = 0; ni < 8; ni++) {
        const int col = h * 64 + ni * 8 + 2 * q;
        *reinterpret_cast<__half2*>(outp + row0 * E_DIM + col) =
            __floats2half2_rn(O[ni][0] * inv0, O[ni][1] * inv0);
        *reinterpret_cast<__half2*>(outp + (row0 + 8) * E_DIM + col) =
            __floats2half2_rn(O[ni][2] * inv1, O[ni][3] * inv1);
    }
}

// ---------------- launcher --------------------------------------------------
extern "C" void kernel_launch(void* const* d_in, const int* in_sizes, int n_in,
                              void* d_out, int out_size)
{
    const float* query = (const float*)d_in[0];
    const float* in_w  = (const float*)d_in[1];
    const float* in_b  = (const float*)d_in[2];
    const float* out_w = (const float*)d_in[3];
    const float* out_b = (const float*)d_in[4];
    const float* up_w  = (const float*)d_in[5];
    const float* up_b  = (const float*)d_in[6];
    float* out = (float*)d_out;

    cudaFuncSetAttribute(gemm_qkv_all, cudaFuncAttributeMaxDynamicSharedMemorySize, GEMM_SMEM);
    cudaFuncSetAttribute(gemm_out_all, cudaFuncAttributeMaxDynamicSharedMemorySize, GEMM_SMEM);
    cudaFuncSetAttribute(combine_proj, cudaFuncAttributeMaxDynamicSharedMemorySize, GEMM_SMEM);
    cudaFuncSetAttribute(attn_all,     cudaFuncAttributeMaxDynamicSharedMemorySize, ATTN_SMEM);

    __half *qrh, *inwh, *outwh, *upwh;
    cudaGetSymbolAddress((void**)&qrh,   g_qrh);
    cudaGetSymbolAddress((void**)&inwh,  g_inwh);
    cudaGetSymbolAddress((void**)&outwh, g_outwh);
    cudaGetSymbolAddress((void**)&upwh,  g_upwh);

    // 0. fp32 -> fp16 copies (same mantissa count as tf32; halves all matmul cost)
    {
        int n4;
        n4 = S_MAX * E_DIM / 4;
        round_h<<<(n4 + 255) / 256, 256>>>((const float4*)query, qrh, n4);
        n4 = LEVELS * 3 * E_DIM * E_DIM / 4;
        round_h<<<(n4 + 255) / 256, 256>>>((const float4*)in_w, inwh, n4);
        n4 = LEVELS * E_DIM * E_DIM / 4;
        round_h<<<(n4 + 255) / 256, 256>>>((const float4*)out_w, outwh, n4);
        n4 = (LEVELS - 1) * E_DIM * E_DIM / 4;
        round_h<<<(n4 + 255) / 256, 256>>>((const float4*)up_w, upwh, n4);
    }

    // 1. W1^T, W2^T
    transpose_w<<<dim3(32, 32, 2), dim3(32, 8)>>>();
    // 2. QKV all levels (+ P2 = W0@W1 hidden in grid)
    gemm_qkv_all<<<dim3(24, 33), 256, GEMM_SMEM>>>(in_b);
    // 3. attention all levels
    attn_all<<<dim3(60, 16), 128, ATTN_SMEM>>>();
    // 4. out-proj all levels (+ P3 = P2@W2 hidden in grid)
    gemm_out_all<<<dim3(8, 38), 256, GEMM_SMEM>>>(out_b);
    // 5. all combine projections + bias row, one launch
    combine_proj<<<116, 256, GEMM_SMEM>>>(up_b);
    // 6. final tap-composed upsample + residual sum
    final_combine<<<2048, 256>>>(out);
}

// round 15
// speedup vs baseline: 1.5257x; 1.1687x over previous
#include <cuda_runtime.h>
#include <cuda_fp16.h>
#include <cstdint>

#define E_DIM 1024
#define S_MAX 2048
#define LEVELS 4
#define R_TOT 3840   // 2048+1024+512+256

// ---------------- scratch ---------------------------------------------------
__device__ __half g_qkvh[R_TOT * 3 * E_DIM];
__device__ __half g_attnh[R_TOT * E_DIM];
__device__ __half g_outsh[R_TOT * E_DIM];
__device__ float  g_outsf[R_TOT * E_DIM];
__device__ __half g_W1T[E_DIM * E_DIM];
__device__ __half g_W2T[E_DIM * E_DIM];
__device__ __half g_P2h[E_DIM * E_DIM];   // W0 @ W1
__device__ __half g_P3h[E_DIM * E_DIM];   // P2 @ W2
__device__ float  g_Q1[1024 * E_DIM];
__device__ float  g_Q2[512 * E_DIM];
__device__ float  g_Q3[256 * E_DIM];
__device__ float  g_rrow[E_DIM];
__device__ float  g_zb[E_DIM];
// fp16 copies of inputs
__device__ __half g_qrh[S_MAX * E_DIM];
__device__ __half g_inwh[LEVELS * 3 * E_DIM * E_DIM];
__device__ __half g_outwh[LEVELS * E_DIM * E_DIM];
__device__ __half g_upwh[(LEVELS - 1) * E_DIM * E_DIM];

// ---------------- helpers ---------------------------------------------------
__device__ __forceinline__ void mma_f16(float* c, const uint32_t* a,
                                        uint32_t b0, uint32_t b1) {
    asm volatile(
        "mma.sync.aligned.m16n8k16.row.col.f32.f16.f16.f32 "
        "{%0,%1,%2,%3}, {%4,%5,%6,%7}, {%8,%9}, {%0,%1,%2,%3};"
        : "+f"(c[0]), "+f"(c[1]), "+f"(c[2]), "+f"(c[3])
        : "r"(a[0]), "r"(a[1]), "r"(a[2]), "r"(a[3]), "r"(b0), "r"(b1));
}

__device__ __forceinline__ void cp_async16(uint32_t smem_addr, const void* gptr) {
    asm volatile("cp.async.cg.shared.global [%0], [%1], 16;\n"
                 :: "r"(smem_addr), "l"(gptr));
}
__device__ __forceinline__ void cp_commit() {
    asm volatile("cp.async.commit_group;\n" ::: "memory");
}
__device__ __forceinline__ void cp_wait0() {
    asm volatile("cp.async.wait_group 0;\n" ::: "memory");
}

// ---------------- fp32 -> fp16 prep kernel ----------------------------------
__global__ void __launch_bounds__(256) round_h(
    const float4* __restrict__ src, __half* __restrict__ dst, int n4)
{
    int i = blockIdx.x * blockDim.x + threadIdx.x;
    if (i < n4) {
        float4 v = src[i];
        __half2* d = reinterpret_cast<__half2*>(dst + (size_t)i * 4);
        d[0] = __floats2half2_rn(v.x, v.y);
        d[1] = __floats2half2_rn(v.z, v.w);
    }
}

// ---------------- fp16 GEMM core (BK=64) -------------------------------------
#define BM 128
#define BN 128
#define BK 64
#define SSTH 72
#define GEMM_SMEM (2 * 2 * BM * SSTH * 2)   // 73728 B

__device__ __forceinline__ void gemm_core(
    const __half* __restrict__ X, int ldx,
    const __half* __restrict__ Wp,          // W + bn*K
    const float* __restrict__ bias,
    __half* __restrict__ Yh,                // nullable
    float* __restrict__ Yf,                 // nullable
    int N, int K, int bm, int bn,
    __half* As, __half* Bs)
{
    const int tid = threadIdx.x;
    const int lane = tid & 31;
    const int wid = tid >> 5;
    const int warp_row = (wid & 1) * 64;
    const int warp_col = (wid >> 1) * 32;

    const int lr = tid >> 3;        // 0..31 row base (4 its of 32 rows)
    const int kb = (tid & 7) * 8;   // half offset within 64-half row

    const uint32_t aBase = (uint32_t)__cvta_generic_to_shared(As);
    const uint32_t bBase = (uint32_t)__cvta_generic_to_shared(Bs);
    const __half* Xp = X + (size_t)bm * ldx;

    float acc[4][4][4];
#pragma unroll
    for (int mi = 0; mi < 4; mi++)
#pragma unroll
        for (int ni = 0; ni < 4; ni++)
#pragma unroll
            for (int j = 0; j < 4; j++) acc[mi][ni][j] = 0.f;

#define G_PREFETCH(k0, sg)                                                     \
    {                                                                          \
        _Pragma("unroll") for (int it = 0; it < 4; it++) {                     \
            int r = lr + it * 32;                                              \
            cp_async16(aBase + ((sg)*BM*SSTH + r*SSTH + kb) * 2,               \
                       Xp + (size_t)r * ldx + (k0) + kb);                      \
            cp_async16(bBase + ((sg)*BN*SSTH + r*SSTH + kb) * 2,               \
                       Wp + (size_t)r * K + (k0) + kb);                        \
        }                                                                      \
        cp_commit();                                                           \
    }

    G_PREFETCH(0, 0);

    const int g = lane >> 2;
    const int q = lane & 3;

    for (int k0 = 0; k0 < K; k0 += BK) {
        const int s = (k0 / BK) & 1;
        const bool more = (k0 + BK) < K;

        cp_wait0();
        __syncthreads();
        if (more) G_PREFETCH(k0 + BK, s ^ 1);

        const __half* Ab = As + s * BM * SSTH;
        const __half* Bb = Bs + s * BN * SSTH;
#pragma unroll
        for (int ks = 0; ks < 4; ks++) {
            const int kc = ks * 16 + 2 * q;
            uint32_t af[4][4], bf[4][2];
#pragma unroll
            for (int mi = 0; mi < 4; mi++) {
                const __half* p = Ab + (warp_row + mi * 16 + g) * SSTH + kc;
                af[mi][0] = *reinterpret_cast<const uint32_t*>(p);
                af[mi][1] = *reinterpret_cast<const uint32_t*>(p + 8 * SSTH);
                af[mi][2] = *reinterpret_cast<const uint32_t*>(p + 8);
                af[mi][3] = *reinterpret_cast<const uint32_t*>(p + 8 * SSTH + 8);
            }
#pragma unroll
            for (int ni = 0; ni < 4; ni++) {
                const __half* p = Bb + (warp_col + ni * 8 + g) * SSTH + kc;
                bf[ni][0] = *reinterpret_cast<const uint32_t*>(p);
                bf[ni][1] = *reinterpret_cast<const uint32_t*>(p + 8);
            }
#pragma unroll
            for (int mi = 0; mi < 4; mi++)
#pragma unroll
                for (int ni = 0; ni < 4; ni++)
                    mma_f16(acc[mi][ni], af[mi], bf[ni][0], bf[ni][1]);
        }
        __syncthreads();
    }

#pragma unroll
    for (int mi = 0; mi < 4; mi++) {
        const int row0 = bm + warp_row + mi * 16 + g;
#pragma unroll
        for (int ni = 0; ni < 4; ni++) {
            const int col = bn + warp_col + ni * 8 + 2 * q;
            float2 bb = *reinterpret_cast<const float2*>(bias + col);
            float v0 = acc[mi][ni][0] + bb.x;
            float v1 = acc[mi][ni][1] + bb.y;
            float v2 = acc[mi][ni][2] + bb.x;
            float v3 = acc[mi][ni][3] + bb.y;
            if (Yh) {
                *reinterpret_cast<__half2*>(Yh + (size_t)row0 * N + col) =
                    __floats2half2_rn(v0, v1);
                *reinterpret_cast<__half2*>(Yh + (size_t)(row0 + 8) * N + col) =
                    __floats2half2_rn(v2, v3);
            }
            if (Yf) {
                *reinterpret_cast<float2*>(Yf + (size_t)row0 * N + col) =
                    make_float2(v0, v1);
                *reinterpret_cast<float2*>(Yf + (size_t)(row0 + 8) * N + col) =
                    make_float2(v2, v3);
            }
        }
    }
#undef G_PREFETCH
}

// level tables
__device__ __constant__ int d_qoff[4] = {0, 2048, 3072, 3584};
__device__ __constant__ int d_rbCum[5] = {0, 16, 24, 28, 30};   // /128 blocks
__device__ __constant__ int d_Llvl[4] = {2048, 1024, 512, 256};

// ---------------- weight transpose (W1, W2; half) ---------------------------
__global__ void __launch_bounds__(256) transpose_w()
{
    __shared__ __half t[32][33];
    const __half* src = g_upwh + (size_t)(blockIdx.z + 1) * E_DIM * E_DIM;
    __half* dst = blockIdx.z == 0 ? g_W1T : g_W2T;
    int x = blockIdx.x * 32 + threadIdx.x;
    int y = blockIdx.y * 32 + threadIdx.y;
#pragma unroll
    for (int i = 0; i < 32; i += 8)
        t[threadIdx.y + i][threadIdx.x] = src[(size_t)(y + i) * E_DIM + x];
    __syncthreads();
    x = blockIdx.y * 32 + threadIdx.x;
    y = blockIdx.x * 32 + threadIdx.y;
#pragma unroll
    for (int i = 0; i < 32; i += 8)
        dst[(size_t)(y + i) * E_DIM + x] = t[threadIdx.x][threadIdx.y + i];
}

// ---------------- batched QKV projection (+ hidden P2 = W0@W1) --------------
__global__ void __launch_bounds__(256, 2) gemm_qkv_all(
    const float* __restrict__ in_b)
{
    extern __shared__ __half smem[];
    const int by = blockIdx.y;

    if (by >= 30) {   // P2 = W0 @ W1T^T
        int li = (by - 30) * gridDim.x + blockIdx.x;
        if (li >= 64) return;
        gemm_core(g_upwh, E_DIM, g_W1T + (size_t)(li % 8) * BN * E_DIM, g_zb,
                  g_P2h, nullptr,
                  E_DIM, E_DIM, (li / 8) * BM, (li % 8) * BN,
                  smem, smem + 2 * BM * SSTH);
        return;
    }

    int lvl = 0;
#pragma unroll
    for (int i = 0; i < 3; i++) if (by >= d_rbCum[i + 1]) lvl = i + 1;
    const int bm = (by - d_rbCum[lvl]) * BM;
    const int bn = blockIdx.x * BN;
    const int stride = 1 << lvl;

    gemm_core(g_qrh, stride * E_DIM,
              g_inwh + (size_t)lvl * 3 * E_DIM * E_DIM + (size_t)bn * E_DIM,
              in_b + (size_t)lvl * 3 * E_DIM,
              g_qkvh + (size_t)d_qoff[lvl] * 3 * E_DIM, nullptr,
              3 * E_DIM, E_DIM, bm, bn,
              smem, smem + 2 * BM * SSTH);
}

// ---------------- batched out projection (+ hidden P3 = P2@W2) --------------
__global__ void __launch_bounds__(256, 2) gemm_out_all(
    const float* __restrict__ out_b)
{
    extern __shared__ __half smem[];
    const int by = blockIdx.y;

    if (by >= 30) {   // P3 = P2 @ W2T^T   (gridDim.x == 8)
        int li = (by - 30) * 8 + blockIdx.x;
        gemm_core(g_P2h, E_DIM, g_W2T + (size_t)(li % 8) * BN * E_DIM, g_zb,
                  g_P3h, nullptr,
                  E_DIM, E_DIM, (li / 8) * BM, (li % 8) * BN,
                  smem, smem + 2 * BM * SSTH);
        return;
    }

    int lvl = 0;
#pragma unroll
    for (int i = 0; i < 3; i++) if (by >= d_rbCum[i + 1]) lvl = i + 1;
    const int bm = (by - d_rbCum[lvl]) * BM;
    const int bn = blockIdx.x * BN;

    gemm_core(g_attnh + (size_t)d_qoff[lvl] * E_DIM, E_DIM,
              g_outwh + (size_t)lvl * E_DIM * E_DIM + (size_t)bn * E_DIM,
              out_b + (size_t)lvl * E_DIM,
              g_outsh + (size_t)d_qoff[lvl] * E_DIM,
              g_outsf + (size_t)d_qoff[lvl] * E_DIM,
              E_DIM, E_DIM, bm, bn,
              smem, smem + 2 * BM * SSTH);
}

// ---------------- one-launch combine projections + bias row -----------------
__global__ void __launch_bounds__(256, 2) combine_proj(
    const float* __restrict__ up_b)
{
    extern __shared__ __half smem[];
    const int li = blockIdx.x;

    if (li < 16) {
        gemm_core(g_outsh + (size_t)d_qoff[3] * E_DIM, E_DIM,
                  g_P3h + (size_t)(li % 8) * BN * E_DIM, g_zb,
                  nullptr, g_Q3,
                  E_DIM, E_DIM, (li / 8) * BM, (li % 8) * BN,
                  smem, smem + 2 * BM * SSTH);
    } else if (li < 48) {
        int t = li - 16;
        gemm_core(g_outsh + (size_t)d_qoff[2] * E_DIM, E_DIM,
                  g_P2h + (size_t)(t % 8) * BN * E_DIM, g_zb,
                  nullptr, g_Q2,
                  E_DIM, E_DIM, (t / 8) * BM, (t % 8) * BN,
                  smem, smem + 2 * BM * SSTH);
    } else if (li < 112) {
        int t = li - 48;
        gemm_core(g_outsh + (size_t)d_qoff[1] * E_DIM, E_DIM,
                  g_upwh + (size_t)(t % 8) * BN * E_DIM, g_zb,
                  nullptr, g_Q1,
                  E_DIM, E_DIM, (t / 8) * BM, (t % 8) * BN,
                  smem, smem + 2 * BM * SSTH);
    } else {
        const float* b0 = up_b;
        const float* b1 = up_b + E_DIM;
        const float* b2 = up_b + 2 * E_DIM;
        int bi = li - 112;
        int warp = threadIdx.x >> 5, lane = threadIdx.x & 31;
        for (int cc = 0; cc < 32; cc++) {
            int c = bi * 256 + warp * 32 + cc;
            float s = 0.f;
            for (int k = lane; k < E_DIM; k += 32)
                s += b2[k] * __half2float(g_P2h[(size_t)c * E_DIM + k])
                   + b1[k] * __half2float(g_upwh[(size_t)c * E_DIM + k]);
#pragma unroll
            for (int off = 16; off; off >>= 1)
                s += __shfl_xor_sync(0xffffffffu, s, off);
            if (lane == 0) g_rrow[c] = s + b0[c];
        }
    }
}

// ---------------- final: out = up3(Q3) + up2(Q2) + up(Q1) + rrow + o0 -------
__device__ __forceinline__ void taps(float pos, int L, int& i0, int& i1, float& w)
{
    pos = fminf(fmaxf(pos, 0.f), (float)(L - 1));
    i0 = (int)floorf(pos);
    i1 = min(i0 + 1, L - 1);
    w = pos - (float)i0;
}

__global__ void __launch_bounds__(256) final_combine(float* __restrict__ out)
{
    const int r = blockIdx.x;
    const int c = threadIdx.x * 4;

    int j0, j1; float w1;
    taps(0.5f * r - 0.25f, 1024, j0, j1, w1);
    int jj[2] = {j0, j1};
    float wj[2] = {1.f - w1, w1};

    int kk2[4]; float wk2[4];
#pragma unroll
    for (int t = 0; t < 2; t++) {
        int a, b; float w;
        taps(0.5f * jj[t] - 0.25f, 512, a, b, w);
        kk2[2 * t] = a;     wk2[2 * t] = wj[t] * (1.f - w);
        kk2[2 * t + 1] = b; wk2[2 * t + 1] = wj[t] * w;
    }

    int mm[8]; float wm[8];
#pragma unroll
    for (int t = 0; t < 4; t++) {
        int a, b; float w;
        taps(0.5f * kk2[t] - 0.25f, 256, a, b, w);
        mm[2 * t] = a;     wm[2 * t] = wk2[t] * (1.f - w);
        mm[2 * t + 1] = b; wm[2 * t + 1] = wk2[t] * w;
    }

    float4 acc = *reinterpret_cast<const float4*>(g_outsf + (size_t)r * E_DIM + c);
    float4 rr  = *reinterpret_cast<const float4*>(g_rrow + c);
    acc.x += rr.x; acc.y += rr.y; acc.z += rr.z; acc.w += rr.w;

#pragma unroll
    for (int t = 0; t < 2; t++) {
        float4 v = *reinterpret_cast<const float4*>(g_Q1 + (size_t)jj[t] * E_DIM + c);
        acc.x += wj[t] * v.x; acc.y += wj[t] * v.y;
        acc.z += wj[t] * v.z; acc.w += wj[t] * v.w;
    }
#pragma unroll
    for (int t = 0; t < 4; t++) {
        float4 v = *reinterpret_cast<const float4*>(g_Q2 + (size_t)kk2[t] * E_DIM + c);
        acc.x += wk2[t] * v.x; acc.y += wk2[t] * v.y;
        acc.z += wk2[t] * v.z; acc.w += wk2[t] * v.w;
    }
#pragma unroll
    for (int t = 0; t < 8; t++) {
        float4 v = *reinterpret_cast<const float4*>(g_Q3 + (size_t)mm[t] * E_DIM + c);
        acc.x += wm[t] * v.x; acc.y += wm[t] * v.y;
        acc.z += wm[t] * v.z; acc.w += wm[t] * v.w;
    }
    *reinterpret_cast<float4*>(out + (size_t)r * E_DIM + c) = acc;
}

// ---------------- batched fp16 flash attention (128 queries / 8 warps) ------
#define SA 72   // smem row stride in halfs
#define ATTN_SMEM ((128 + 64 + 64) * SA * 2)   // Q(=P) 128 rows, K 64, Vt 64

__global__ void __launch_bounds__(256) attn_all()
{
    extern __shared__ __half sm[];
    __half* Qs = sm;                 // [128 q rows][SA]  (reused as P)
    __half* Ks = sm + 128 * SA;      // [64 key rows][SA]
    __half* Vt = sm + 192 * SA;      // [64 d rows][SA]
    __half* Ps = Qs;

    const int bx = blockIdx.x;
    int lvl = 0;
#pragma unroll
    for (int i = 0; i < 3; i++) if (bx >= d_rbCum[i + 1]) lvl = i + 1;
    const int L = d_Llvl[lvl];
    const __half* qkv = g_qkvh + (size_t)d_qoff[lvl] * 3 * E_DIM;
    __half* outp = g_attnh + (size_t)d_qoff[lvl] * E_DIM;

    const int h = blockIdx.y;
    const int q0 = (bx - d_rbCum[lvl]) * 128;
    const int tid = threadIdx.x;
    const int wid = tid >> 5;
    const int lane = tid & 31;
    const int g = lane >> 2;
    const int q = lane & 3;

    const int lc8 = (tid & 7) * 8;  // half offset within 64-half row
    const int lrw = tid >> 3;       // 0..31

    // load Q tile (128 rows; scaled by 1/8, exact in fp16)
    const __half2 sc2 = __floats2half2_rn(0.125f, 0.125f);
#pragma unroll
    for (int it = 0; it < 4; it++) {
        int r = lrw + it * 32;
        const __half2* src = reinterpret_cast<const __half2*>(
            qkv + (size_t)(q0 + r) * 3072 + h * 64 + lc8);
        __half2* dst = reinterpret_cast<__half2*>(Qs + r * SA + lc8);
#pragma unroll
        for (int j = 0; j < 4; j++) dst[j] = __hmul2(src[j], sc2);
    }
    __syncthreads();

    // preload Q fragments (4 ksteps of 16); warp w owns rows wid*16..wid*16+15
    uint32_t qa[4][4];
    const int arow = wid * 16 + g;
#pragma unroll
    for (int ks = 0; ks < 4; ks++) {
        const __half* p = Qs + arow * SA + ks * 16 + 2 * q;
        qa[ks][0] = *reinterpret_cast<const uint32_t*>(p);
        qa[ks][1] = *reinterpret_cast<const uint32_t*>(p + 8 * SA);
        qa[ks][2] = *reinterpret_cast<const uint32_t*>(p + 8);
        qa[ks][3] = *reinterpret_cast<const uint32_t*>(p + 8 * SA + 8);
    }

    float m_i[2] = {-1e30f, -1e30f};
    float l_i[2] = {0.f, 0.f};
    float O[8][4];
#pragma unroll
    for (int ni = 0; ni < 8; ni++)
#pragma unroll
        for (int j = 0; j < 4; j++) O[ni][j] = 0.f;

    for (int kb = 0; kb < L; kb += 64) {
        __syncthreads();   // prior block's K/Vt reads complete
#pragma unroll
        for (int it = 0; it < 2; it++) {
            int r = lrw + it * 32;
            const __half* base = qkv + (size_t)(kb + r) * 3072 + h * 64 + lc8;
            *reinterpret_cast<uint4*>(Ks + r * SA + lc8) =
                *reinterpret_cast<const uint4*>(base + 1024);
            const __half* vsrc = base + 2048;
#pragma unroll
            for (int j = 0; j < 8; j++)
                Vt[(lc8 + j) * SA + r] = vsrc[j];
        }
        __syncthreads();

        // S = Q @ K^T
        float s[8][4];
#pragma unroll
        for (int ni = 0; ni < 8; ni++)
#pragma unroll
            for (int j = 0; j < 4; j++) s[ni][j] = 0.f;
#pragma unroll
        for (int ks = 0; ks < 4; ks++) {
            const int kc = ks * 16 + 2 * q;
#pragma unroll
            for (int ni = 0; ni < 8; ni++) {
                const __half* p = Ks + (ni * 8 + g) * SA + kc;
                mma_f16(s[ni], qa[ks],
                        *reinterpret_cast<const uint32_t*>(p),
                        *reinterpret_cast<const uint32_t*>(p + 8));
            }
        }

        // online softmax
        float rmax0 = -1e30f, rmax1 = -1e30f;
#pragma unroll
        for (int ni = 0; ni < 8; ni++) {
            rmax0 = fmaxf(rmax0, fmaxf(s[ni][0], s[ni][1]));
            rmax1 = fmaxf(rmax1, fmaxf(s[ni][2], s[ni][3]));
        }
#pragma unroll
        for (int off = 1; off <= 2; off <<= 1) {
            rmax0 = fmaxf(rmax0, __shfl_xor_sync(0xffffffffu, rmax0, off));
            rmax1 = fmaxf(rmax1, __shfl_xor_sync(0xffffffffu, rmax1, off));
        }
        float mnew0 = fmaxf(m_i[0], rmax0);
        float mnew1 = fmaxf(m_i[1], rmax1);
        float al0 = __expf(m_i[0] - mnew0);
        float al1 = __expf(m_i[1] - mnew1);
        float sum0 = 0.f, sum1 = 0.f;
#pragma unroll
        for (int ni = 0; ni < 8; ni++) {
            s[ni][0] = __expf(s[ni][0] - mnew0);
            s[ni][1] = __expf(s[ni][1] - mnew0);
            s[ni][2] = __expf(s[ni][2] - mnew1);
            s[ni][3] = __expf(s[ni][3] - mnew1);
            sum0 += s[ni][0] + s[ni][1];
            sum1 += s[ni][2] + s[ni][3];
        }
#pragma unroll
        for (int off = 1; off <= 2; off <<= 1) {
            sum0 += __shfl_xor_sync(0xffffffffu, sum0, off);
            sum1 += __shfl_xor_sync(0xffffffffu, sum1, off);
        }
        l_i[0] = l_i[0] * al0 + sum0;
        l_i[1] = l_i[1] * al1 + sum1;
        m_i[0] = mnew0;
        m_i[1] = mnew1;
#pragma unroll
        for (int ni = 0; ni < 8; ni++) {
            O[ni][0] *= al0; O[ni][1] *= al0;
            O[ni][2] *= al1; O[ni][3] *= al1;
        }

        // write P into warp-local rows of reused Q region
        __syncwarp();
#pragma unroll
        for (int ni = 0; ni < 8; ni++) {
            const int col = ni * 8 + 2 * q;
            *reinterpret_cast<__half2*>(Ps + arow * SA + col) =
                __floats2half2_rn(s[ni][0], s[ni][1]);
            *reinterpret_cast<__half2*>(Ps + (arow + 8) * SA + col) =
                __floats2half2_rn(s[ni][2], s[ni][3]);
        }
        __syncwarp();

        // O += P @ V
#pragma unroll
        for (int ks = 0; ks < 4; ks++) {
            const int kc = ks * 16 + 2 * q;
            uint32_t pa[4];
            const __half* pp = Ps + arow * SA + kc;
            pa[0] = *reinterpret_cast<const uint32_t*>(pp);
            pa[1] = *reinterpret_cast<const uint32_t*>(pp + 8 * SA);
            pa[2] = *reinterpret_cast<const uint32_t*>(pp + 8);
            pa[3] = *reinterpret_cast<const uint32_t*>(pp + 8 * SA + 8);
#pragma unroll
            for (int ni = 0; ni < 8; ni++) {
                const __half* vp = Vt + (ni * 8 + g) * SA + kc;
                mma_f16(O[ni], pa,
                        *reinterpret_cast<const uint32_t*>(vp),
                        *reinterpret_cast<const uint32_t*>(vp + 8));
            }
        }
    }

    // normalize + write fp16
    const float inv0 = 1.0f / l_i[0];
    const float inv1 = 1.0f / l_i[1];
    const size_t row0 = (size_t)(q0 + arow);
#pragma unroll
    for (int ni = 0; ni < 8; ni++) {
        const int col = h * 64 + ni * 8 + 2 * q;
        *reinterpret_cast<__half2*>(outp + row0 * E_DIM + col) =
            __floats2half2_rn(O[ni][0] * inv0, O[ni][1] * inv0);
        *reinterpret_cast<__half2*>(outp + (row0 + 8) * E_DIM + col) =
            __floats2half2_rn(O[ni][2] * inv1, O[ni][3] * inv1);
    }
}

// ---------------- launcher --------------------------------------------------
extern "C" void kernel_launch(void* const* d_in, const int* in_sizes, int n_in,
                              void* d_out, int out_size)
{
    const float* query = (const float*)d_in[0];
    const float* in_w  = (const float*)d_in[1];
    const float* in_b  = (const float*)d_in[2];
    const float* out_w = (const float*)d_in[3];
    const float* out_b = (const float*)d_in[4];
    const float* up_w  = (const float*)d_in[5];
    const float* up_b  = (const float*)d_in[6];
    float* out = (float*)d_out;

    cudaFuncSetAttribute(gemm_qkv_all, cudaFuncAttributeMaxDynamicSharedMemorySize, GEMM_SMEM);
    cudaFuncSetAttribute(gemm_out_all, cudaFuncAttributeMaxDynamicSharedMemorySize, GEMM_SMEM);
    cudaFuncSetAttribute(combine_proj, cudaFuncAttributeMaxDynamicSharedMemorySize, GEMM_SMEM);
    cudaFuncSetAttribute(attn_all,     cudaFuncAttributeMaxDynamicSharedMemorySize, ATTN_SMEM);

    __half *qrh, *inwh, *outwh, *upwh;
    cudaGetSymbolAddress((void**)&qrh,   g_qrh);
    cudaGetSymbolAddress((void**)&inwh,  g_inwh);
    cudaGetSymbolAddress((void**)&outwh, g_outwh);
    cudaGetSymbolAddress((void**)&upwh,  g_upwh);

    // 0. fp32 -> fp16 copies
    {
        int n4;
        n4 = S_MAX * E_DIM / 4;
        round_h<<<(n4 + 255) / 256, 256>>>((const float4*)query, qrh, n4);
        n4 = LEVELS * 3 * E_DIM * E_DIM / 4;
        round_h<<<(n4 + 255) / 256, 256>>>((const float4*)in_w, inwh, n4);
        n4 = LEVELS * E_DIM * E_DIM / 4;
        round_h<<<(n4 + 255) / 256, 256>>>((const float4*)out_w, outwh, n4);
        n4 = (LEVELS - 1) * E_DIM * E_DIM / 4;
        round_h<<<(n4 + 255) / 256, 256>>>((const float4*)up_w, upwh, n4);
    }

    // 1. W1^T, W2^T
    transpose_w<<<dim3(32, 32, 2), dim3(32, 8)>>>();
    // 2. QKV all levels (+ P2 = W0@W1 hidden in grid)
    gemm_qkv_all<<<dim3(24, 33), 256, GEMM_SMEM>>>(in_b);
    // 3. attention all levels (128-query CTAs)
    attn_all<<<dim3(30, 16), 256, ATTN_SMEM>>>();
    // 4. out-proj all levels (+ P3 = P2@W2 hidden in grid)
    gemm_out_all<<<dim3(8, 38), 256, GEMM_SMEM>>>(out_b);
    // 5. all combine projections + bias row, one launch
    combine_proj<<<116, 256, GEMM_SMEM>>>(up_b);
    // 6. final tap-composed upsample + residual sum
    final_combine<<<2048, 256>>>(out);
}

// round 16
// speedup vs baseline: 1.5407x; 1.0098x over previous
#include <cuda_runtime.h>
#include <cuda_fp16.h>
#include <cstdint>

#define E_DIM 1024
#define S_MAX 2048
#define LEVELS 4
#define R_TOT 3840   // 2048+1024+512+256

// ---------------- scratch ---------------------------------------------------
__device__ __half g_qkvh[R_TOT * 3 * E_DIM];
__device__ __half g_attnh[R_TOT * E_DIM];
__device__ __half g_outsh[R_TOT * E_DIM];
__device__ float  g_outsf[R_TOT * E_DIM];
__device__ __half g_W1T[E_DIM * E_DIM];
__device__ __half g_W2T[E_DIM * E_DIM];
__device__ __half g_P2h[E_DIM * E_DIM];   // W0 @ W1
__device__ __half g_P3h[E_DIM * E_DIM];   // P2 @ W2
__device__ float  g_Q1[1024 * E_DIM];
__device__ float  g_Q2[512 * E_DIM];
__device__ float  g_Q3[256 * E_DIM];
__device__ float  g_rrow[E_DIM];
__device__ float  g_zb[E_DIM];
// fp16 copies of inputs
__device__ __half g_qrh[S_MAX * E_DIM];
__device__ __half g_inwh[LEVELS * 3 * E_DIM * E_DIM];
__device__ __half g_outwh[LEVELS * E_DIM * E_DIM];
__device__ __half g_upwh[(LEVELS - 1) * E_DIM * E_DIM];

// ---------------- helpers ---------------------------------------------------
__device__ __forceinline__ void mma_f16(float* c, const uint32_t* a,
                                        uint32_t b0, uint32_t b1) {
    asm volatile(
        "mma.sync.aligned.m16n8k16.row.col.f32.f16.f16.f32 "
        "{%0,%1,%2,%3}, {%4,%5,%6,%7}, {%8,%9}, {%0,%1,%2,%3};"
        : "+f"(c[0]), "+f"(c[1]), "+f"(c[2]), "+f"(c[3])
        : "r"(a[0]), "r"(a[1]), "r"(a[2]), "r"(a[3]), "r"(b0), "r"(b1));
}

__device__ __forceinline__ void cp_async16(uint32_t smem_addr, const void* gptr) {
    asm volatile("cp.async.cg.shared.global [%0], [%1], 16;\n"
                 :: "r"(smem_addr), "l"(gptr));
}
__device__ __forceinline__ void cp_commit() {
    asm volatile("cp.async.commit_group;\n" ::: "memory");
}
__device__ __forceinline__ void cp_wait0() {
    asm volatile("cp.async.wait_group 0;\n" ::: "memory");
}
__device__ __forceinline__ void cp_wait1() {
    asm volatile("cp.async.wait_group 1;\n" ::: "memory");
}

// ---------------- merged fp32 -> fp16 prep kernel ----------------------------
#define N4_Q   (S_MAX * E_DIM / 4)                      // 524288
#define N4_IW  (LEVELS * 3 * E_DIM * E_DIM / 4)         // 3145728
#define N4_OW  (LEVELS * E_DIM * E_DIM / 4)             // 1048576
#define N4_UW  ((LEVELS - 1) * E_DIM * E_DIM / 4)       // 786432
#define N4_ALL (N4_Q + N4_IW + N4_OW + N4_UW)

__global__ void __launch_bounds__(256) prep_all(
    const float4* __restrict__ q, const float4* __restrict__ iw,
    const float4* __restrict__ ow, const float4* __restrict__ uw)
{
    int i = blockIdx.x * blockDim.x + threadIdx.x;
    if (i >= N4_ALL) return;
    const float4* src;
    __half* dst;
    int off;
    if (i < N4_Q)                      { src = q;  dst = g_qrh;   off = i; }
    else if (i < N4_Q + N4_IW)         { src = iw; dst = g_inwh;  off = i - N4_Q; }
    else if (i < N4_Q + N4_IW + N4_OW) { src = ow; dst = g_outwh; off = i - N4_Q - N4_IW; }
    else                               { src = uw; dst = g_upwh;  off = i - N4_Q - N4_IW - N4_OW; }
    float4 v = src[off];
    __half2* d = reinterpret_cast<__half2*>(dst + (size_t)off * 4);
    d[0] = __floats2half2_rn(v.x, v.y);
    d[1] = __floats2half2_rn(v.z, v.w);
}

// ---------------- fp16 GEMM core (BK=64, 3-stage cp.async pipeline) ---------
#define BM 128
#define BN 128
#define BK 64
#define SSTH 72
#define NSTG 3
#define GEMM_SMEM (NSTG * 2 * BM * SSTH * 2)   // 110592 B

__device__ __forceinline__ void gemm_core(
    const __half* __restrict__ X, int ldx,
    const __half* __restrict__ Wp,          // W + bn*K
    const float* __restrict__ bias,
    __half* __restrict__ Yh,                // nullable
    float* __restrict__ Yf,                 // nullable
    int N, int K, int bm, int bn,
    __half* As, __half* Bs)
{
    const int tid = threadIdx.x;
    const int lane = tid & 31;
    const int wid = tid >> 5;
    const int warp_row = (wid & 1) * 64;
    const int warp_col = (wid >> 1) * 32;

    const int lr = tid >> 3;        // 0..31 row base (4 its of 32 rows)
    const int kb = (tid & 7) * 8;   // half offset within 64-half row

    const uint32_t aBase = (uint32_t)__cvta_generic_to_shared(As);
    const uint32_t bBase = (uint32_t)__cvta_generic_to_shared(Bs);
    const __half* Xp = X + (size_t)bm * ldx;
    const int nchunk = K / BK;

    float acc[4][4][4];
#pragma unroll
    for (int mi = 0; mi < 4; mi++)
#pragma unroll
        for (int ni = 0; ni < 4; ni++)
#pragma unroll
            for (int j = 0; j < 4; j++) acc[mi][ni][j] = 0.f;

#define G_PREFETCH(cc, sg)                                                     \
    {                                                                          \
        _Pragma("unroll") for (int it = 0; it < 4; it++) {                     \
            int r = lr + it * 32;                                              \
            cp_async16(aBase + ((sg)*BM*SSTH + r*SSTH + kb) * 2,               \
                       Xp + (size_t)r * ldx + (cc)*BK + kb);                   \
            cp_async16(bBase + ((sg)*BN*SSTH + r*SSTH + kb) * 2,               \
                       Wp + (size_t)r * K + (cc)*BK + kb);                     \
        }                                                                      \
        cp_commit();                                                           \
    }

    G_PREFETCH(0, 0);
    if (nchunk > 1) G_PREFETCH(1, 1);

    const int g = lane >> 2;
    const int q = lane & 3;

    for (int c = 0; c < nchunk; c++) {
        const int s = c % NSTG;
        if (c + 1 < nchunk) cp_wait1(); else cp_wait0();
        __syncthreads();
        if (c + 2 < nchunk) G_PREFETCH(c + 2, (c + 2) % NSTG);

        const __half* Ab = As + s * BM * SSTH;
        const __half* Bb = Bs + s * BN * SSTH;
#pragma unroll
        for (int ks = 0; ks < 4; ks++) {
            const int kc = ks * 16 + 2 * q;
            uint32_t af[4][4], bf[4][2];
#pragma unroll
            for (int mi = 0; mi < 4; mi++) {
                const __half* p = Ab + (warp_row + mi * 16 + g) * SSTH + kc;
                af[mi][0] = *reinterpret_cast<const uint32_t*>(p);
                af[mi][1] = *reinterpret_cast<const uint32_t*>(p + 8 * SSTH);
                af[mi][2] = *reinterpret_cast<const uint32_t*>(p + 8);
                af[mi][3] = *reinterpret_cast<const uint32_t*>(p + 8 * SSTH + 8);
            }
#pragma unroll
            for (int ni = 0; ni < 4; ni++) {
                const __half* p = Bb + (warp_col + ni * 8 + g) * SSTH + kc;
                bf[ni][0] = *reinterpret_cast<const uint32_t*>(p);
                bf[ni][1] = *reinterpret_cast<const uint32_t*>(p + 8);
            }
#pragma unroll
            for (int mi = 0; mi < 4; mi++)
#pragma unroll
                for (int ni = 0; ni < 4; ni++)
                    mma_f16(acc[mi][ni], af[mi], bf[ni][0], bf[ni][1]);
        }
    }

    __syncthreads();   // all reads done before tile exit (smem reused by next call)

#pragma unroll
    for (int mi = 0; mi < 4; mi++) {
        const int row0 = bm + warp_row + mi * 16 + g;
#pragma unroll
        for (int ni = 0; ni < 4; ni++) {
            const int col = bn + warp_col + ni * 8 + 2 * q;
            float2 bb = *reinterpret_cast<const float2*>(bias + col);
            float v0 = acc[mi][ni][0] + bb.x;
            float v1 = acc[mi][ni][1] + bb.y;
            float v2 = acc[mi][ni][2] + bb.x;
            float v3 = acc[mi][ni][3] + bb.y;
            if (Yh) {
                *reinterpret_cast<__half2*>(Yh + (size_t)row0 * N + col) =
                    __floats2half2_rn(v0, v1);
                *reinterpret_cast<__half2*>(Yh + (size_t)(row0 + 8) * N + col) =
                    __floats2half2_rn(v2, v3);
            }
            if (Yf) {
                *reinterpret_cast<float2*>(Yf + (size_t)row0 * N + col) =
                    make_float2(v0, v1);
                *reinterpret_cast<float2*>(Yf + (size_t)(row0 + 8) * N + col) =
                    make_float2(v2, v3);
            }
        }
    }
#undef G_PREFETCH
}

// level tables
__device__ __constant__ int d_qoff[4] = {0, 2048, 3072, 3584};
__device__ __constant__ int d_rbCum[5] = {0, 16, 24, 28, 30};   // /128 blocks
__device__ __constant__ int d_Llvl[4] = {2048, 1024, 512, 256};

// ---------------- weight transpose (W1, W2; half) ---------------------------
__global__ void __launch_bounds__(256) transpose_w()
{
    __shared__ __half t[32][33];
    const __half* src = g_upwh + (size_t)(blockIdx.z + 1) * E_DIM * E_DIM;
    __half* dst = blockIdx.z == 0 ? g_W1T : g_W2T;
    int x = blockIdx.x * 32 + threadIdx.x;
    int y = blockIdx.y * 32 + threadIdx.y;
#pragma unroll
    for (int i = 0; i < 32; i += 8)
        t[threadIdx.y + i][threadIdx.x] = src[(size_t)(y + i) * E_DIM + x];
    __syncthreads();
    x = blockIdx.y * 32 + threadIdx.x;
    y = blockIdx.x * 32 + threadIdx.y;
#pragma unroll
    for (int i = 0; i < 32; i += 8)
        dst[(size_t)(y + i) * E_DIM + x] = t[threadIdx.x][threadIdx.y + i];
}

// ---------------- batched QKV projection (+ hidden P2 = W0@W1) --------------
__global__ void __launch_bounds__(256, 2) gemm_qkv_all(
    const float* __restrict__ in_b)
{
    extern __shared__ __half smem[];
    const int by = blockIdx.y;

    if (by >= 30) {   // P2 = W0 @ W1T^T
        int li = (by - 30) * gridDim.x + blockIdx.x;
        if (li >= 64) return;
        gemm_core(g_upwh, E_DIM, g_W1T + (size_t)(li % 8) * BN * E_DIM, g_zb,
                  g_P2h, nullptr,
                  E_DIM, E_DIM, (li / 8) * BM, (li % 8) * BN,
                  smem, smem + NSTG * BM * SSTH);
        return;
    }

    int lvl = 0;
#pragma unroll
    for (int i = 0; i < 3; i++) if (by >= d_rbCum[i + 1]) lvl = i + 1;
    const int bm = (by - d_rbCum[lvl]) * BM;
    const int bn = blockIdx.x * BN;
    const int stride = 1 << lvl;

    gemm_core(g_qrh, stride * E_DIM,
              g_inwh + (size_t)lvl * 3 * E_DIM * E_DIM + (size_t)bn * E_DIM,
              in_b + (size_t)lvl * 3 * E_DIM,
              g_qkvh + (size_t)d_qoff[lvl] * 3 * E_DIM, nullptr,
              3 * E_DIM, E_DIM, bm, bn,
              smem, smem + NSTG * BM * SSTH);
}

// ---------------- batched out projection (+ hidden P3 = P2@W2) --------------
__global__ void __launch_bounds__(256, 2) gemm_out_all(
    const float* __restrict__ out_b)
{
    extern __shared__ __half smem[];
    const int by = blockIdx.y;

    if (by >= 30) {   // P3 = P2 @ W2T^T   (gridDim.x == 8)
        int li = (by - 30) * 8 + blockIdx.x;
        gemm_core(g_P2h, E_DIM, g_W2T + (size_t)(li % 8) * BN * E_DIM, g_zb,
                  g_P3h, nullptr,
                  E_DIM, E_DIM, (li / 8) * BM, (li % 8) * BN,
                  smem, smem + NSTG * BM * SSTH);
        return;
    }

    int lvl = 0;
#pragma unroll
    for (int i = 0; i < 3; i++) if (by >= d_rbCum[i + 1]) lvl = i + 1;
    const int bm = (by - d_rbCum[lvl]) * BM;
    const int bn = blockIdx.x * BN;

    gemm_core(g_attnh + (size_t)d_qoff[lvl] * E_DIM, E_DIM,
              g_outwh + (size_t)lvl * E_DIM * E_DIM + (size_t)bn * E_DIM,
              out_b + (size_t)lvl * E_DIM,
              g_outsh + (size_t)d_qoff[lvl] * E_DIM,
              g_outsf + (size_t)d_qoff[lvl] * E_DIM,
              E_DIM, E_DIM, bm, bn,
              smem, smem + NSTG * BM * SSTH);
}

// ---------------- one-launch combine projections + bias row -----------------
__global__ void __launch_bounds__(256, 2) combine_proj(
    const float* __restrict__ up_b)
{
    extern __shared__ __half smem[];
    const int li = blockIdx.x;

    if (li < 16) {
        gemm_core(g_outsh + (size_t)d_qoff[3] * E_DIM, E_DIM,
                  g_P3h + (size_t)(li % 8) * BN * E_DIM, g_zb,
                  nullptr, g_Q3,
                  E_DIM, E_DIM, (li / 8) * BM, (li % 8) * BN,
                  smem, smem + NSTG * BM * SSTH);
    } else if (li < 48) {
        int t = li - 16;
        gemm_core(g_outsh + (size_t)d_qoff[2] * E_DIM, E_DIM,
                  g_P2h + (size_t)(t % 8) * BN * E_DIM, g_zb,
                  nullptr, g_Q2,
                  E_DIM, E_DIM, (t / 8) * BM, (t % 8) * BN,
                  smem, smem + NSTG * BM * SSTH);
    } else if (li < 112) {
        int t = li - 48;
        gemm_core(g_outsh + (size_t)d_qoff[1] * E_DIM, E_DIM,
                  g_upwh + (size_t)(t % 8) * BN * E_DIM, g_zb,
                  nullptr, g_Q1,
                  E_DIM, E_DIM, (t / 8) * BM, (t % 8) * BN,
                  smem, smem + NSTG * BM * SSTH);
    } else {
        const float* b0 = up_b;
        const float* b1 = up_b + E_DIM;
        const float* b2 = up_b + 2 * E_DIM;
        int bi = li - 112;
        int warp = threadIdx.x >> 5, lane = threadIdx.x & 31;
        for (int cc = 0; cc < 32; cc++) {
            int c = bi * 256 + warp * 32 + cc;
            float s = 0.f;
            for (int k = lane; k < E_DIM; k += 32)
                s += b2[k] * __half2float(g_P2h[(size_t)c * E_DIM + k])
                   + b1[k] * __half2float(g_upwh[(size_t)c * E_DIM + k]);
#pragma unroll
            for (int off = 16; off; off >>= 1)
                s += __shfl_xor_sync(0xffffffffu, s, off);
            if (lane == 0) g_rrow[c] = s + b0[c];
        }
    }
}

// ---------------- final: out = up3(Q3) + up2(Q2) + up(Q1) + rrow + o0 -------
__device__ __forceinline__ void taps(float pos, int L, int& i0, int& i1, float& w)
{
    pos = fminf(fmaxf(pos, 0.f), (float)(L - 1));
    i0 = (int)floorf(pos);
    i1 = min(i0 + 1, L - 1);
    w = pos - (float)i0;
}

__global__ void __launch_bounds__(256) final_combine(float* __restrict__ out)
{
    const int r = blockIdx.x;
    const int c = threadIdx.x * 4;

    int j0, j1; float w1;
    taps(0.5f * r - 0.25f, 1024, j0, j1, w1);
    int jj[2] = {j0, j1};
    float wj[2] = {1.f - w1, w1};

    int kk2[4]; float wk2[4];
#pragma unroll
    for (int t = 0; t < 2; t++) {
        int a, b; float w;
        taps(0.5f * jj[t] - 0.25f, 512, a, b, w);
        kk2[2 * t] = a;     wk2[2 * t] = wj[t] * (1.f - w);
        kk2[2 * t + 1] = b; wk2[2 * t + 1] = wj[t] * w;
    }

    int mm[8]; float wm[8];
#pragma unroll
    for (int t = 0; t < 4; t++) {
        int a, b; float w;
        taps(0.5f * kk2[t] - 0.25f, 256, a, b, w);
        mm[2 * t] = a;     wm[2 * t] = wk2[t] * (1.f - w);
        mm[2 * t + 1] = b; wm[2 * t + 1] = wk2[t] * w;
    }

    float4 acc = *reinterpret_cast<const float4*>(g_outsf + (size_t)r * E_DIM + c);
    float4 rr  = *reinterpret_cast<const float4*>(g_rrow + c);
    acc.x += rr.x; acc.y += rr.y; acc.z += rr.z; acc.w += rr.w;

#pragma unroll
    for (int t = 0; t < 2; t++) {
        float4 v = *reinterpret_cast<const float4*>(g_Q1 + (size_t)jj[t] * E_DIM + c);
        acc.x += wj[t] * v.x; acc.y += wj[t] * v.y;
        acc.z += wj[t] * v.z; acc.w += wj[t] * v.w;
    }
#pragma unroll
    for (int t = 0; t < 4; t++) {
        float4 v = *reinterpret_cast<const float4*>(g_Q2 + (size_t)kk2[t] * E_DIM + c);
        acc.x += wk2[t] * v.x; acc.y += wk2[t] * v.y;
        acc.z += wk2[t] * v.z; acc.w += wk2[t] * v.w;
    }
#pragma unroll
    for (int t = 0; t < 8; t++) {
        float4 v = *reinterpret_cast<const float4*>(g_Q3 + (size_t)mm[t] * E_DIM + c);
        acc.x += wm[t] * v.x; acc.y += wm[t] * v.y;
        acc.z += wm[t] * v.z; acc.w += wm[t] * v.w;
    }
    *reinterpret_cast<float4*>(out + (size_t)r * E_DIM + c) = acc;
}

// ---------------- batched fp16 flash attention (128 queries / 8 warps) ------
#define SA 72   // smem row stride in halfs
#define ATTN_SMEM ((128 + 64 + 64) * SA * 2)   // Q(=P) 128 rows, K 64, Vt 64

__global__ void __launch_bounds__(256) attn_all()
{
    extern __shared__ __half sm[];
    __half* Qs = sm;                 // [128 q rows][SA]  (reused as P)
    __half* Ks = sm + 128 * SA;      // [64 key rows][SA]
    __half* Vt = sm + 192 * SA;      // [64 d rows][SA]
    __half* Ps = Qs;

    const int bx = blockIdx.x;
    int lvl = 0;
#pragma unroll
    for (int i = 0; i < 3; i++) if (bx >= d_rbCum[i + 1]) lvl = i + 1;
    const int L = d_Llvl[lvl];
    const __half* qkv = g_qkvh + (size_t)d_qoff[lvl] * 3 * E_DIM;
    __half* outp = g_attnh + (size_t)d_qoff[lvl] * E_DIM;

    const int h = blockIdx.y;
    const int q0 = (bx - d_rbCum[lvl]) * 128;
    const int tid = threadIdx.x;
    const int wid = tid >> 5;
    const int lane = tid & 31;
    const int g = lane >> 2;
    const int q = lane & 3;

    const int lc8 = (tid & 7) * 8;  // half offset within 64-half row
    const int lrw = tid >> 3;       // 0..31

    // load Q tile (128 rows; scaled by 1/8, exact in fp16)
    const __half2 sc2 = __floats2half2_rn(0.125f, 0.125f);
#pragma unroll
    for (int it = 0; it < 4; it++) {
        int r = lrw + it * 32;
        const __half2* src = reinterpret_cast<const __half2*>(
            qkv + (size_t)(q0 + r) * 3072 + h * 64 + lc8);
        __half2* dst = reinterpret_cast<__half2*>(Qs + r * SA + lc8);
#pragma unroll
        for (int j = 0; j < 4; j++) dst[j] = __hmul2(src[j], sc2);
    }
    __syncthreads();

    // preload Q fragments (4 ksteps of 16); warp w owns rows wid*16..wid*16+15
    uint32_t qa[4][4];
    const int arow = wid * 16 + g;
#pragma unroll
    for (int ks = 0; ks < 4; ks++) {
        const __half* p = Qs + arow * SA + ks * 16 + 2 * q;
        qa[ks][0] = *reinterpret_cast<const uint32_t*>(p);
        qa[ks][1] = *reinterpret_cast<const uint32_t*>(p + 8 * SA);
        qa[ks][2] = *reinterpret_cast<const uint32_t*>(p + 8);
        qa[ks][3] = *reinterpret_cast<const uint32_t*>(p + 8 * SA + 8);
    }

    float m_i[2] = {-1e30f, -1e30f};
    float l_i[2] = {0.f, 0.f};
    float O[8][4];
#pragma unroll
    for (int ni = 0; ni < 8; ni++)
#pragma unroll
        for (int j = 0; j < 4; j++) O[ni][j] = 0.f;

    for (int kb = 0; kb < L; kb += 64) {
        __syncthreads();   // prior block's K/Vt reads complete
#pragma unroll
        for (int it = 0; it < 2; it++) {
            int r = lrw + it * 32;
            const __half* base = qkv + (size_t)(kb + r) * 3072 + h * 64 + lc8;
            *reinterpret_cast<uint4*>(Ks + r * SA + lc8) =
                *reinterpret_cast<const uint4*>(base + 1024);
            const __half* vsrc = base + 2048;
#pragma unroll
            for (int j = 0; j < 8; j++)
                Vt[(lc8 + j) * SA + r] = vsrc[j];
        }
        __syncthreads();

        // S = Q @ K^T
        float s[8][4];
#pragma unroll
        for (int ni = 0; ni < 8; ni++)
#pragma unroll
            for (int j = 0; j < 4; j++) s[ni][j] = 0.f;
#pragma unroll
        for (int ks = 0; ks < 4; ks++) {
            const int kc = ks * 16 + 2 * q;
#pragma unroll
            for (int ni = 0; ni < 8; ni++) {
                const __half* p = Ks + (ni * 8 + g) * SA + kc;
                mma_f16(s[ni], qa[ks],
                        *reinterpret_cast<const uint32_t*>(p),
                        *reinterpret_cast<const uint32_t*>(p + 8));
            }
        }

        // online softmax
        float rmax0 = -1e30f, rmax1 = -1e30f;
#pragma unroll
        for (int ni = 0; ni < 8; ni++) {
            rmax0 = fmaxf(rmax0, fmaxf(s[ni][0], s[ni][1]));
            rmax1 = fmaxf(rmax1, fmaxf(s[ni][2], s[ni][3]));
        }
#pragma unroll
        for (int off = 1; off <= 2; off <<= 1) {
            rmax0 = fmaxf(rmax0, __shfl_xor_sync(0xffffffffu, rmax0, off));
            rmax1 = fmaxf(rmax1, __shfl_xor_sync(0xffffffffu, rmax1, off));
        }
        float mnew0 = fmaxf(m_i[0], rmax0);
        float mnew1 = fmaxf(m_i[1], rmax1);
        float al0 = __expf(m_i[0] - mnew0);
        float al1 = __expf(m_i[1] - mnew1);
        float sum0 = 0.f, sum1 = 0.f;
#pragma unroll
        for (int ni = 0; ni < 8; ni++) {
            s[ni][0] = __expf(s[ni][0] - mnew0);
            s[ni][1] = __expf(s[ni][1] - mnew0);
            s[ni][2] = __expf(s[ni][2] - mnew1);
            s[ni][3] = __expf(s[ni][3] - mnew1);
            sum0 += s[ni][0] + s[ni][1];
            sum1 += s[ni][2] + s[ni][3];
        }
#pragma unroll
        for (int off = 1; off <= 2; off <<= 1) {
            sum0 += __shfl_xor_sync(0xffffffffu, sum0, off);
            sum1 += __shfl_xor_sync(0xffffffffu, sum1, off);
        }
        l_i[0] = l_i[0] * al0 + sum0;
        l_i[1] = l_i[1] * al1 + sum1;
        m_i[0] = mnew0;
        m_i[1] = mnew1;
#pragma unroll
        for (int ni = 0; ni < 8; ni++) {
            O[ni][0] *= al0; O[ni][1] *= al0;
            O[ni][2] *= al1; O[ni][3] *= al1;
        }

        // write P into warp-local rows of reused Q region
        __syncwarp();
#pragma unroll
        for (int ni = 0; ni < 8; ni++) {
            const int col = ni * 8 + 2 * q;
            *reinterpret_cast<__half2*>(Ps + arow * SA + col) =
                __floats2half2_rn(s[ni][0], s[ni][1]);
            *reinterpret_cast<__half2*>(Ps + (arow + 8) * SA + col) =
                __floats2half2_rn(s[ni][2], s[ni][3]);
        }
        __syncwarp();

        // O += P @ V
#pragma unroll
        for (int ks = 0; ks < 4; ks++) {
            const int kc = ks * 16 + 2 * q;
            uint32_t pa[4];
            const __half* pp = Ps + arow * SA + kc;
            pa[0] = *reinterpret_cast<const uint32_t*>(pp);
            pa[1] = *reinterpret_cast<const uint32_t*>(pp + 8 * SA);
            pa[2] = *reinterpret_cast<const uint32_t*>(pp + 8);
            pa[3] = *reinterpret_cast<const uint32_t*>(pp + 8 * SA + 8);
#pragma unroll
            for (int ni = 0; ni < 8; ni++) {
                const __half* vp = Vt + (ni * 8 + g) * SA + kc;
                mma_f16(O[ni], pa,
                        *reinterpret_cast<const uint32_t*>(vp),
                        *reinterpret_cast<const uint32_t*>(vp + 8));
            }
        }
    }

    // normalize + write fp16
    const float inv0 = 1.0f / l_i[0];
    const float inv1 = 1.0f / l_i[1];
    const size_t row0 = (size_t)(q0 + arow);
#pragma unroll
    for (int ni = 0; ni < 8; ni++) {
        const int col = h * 64 + ni * 8 + 2 * q;
        *reinterpret_cast<__half2*>(outp + row0 * E_DIM + col) =
            __floats2half2_rn(O[ni][0] * inv0, O[ni][1] * inv0);
        *reinterpret_cast<__half2*>(outp + (row0 + 8) * E_DIM + col) =
            __floats2half2_rn(O[ni][2] * inv1, O[ni][3] * inv1);
    }
}

// ---------------- launcher --------------------------------------------------
extern "C" void kernel_launch(void* const* d_in, const int* in_sizes, int n_in,
                              void* d_out, int out_size)
{
    const float* query = (const float*)d_in[0];
    const float* in_w  = (const float*)d_in[1];
    const float* in_b  = (const float*)d_in[2];
    const float* out_w = (const float*)d_in[3];
    const float* out_b = (const float*)d_in[4];
    const float* up_w  = (const float*)d_in[5];
    const float* up_b  = (const float*)d_in[6];
    float* out = (float*)d_out;

    cudaFuncSetAttribute(gemm_qkv_all, cudaFuncAttributeMaxDynamicSharedMemorySize, GEMM_SMEM);
    cudaFuncSetAttribute(gemm_out_all, cudaFuncAttributeMaxDynamicSharedMemorySize, GEMM_SMEM);
    cudaFuncSetAttribute(combine_proj, cudaFuncAttributeMaxDynamicSharedMemorySize, GEMM_SMEM);
    cudaFuncSetAttribute(attn_all,     cudaFuncAttributeMaxDynamicSharedMemorySize, ATTN_SMEM);

    // 0. fp32 -> fp16 copies, single launch
    prep_all<<<(N4_ALL + 255) / 256, 256>>>(
        (const float4*)query, (const float4*)in_w,
        (const float4*)out_w, (const float4*)up_w);

    // 1. W1^T, W2^T
    transpose_w<<<dim3(32, 32, 2), dim3(32, 8)>>>();
    // 2. QKV all levels (+ P2 = W0@W1 hidden in grid)
    gemm_qkv_all<<<dim3(24, 33), 256, GEMM_SMEM>>>(in_b);
    // 3. attention all levels (128-query CTAs)
    attn_all<<<dim3(30, 16), 256, ATTN_SMEM>>>();
    // 4. out-proj all levels (+ P3 = P2@W2 hidden in grid)
    gemm_out_all<<<dim3(8, 38), 256, GEMM_SMEM>>>(out_b);
    // 5. all combine projections + bias row, one launch
    combine_proj<<<116, 256, GEMM_SMEM>>>(up_b);
    // 6. final tap-composed upsample + residual sum
    final_combine<<<2048, 256>>>(out);
}

// round 17
// speedup vs baseline: 1.9619x; 1.2734x over previous
#include <cuda_runtime.h>
#include <cuda_fp16.h>
#include <cstdint>

#define E_DIM 1024
#define S_MAX 2048
#define LEVELS 4
#define R_TOT 3840   // 2048+1024+512+256

// ---------------- scratch ---------------------------------------------------
__device__ __half g_qkvh[R_TOT * 3 * E_DIM];
__device__ __half g_attnh[R_TOT * E_DIM];
__device__ __half g_outsh[R_TOT * E_DIM];
__device__ float  g_outsf[R_TOT * E_DIM];
__device__ __half g_W1T[E_DIM * E_DIM];
__device__ __half g_W2T[E_DIM * E_DIM];
__device__ __half g_P2h[E_DIM * E_DIM];   // W0 @ W1
__device__ __half g_P3h[E_DIM * E_DIM];   // P2 @ W2
__device__ float  g_Q1[1024 * E_DIM];
__device__ float  g_Q2[512 * E_DIM];
__device__ float  g_Q3[256 * E_DIM];
__device__ float  g_rrow[E_DIM];
__device__ float  g_zb[E_DIM];
// fp16 copies of inputs
__device__ __half g_qrh[S_MAX * E_DIM];
__device__ __half g_inwh[LEVELS * 3 * E_DIM * E_DIM];
__device__ __half g_outwh[LEVELS * E_DIM * E_DIM];
__device__ __half g_upwh[(LEVELS - 1) * E_DIM * E_DIM];

// ---------------- helpers ---------------------------------------------------
__device__ __forceinline__ void mma_f16(float* c, const uint32_t* a,
                                        uint32_t b0, uint32_t b1) {
    asm volatile(
        "mma.sync.aligned.m16n8k16.row.col.f32.f16.f16.f32 "
        "{%0,%1,%2,%3}, {%4,%5,%6,%7}, {%8,%9}, {%0,%1,%2,%3};"
        : "+f"(c[0]), "+f"(c[1]), "+f"(c[2]), "+f"(c[3])
        : "r"(a[0]), "r"(a[1]), "r"(a[2]), "r"(a[3]), "r"(b0), "r"(b1));
}

__device__ __forceinline__ void cp_async16(uint32_t smem_addr, const void* gptr) {
    asm volatile("cp.async.cg.shared.global [%0], [%1], 16;\n"
                 :: "r"(smem_addr), "l"(gptr));
}
__device__ __forceinline__ void cp_commit() {
    asm volatile("cp.async.commit_group;\n" ::: "memory");
}
__device__ __forceinline__ void cp_wait0() {
    asm volatile("cp.async.wait_group 0;\n" ::: "memory");
}
__device__ __forceinline__ void cp_wait1() {
    asm volatile("cp.async.wait_group 1;\n" ::: "memory");
}

__device__ __forceinline__ void ldm_x2_trans(uint32_t& d0, uint32_t& d1, uint32_t a) {
    asm volatile("ldmatrix.sync.aligned.m8n8.x2.trans.shared.b16 {%0,%1}, [%2];"
                 : "=r"(d0), "=r"(d1) : "r"(a));
}

__device__ __forceinline__ uint32_t packh2(float a, float b) {
    __half2 h = __floats2half2_rn(a, b);
    return *reinterpret_cast<uint32_t*>(&h);
}

// ---------------- merged fp32 -> fp16 prep kernel ----------------------------
#define N4_Q   (S_MAX * E_DIM / 4)
#define N4_IW  (LEVELS * 3 * E_DIM * E_DIM / 4)
#define N4_OW  (LEVELS * E_DIM * E_DIM / 4)
#define N4_UW  ((LEVELS - 1) * E_DIM * E_DIM / 4)
#define N4_ALL (N4_Q + N4_IW + N4_OW + N4_UW)

__global__ void __launch_bounds__(256) prep_all(
    const float4* __restrict__ q, const float4* __restrict__ iw,
    const float4* __restrict__ ow, const float4* __restrict__ uw)
{
    int i = blockIdx.x * blockDim.x + threadIdx.x;
    if (i >= N4_ALL) return;
    const float4* src;
    __half* dst;
    int off;
    if (i < N4_Q)                      { src = q;  dst = g_qrh;   off = i; }
    else if (i < N4_Q + N4_IW)         { src = iw; dst = g_inwh;  off = i - N4_Q; }
    else if (i < N4_Q + N4_IW + N4_OW) { src = ow; dst = g_outwh; off = i - N4_Q - N4_IW; }
    else                               { src = uw; dst = g_upwh;  off = i - N4_Q - N4_IW - N4_OW; }
    float4 v = src[off];
    __half2* d = reinterpret_cast<__half2*>(dst + (size_t)off * 4);
    d[0] = __floats2half2_rn(v.x, v.y);
    d[1] = __floats2half2_rn(v.z, v.w);
}

// ---------------- fp16 GEMM core (BK=64, 3-stage cp.async pipeline) ---------
#define BM 128
#define BN 128
#define BK 64
#define SSTH 72
#define NSTG 3
#define GEMM_SMEM (NSTG * 2 * BM * SSTH * 2)   // 110592 B

__device__ __forceinline__ void gemm_core(
    const __half* __restrict__ X, int ldx,
    const __half* __restrict__ Wp,
    const float* __restrict__ bias,
    __half* __restrict__ Yh,
    float* __restrict__ Yf,
    int N, int K, int bm, int bn,
    __half* As, __half* Bs)
{
    const int tid = threadIdx.x;
    const int lane = tid & 31;
    const int wid = tid >> 5;
    const int warp_row = (wid & 1) * 64;
    const int warp_col = (wid >> 1) * 32;

    const int lr = tid >> 3;
    const int kb = (tid & 7) * 8;

    const uint32_t aBase = (uint32_t)__cvta_generic_to_shared(As);
    const uint32_t bBase = (uint32_t)__cvta_generic_to_shared(Bs);
    const __half* Xp = X + (size_t)bm * ldx;
    const int nchunk = K / BK;

    float acc[4][4][4];
#pragma unroll
    for (int mi = 0; mi < 4; mi++)
#pragma unroll
        for (int ni = 0; ni < 4; ni++)
#pragma unroll
            for (int j = 0; j < 4; j++) acc[mi][ni][j] = 0.f;

#define G_PREFETCH(cc, sg)                                                     \
    {                                                                          \
        _Pragma("unroll") for (int it = 0; it < 4; it++) {                     \
            int r = lr + it * 32;                                              \
            cp_async16(aBase + ((sg)*BM*SSTH + r*SSTH + kb) * 2,               \
                       Xp + (size_t)r * ldx + (cc)*BK + kb);                   \
            cp_async16(bBase + ((sg)*BN*SSTH + r*SSTH + kb) * 2,               \
                       Wp + (size_t)r * K + (cc)*BK + kb);                     \
        }                                                                      \
        cp_commit();                                                           \
    }

    G_PREFETCH(0, 0);
    if (nchunk > 1) G_PREFETCH(1, 1);

    const int g = lane >> 2;
    const int q = lane & 3;

    for (int c = 0; c < nchunk; c++) {
        const int s = c % NSTG;
        if (c + 1 < nchunk) cp_wait1(); else cp_wait0();
        __syncthreads();
        if (c + 2 < nchunk) G_PREFETCH(c + 2, (c + 2) % NSTG);

        const __half* Ab = As + s * BM * SSTH;
        const __half* Bb = Bs + s * BN * SSTH;
#pragma unroll
        for (int ks = 0; ks < 4; ks++) {
            const int kc = ks * 16 + 2 * q;
            uint32_t af[4][4], bf[4][2];
#pragma unroll
            for (int mi = 0; mi < 4; mi++) {
                const __half* p = Ab + (warp_row + mi * 16 + g) * SSTH + kc;
                af[mi][0] = *reinterpret_cast<const uint32_t*>(p);
                af[mi][1] = *reinterpret_cast<const uint32_t*>(p + 8 * SSTH);
                af[mi][2] = *reinterpret_cast<const uint32_t*>(p + 8);
                af[mi][3] = *reinterpret_cast<const uint32_t*>(p + 8 * SSTH + 8);
            }
#pragma unroll
            for (int ni = 0; ni < 4; ni++) {
                const __half* p = Bb + (warp_col + ni * 8 + g) * SSTH + kc;
                bf[ni][0] = *reinterpret_cast<const uint32_t*>(p);
                bf[ni][1] = *reinterpret_cast<const uint32_t*>(p + 8);
            }
#pragma unroll
            for (int mi = 0; mi < 4; mi++)
#pragma unroll
                for (int ni = 0; ni < 4; ni++)
                    mma_f16(acc[mi][ni], af[mi], bf[ni][0], bf[ni][1]);
        }
    }

    __syncthreads();

#pragma unroll
    for (int mi = 0; mi < 4; mi++) {
        const int row0 = bm + warp_row + mi * 16 + g;
#pragma unroll
        for (int ni = 0; ni < 4; ni++) {
            const int col = bn + warp_col + ni * 8 + 2 * q;
            float2 bb = *reinterpret_cast<const float2*>(bias + col);
            float v0 = acc[mi][ni][0] + bb.x;
            float v1 = acc[mi][ni][1] + bb.y;
            float v2 = acc[mi][ni][2] + bb.x;
            float v3 = acc[mi][ni][3] + bb.y;
            if (Yh) {
                *reinterpret_cast<__half2*>(Yh + (size_t)row0 * N + col) =
                    __floats2half2_rn(v0, v1);
                *reinterpret_cast<__half2*>(Yh + (size_t)(row0 + 8) * N + col) =
                    __floats2half2_rn(v2, v3);
            }
            if (Yf) {
                *reinterpret_cast<float2*>(Yf + (size_t)row0 * N + col) =
                    make_float2(v0, v1);
                *reinterpret_cast<float2*>(Yf + (size_t)(row0 + 8) * N + col) =
                    make_float2(v2, v3);
            }
        }
    }
#undef G_PREFETCH
}

// level tables
__device__ __constant__ int d_qoff[4] = {0, 2048, 3072, 3584};
__device__ __constant__ int d_rbCum[5] = {0, 16, 24, 28, 30};
__device__ __constant__ int d_Llvl[4] = {2048, 1024, 512, 256};

// ---------------- weight transpose (W1, W2; half) ---------------------------
__global__ void __launch_bounds__(256) transpose_w()
{
    __shared__ __half t[32][33];
    const __half* src = g_upwh + (size_t)(blockIdx.z + 1) * E_DIM * E_DIM;
    __half* dst = blockIdx.z == 0 ? g_W1T : g_W2T;
    int x = blockIdx.x * 32 + threadIdx.x;
    int y = blockIdx.y * 32 + threadIdx.y;
#pragma unroll
    for (int i = 0; i < 32; i += 8)
        t[threadIdx.y + i][threadIdx.x] = src[(size_t)(y + i) * E_DIM + x];
    __syncthreads();
    x = blockIdx.y * 32 + threadIdx.x;
    y = blockIdx.x * 32 + threadIdx.y;
#pragma unroll
    for (int i = 0; i < 32; i += 8)
        dst[(size_t)(y + i) * E_DIM + x] = t[threadIdx.x][threadIdx.y + i];
}

// ---------------- batched QKV projection (+ hidden P2 = W0@W1) --------------
__global__ void __launch_bounds__(256, 2) gemm_qkv_all(
    const float* __restrict__ in_b)
{
    extern __shared__ __half smem[];
    const int by = blockIdx.y;

    if (by >= 30) {
        int li = (by - 30) * gridDim.x + blockIdx.x;
        if (li >= 64) return;
        gemm_core(g_upwh, E_DIM, g_W1T + (size_t)(li % 8) * BN * E_DIM, g_zb,
                  g_P2h, nullptr,
                  E_DIM, E_DIM, (li / 8) * BM, (li % 8) * BN,
                  smem, smem + NSTG * BM * SSTH);
        return;
    }

    int lvl = 0;
#pragma unroll
    for (int i = 0; i < 3; i++) if (by >= d_rbCum[i + 1]) lvl = i + 1;
    const int bm = (by - d_rbCum[lvl]) * BM;
    const int bn = blockIdx.x * BN;
    const int stride = 1 << lvl;

    gemm_core(g_qrh, stride * E_DIM,
              g_inwh + (size_t)lvl * 3 * E_DIM * E_DIM + (size_t)bn * E_DIM,
              in_b + (size_t)lvl * 3 * E_DIM,
              g_qkvh + (size_t)d_qoff[lvl] * 3 * E_DIM, nullptr,
              3 * E_DIM, E_DIM, bm, bn,
              smem, smem + NSTG * BM * SSTH);
}

// ---------------- batched out projection (+ hidden P3 = P2@W2) --------------
__global__ void __launch_bounds__(256, 2) gemm_out_all(
    const float* __restrict__ out_b)
{
    extern __shared__ __half smem[];
    const int by = blockIdx.y;

    if (by >= 30) {
        int li = (by - 30) * 8 + blockIdx.x;
        gemm_core(g_P2h, E_DIM, g_W2T + (size_t)(li % 8) * BN * E_DIM, g_zb,
                  g_P3h, nullptr,
                  E_DIM, E_DIM, (li / 8) * BM, (li % 8) * BN,
                  smem, smem + NSTG * BM * SSTH);
        return;
    }

    int lvl = 0;
#pragma unroll
    for (int i = 0; i < 3; i++) if (by >= d_rbCum[i + 1]) lvl = i + 1;
    const int bm = (by - d_rbCum[lvl]) * BM;
    const int bn = blockIdx.x * BN;

    gemm_core(g_attnh + (size_t)d_qoff[lvl] * E_DIM, E_DIM,
              g_outwh + (size_t)lvl * E_DIM * E_DIM + (size_t)bn * E_DIM,
              out_b + (size_t)lvl * E_DIM,
              g_outsh + (size_t)d_qoff[lvl] * E_DIM,
              g_outsf + (size_t)d_qoff[lvl] * E_DIM,
              E_DIM, E_DIM, bm, bn,
              smem, smem + NSTG * BM * SSTH);
}

// ---------------- one-launch combine projections + bias row -----------------
__global__ void __launch_bounds__(256, 2) combine_proj(
    const float* __restrict__ up_b)
{
    extern __shared__ __half smem[];
    const int li = blockIdx.x;

    if (li < 16) {
        gemm_core(g_outsh + (size_t)d_qoff[3] * E_DIM, E_DIM,
                  g_P3h + (size_t)(li % 8) * BN * E_DIM, g_zb,
                  nullptr, g_Q3,
                  E_DIM, E_DIM, (li / 8) * BM, (li % 8) * BN,
                  smem, smem + NSTG * BM * SSTH);
    } else if (li < 48) {
        int t = li - 16;
        gemm_core(g_outsh + (size_t)d_qoff[2] * E_DIM, E_DIM,
                  g_P2h + (size_t)(t % 8) * BN * E_DIM, g_zb,
                  nullptr, g_Q2,
                  E_DIM, E_DIM, (t / 8) * BM, (t % 8) * BN,
                  smem, smem + NSTG * BM * SSTH);
    } else if (li < 112) {
        int t = li - 48;
        gemm_core(g_outsh + (size_t)d_qoff[1] * E_DIM, E_DIM,
                  g_upwh + (size_t)(t % 8) * BN * E_DIM, g_zb,
                  nullptr, g_Q1,
                  E_DIM, E_DIM, (t / 8) * BM, (t % 8) * BN,
                  smem, smem + NSTG * BM * SSTH);
    } else {
        const float* b0 = up_b;
        const float* b1 = up_b + E_DIM;
        const float* b2 = up_b + 2 * E_DIM;
        int bi = li - 112;
        int warp = threadIdx.x >> 5, lane = threadIdx.x & 31;
        for (int cc = 0; cc < 32; cc++) {
            int c = bi * 256 + warp * 32 + cc;
            float s = 0.f;
            for (int k = lane; k < E_DIM; k += 32)
                s += b2[k] * __half2float(g_P2h[(size_t)c * E_DIM + k])
                   + b1[k] * __half2float(g_upwh[(size_t)c * E_DIM + k]);
#pragma unroll
            for (int off = 16; off; off >>= 1)
                s += __shfl_xor_sync(0xffffffffu, s, off);
            if (lane == 0) g_rrow[c] = s + b0[c];
        }
    }
}

// ---------------- final: out = up3(Q3) + up2(Q2) + up(Q1) + rrow + o0 -------
__device__ __forceinline__ void taps(float pos, int L, int& i0, int& i1, float& w)
{
    pos = fminf(fmaxf(pos, 0.f), (float)(L - 1));
    i0 = (int)floorf(pos);
    i1 = min(i0 + 1, L - 1);
    w = pos - (float)i0;
}

__global__ void __launch_bounds__(256) final_combine(float* __restrict__ out)
{
    const int r = blockIdx.x;
    const int c = threadIdx.x * 4;

    int j0, j1; float w1;
    taps(0.5f * r - 0.25f, 1024, j0, j1, w1);
    int jj[2] = {j0, j1};
    float wj[2] = {1.f - w1, w1};

    int kk2[4]; float wk2[4];
#pragma unroll
    for (int t = 0; t < 2; t++) {
        int a, b; float w;
        taps(0.5f * jj[t] - 0.25f, 512, a, b, w);
        kk2[2 * t] = a;     wk2[2 * t] = wj[t] * (1.f - w);
        kk2[2 * t + 1] = b; wk2[2 * t + 1] = wj[t] * w;
    }

    int mm[8]; float wm[8];
#pragma unroll
    for (int t = 0; t < 4; t++) {
        int a, b; float w;
        taps(0.5f * kk2[t] - 0.25f, 256, a, b, w);
        mm[2 * t] = a;     wm[2 * t] = wk2[t] * (1.f - w);
        mm[2 * t + 1] = b; wm[2 * t + 1] = wk2[t] * w;
    }

    float4 acc = *reinterpret_cast<const float4*>(g_outsf + (size_t)r * E_DIM + c);
    float4 rr  = *reinterpret_cast<const float4*>(g_rrow + c);
    acc.x += rr.x; acc.y += rr.y; acc.z += rr.z; acc.w += rr.w;

#pragma unroll
    for (int t = 0; t < 2; t++) {
        float4 v = *reinterpret_cast<const float4*>(g_Q1 + (size_t)jj[t] * E_DIM + c);
        acc.x += wj[t] * v.x; acc.y += wj[t] * v.y;
        acc.z += wj[t] * v.z; acc.w += wj[t] * v.w;
    }
#pragma unroll
    for (int t = 0; t < 4; t++) {
        float4 v = *reinterpret_cast<const float4*>(g_Q2 + (size_t)kk2[t] * E_DIM + c);
        acc.x += wk2[t] * v.x; acc.y += wk2[t] * v.y;
        acc.z += wk2[t] * v.z; acc.w += wk2[t] * v.w;
    }
#pragma unroll
    for (int t = 0; t < 8; t++) {
        float4 v = *reinterpret_cast<const float4*>(g_Q3 + (size_t)mm[t] * E_DIM + c);
        acc.x += wm[t] * v.x; acc.y += wm[t] * v.y;
        acc.z += wm[t] * v.z; acc.w += wm[t] * v.w;
    }
    *reinterpret_cast<float4*>(out + (size_t)r * E_DIM + c) = acc;
}

// ---------------- FA-2 fp16 attention (128 q / 8 warps, P in regs, ---------
//                   natural-V + ldmatrix.trans, 2-stage cp.async K/V) --------
#define SA 72   // smem row stride in halfs
#define ATTN_SMEM ((128 + 2 * 64 + 2 * 64) * SA * 2)   // 55296 B

__global__ void __launch_bounds__(256, 2) attn_all()
{
    extern __shared__ __half sm[];
    __half* Qs = sm;                                   // [128][SA]
    const uint32_t smBase = (uint32_t)__cvta_generic_to_shared(sm);
    const uint32_t kStage0 = smBase + 128 * SA * 2;    // K stages at rows 128,192
    const uint32_t vStage0 = smBase + 256 * SA * 2;    // V stages at rows 256,320

    const int bx = blockIdx.x;
    int lvl = 0;
#pragma unroll
    for (int i = 0; i < 3; i++) if (bx >= d_rbCum[i + 1]) lvl = i + 1;
    const int L = d_Llvl[lvl];
    const __half* qkv = g_qkvh + (size_t)d_qoff[lvl] * 3 * E_DIM;
    __half* outp = g_attnh + (size_t)d_qoff[lvl] * E_DIM;

    const int h = blockIdx.y;
    const int q0 = (bx - d_rbCum[lvl]) * 128;
    const int tid = threadIdx.x;
    const int wid = tid >> 5;
    const int lane = tid & 31;
    const int g = lane >> 2;
    const int q = lane & 3;

    const int lc8 = (tid & 7) * 8;
    const int lrw = tid >> 3;       // 0..31

    // prefetch of K/V block (cp.async; K natural, V natural)
    auto PREFETCH = [&](int kb, int st) {
        const uint32_t kb_ = kStage0 + st * 64 * SA * 2;
        const uint32_t vb_ = vStage0 + st * 64 * SA * 2;
#pragma unroll
        for (int it = 0; it < 2; it++) {
            int r = lrw + it * 32;
            const __half* base = qkv + (size_t)(kb + r) * 3072 + h * 64 + lc8;
            cp_async16(kb_ + (r * SA + lc8) * 2, base + 1024);
            cp_async16(vb_ + (r * SA + lc8) * 2, base + 2048);
        }
        cp_commit();
    };

    // load Q tile (scaled by 1/8, exact in fp16)
    const __half2 sc2 = __floats2half2_rn(0.125f, 0.125f);
#pragma unroll
    for (int it = 0; it < 4; it++) {
        int r = lrw + it * 32;
        const __half2* src = reinterpret_cast<const __half2*>(
            qkv + (size_t)(q0 + r) * 3072 + h * 64 + lc8);
        __half2* dst = reinterpret_cast<__half2*>(Qs + r * SA + lc8);
#pragma unroll
        for (int j = 0; j < 4; j++) dst[j] = __hmul2(src[j], sc2);
    }
    PREFETCH(0, 0);

    uint32_t qa[4][4];
    const int arow = wid * 16 + g;

    float m_i[2] = {-1e30f, -1e30f};
    float l_i[2] = {0.f, 0.f};
    float O[8][4];
#pragma unroll
    for (int ni = 0; ni < 8; ni++)
#pragma unroll
        for (int j = 0; j < 4; j++) O[ni][j] = 0.f;

    // per-thread ldmatrix row offset within a V stage (lanes 0..15 meaningful)
    const uint32_t vrow = (uint32_t)((lane & 15) * SA * 2);

    const int nblk = L / 64;
    for (int c = 0; c < nblk; c++) {
        const int s = c & 1;
        __syncthreads();   // stage (c+1)&1 free (compute c-1 done); Q visible at c==0
        if (c == 0) {
#pragma unroll
            for (int ks = 0; ks < 4; ks++) {
                const __half* p = Qs + arow * SA + ks * 16 + 2 * q;
                qa[ks][0] = *reinterpret_cast<const uint32_t*>(p);
                qa[ks][1] = *reinterpret_cast<const uint32_t*>(p + 8 * SA);
                qa[ks][2] = *reinterpret_cast<const uint32_t*>(p + 8);
                qa[ks][3] = *reinterpret_cast<const uint32_t*>(p + 8 * SA + 8);
            }
        }
        if (c + 1 < nblk) PREFETCH((c + 1) * 64, s ^ 1);
        if (c + 1 < nblk) cp_wait1(); else cp_wait0();
        __syncthreads();   // K/V stage s visible

        const __half* Ks = sm + (128 + s * 64) * SA;
        const uint32_t vb = vStage0 + s * 64 * SA * 2 + vrow;

        // S = Q @ K^T
        float sc[8][4];
#pragma unroll
        for (int ni = 0; ni < 8; ni++)
#pragma unroll
            for (int j = 0; j < 4; j++) sc[ni][j] = 0.f;
#pragma unroll
        for (int ks = 0; ks < 4; ks++) {
            const int kc = ks * 16 + 2 * q;
#pragma unroll
            for (int ni = 0; ni < 8; ni++) {
                const __half* p = Ks + (ni * 8 + g) * SA + kc;
                mma_f16(sc[ni], qa[ks],
                        *reinterpret_cast<const uint32_t*>(p),
                        *reinterpret_cast<const uint32_t*>(p + 8));
            }
        }

        // online softmax
        float rmax0 = -1e30f, rmax1 = -1e30f;
#pragma unroll
        for (int ni = 0; ni < 8; ni++) {
            rmax0 = fmaxf(rmax0, fmaxf(sc[ni][0], sc[ni][1]));
            rmax1 = fmaxf(rmax1, fmaxf(sc[ni][2], sc[ni][3]));
        }
#pragma unroll
        for (int off = 1; off <= 2; off <<= 1) {
            rmax0 = fmaxf(rmax0, __shfl_xor_sync(0xffffffffu, rmax0, off));
            rmax1 = fmaxf(rmax1, __shfl_xor_sync(0xffffffffu, rmax1, off));
        }
        float mnew0 = fmaxf(m_i[0], rmax0);
        float mnew1 = fmaxf(m_i[1], rmax1);
        float al0 = __expf(m_i[0] - mnew0);
        float al1 = __expf(m_i[1] - mnew1);
        float sum0 = 0.f, sum1 = 0.f;
#pragma unroll
        for (int ni = 0; ni < 8; ni++) {
            sc[ni][0] = __expf(sc[ni][0] - mnew0);
            sc[ni][1] = __expf(sc[ni][1] - mnew0);
            sc[ni][2] = __expf(sc[ni][2] - mnew1);
            sc[ni][3] = __expf(sc[ni][3] - mnew1);
            sum0 += sc[ni][0] + sc[ni][1];
            sum1 += sc[ni][2] + sc[ni][3];
        }
#pragma unroll
        for (int off = 1; off <= 2; off <<= 1) {
            sum0 += __shfl_xor_sync(0xffffffffu, sum0, off);
            sum1 += __shfl_xor_sync(0xffffffffu, sum1, off);
        }
        l_i[0] = l_i[0] * al0 + sum0;
        l_i[1] = l_i[1] * al1 + sum1;
        m_i[0] = mnew0;
        m_i[1] = mnew1;
#pragma unroll
        for (int ni = 0; ni < 8; ni++) {
            O[ni][0] *= al0; O[ni][1] *= al0;
            O[ni][2] *= al1; O[ni][3] *= al1;
        }

        // O += P @ V : P from registers, V^T via ldmatrix.trans on natural V
#pragma unroll
        for (int ks = 0; ks < 4; ks++) {
            uint32_t pa[4];
            pa[0] = packh2(sc[2 * ks][0], sc[2 * ks][1]);
            pa[1] = packh2(sc[2 * ks][2], sc[2 * ks][3]);
            pa[2] = packh2(sc[2 * ks + 1][0], sc[2 * ks + 1][1]);
            pa[3] = packh2(sc[2 * ks + 1][2], sc[2 * ks + 1][3]);
            const uint32_t rowa = vb + (uint32_t)(16 * ks * SA * 2);
#pragma unroll
            for (int ni = 0; ni < 8; ni++) {
                uint32_t b0, b1;
                ldm_x2_trans(b0, b1, rowa + ni * 16);
                mma_f16(O[ni], pa, b0, b1);
            }
        }
    }

    // normalize + write fp16
    const float inv0 = 1.0f / l_i[0];
    const float inv1 = 1.0f / l_i[1];
    const size_t row0 = (size_t)(q0 + arow);
#pragma unroll
    for (int ni = 0; ni < 8; ni++) {
        const int col = h * 64 + ni * 8 + 2 * q;
        *reinterpret_cast<__half2*>(outp + row0 * E_DIM + col) =
            __floats2half2_rn(O[ni][0] * inv0, O[ni][1] * inv0);
        *reinterpret_cast<__half2*>(outp + (row0 + 8) * E_DIM + col) =
            __floats2half2_rn(O[ni][2] * inv1, O[ni][3] * inv1);
    }
}

// ---------------- launcher --------------------------------------------------
extern "C" void kernel_launch(void* const* d_in, const int* in_sizes, int n_in,
                              void* d_out, int out_size)
{
    const float* query = (const float*)d_in[0];
    const float* in_w  = (const float*)d_in[1];
    const float* in_b  = (const float*)d_in[2];
    const float* out_w = (const float*)d_in[3];
    const float* out_b = (const float*)d_in[4];
    const float* up_w  = (const float*)d_in[5];
    const float* up_b  = (const float*)d_in[6];
    float* out = (float*)d_out;

    cudaFuncSetAttribute(gemm_qkv_all, cudaFuncAttributeMaxDynamicSharedMemorySize, GEMM_SMEM);
    cudaFuncSetAttribute(gemm_out_all, cudaFuncAttributeMaxDynamicSharedMemorySize, GEMM_SMEM);
    cudaFuncSetAttribute(combine_proj, cudaFuncAttributeMaxDynamicSharedMemorySize, GEMM_SMEM);
    cudaFuncSetAttribute(attn_all,     cudaFuncAttributeMaxDynamicSharedMemorySize, ATTN_SMEM);

    // 0. fp32 -> fp16 copies, single launch
    prep_all<<<(N4_ALL + 255) / 256, 256>>>(
        (const float4*)query, (const float4*)in_w,
        (const float4*)out_w, (const float4*)up_w);

    // 1. W1^T, W2^T
    transpose_w<<<dim3(32, 32, 2), dim3(32, 8)>>>();
    // 2. QKV all levels (+ P2 = W0@W1 hidden in grid)
    gemm_qkv_all<<<dim3(24, 33), 256, GEMM_SMEM>>>(in_b);
    // 3. attention all levels (128-query CTAs, FA-2 style)
    attn_all<<<dim3(30, 16), 256, ATTN_SMEM>>>();
    // 4. out-proj all levels (+ P3 = P2@W2 hidden in grid)
    gemm_out_all<<<dim3(8, 38), 256, GEMM_SMEM>>>(out_b);
    // 5. all combine projections + bias row, one launch
    combine_proj<<<116, 256, GEMM_SMEM>>>(up_b);
    // 6. final tap-composed upsample + residual sum
    final_combine<<<2048, 256>>>(out);
}